// round 1
// baseline (speedup 1.0000x reference)
#include <cuda_runtime.h>
#include <math.h>

#define C_DIM 228
#define TOKENS 2048
#define SEQ 1024
#define HD 57
#define LANES 4
#define FF 912
#define NLAYER 4
#define VOCAB 50257

// ------------------------------------------------------------------
// Scratch (no allocations allowed -> __device__ globals)
// ------------------------------------------------------------------
__device__ float g_x   [TOKENS * C_DIM];
__device__ float g_h   [TOKENS * C_DIM];
__device__ float g_v   [TOKENS * C_DIM];
__device__ float g_bufA[TOKENS * C_DIM];
__device__ float g_bufB[TOKENS * C_DIM];
__device__ float g_mix [TOKENS * C_DIM];
__device__ float g_mlp [TOKENS * FF];

__device__ __forceinline__ float gelu_f(float x) {
    float x3 = x * x * x;
    return 0.5f * x * (1.0f + tanhf(0.7978845608028654f * (x + 0.044715f * x3)));
}

// ------------------------------------------------------------------
// Embedding gather, with int32/int64 auto-detect on the idx buffer
// ------------------------------------------------------------------
__global__ __launch_bounds__(256) void embed_kernel(const int* __restrict__ idx32,
                                                    const float* __restrict__ wte,
                                                    float* __restrict__ x) {
    __shared__ int s_is64;
    if (threadIdx.x == 0) {
        // if idx is int64 little-endian with values < 2^31, every odd 32-bit word is 0
        int all0 = 1;
        #pragma unroll
        for (int i = 1; i < 16; i += 2)
            if (idx32[i] != 0) all0 = 0;
        s_is64 = all0;
    }
    __syncthreads();
    int gid = blockIdx.x * 256 + threadIdx.x;
    if (gid >= TOKENS * C_DIM) return;
    int t = gid / C_DIM;
    int c = gid - t * C_DIM;
    int id = s_is64 ? idx32[2 * t] : idx32[t];
    x[gid] = wte[id * C_DIM + c];
}

// ------------------------------------------------------------------
// LayerNorm (no bias), one warp per token
// ------------------------------------------------------------------
__global__ __launch_bounds__(256) void ln_kernel(const float* __restrict__ x,
                                                 const float* __restrict__ g,
                                                 float* __restrict__ out) {
    int w = (blockIdx.x * 256 + threadIdx.x) >> 5;
    int lane = threadIdx.x & 31;
    if (w >= TOKENS) return;
    const float* row = x + w * C_DIM;
    float s = 0.f, s2 = 0.f;
    for (int c = lane; c < C_DIM; c += 32) {
        float v = row[c];
        s += v; s2 += v * v;
    }
    #pragma unroll
    for (int o = 16; o > 0; o >>= 1) {
        s  += __shfl_xor_sync(0xffffffffu, s, o);
        s2 += __shfl_xor_sync(0xffffffffu, s2, o);
    }
    float mean = s * (1.0f / C_DIM);
    float var = s2 * (1.0f / C_DIM) - mean * mean;
    float rstd = rsqrtf(var + 1e-5f);
    float* orow = out + w * C_DIM;
    for (int c = lane; c < C_DIM; c += 32)
        orow[c] = (row[c] - mean) * rstd * g[c];
}

// ------------------------------------------------------------------
// Combine: lane-attention + rms + residual. One warp per (token, lane).
// left = shift(xin, off) with ident fill; mix precomputed = (left+right)@W
// ------------------------------------------------------------------
__global__ __launch_bounds__(256) void combine_kernel(const float* __restrict__ xin,
                                                      const float* __restrict__ mix,
                                                      const float* __restrict__ ident,
                                                      float* __restrict__ xout,
                                                      int off) {
    int gw = (blockIdx.x * 256 + threadIdx.x) >> 5;
    int lane = threadIdx.x & 31;
    if (gw >= TOKENS * LANES) return;
    int t = gw >> 2;
    int l = gw & 3;
    int tt = t & (SEQ - 1);
    const float* right = xin + t * C_DIM;
    const float* leftr = (tt >= off) ? (xin + (t - off) * C_DIM) : ident;
    const float* mr = mix + t * C_DIM;
    const int d0 = lane;
    const int d1 = lane + 32;
    const bool has1 = (d1 < HD);

    float q0 = leftr[l * HD + d0];
    float q1 = has1 ? leftr[l * HD + d1] : 0.f;

    float sc[4];
    #pragma unroll
    for (int m = 0; m < 4; m++) {
        float p = q0 * right[m * HD + d0];
        if (has1) p += q1 * right[m * HD + d1];
        #pragma unroll
        for (int o = 16; o > 0; o >>= 1) p += __shfl_xor_sync(0xffffffffu, p, o);
        sc[m] = p * 0.13245323570650439f; // 1/sqrt(57)
    }
    float mx = fmaxf(fmaxf(sc[0], sc[1]), fmaxf(sc[2], sc[3]));
    float e0 = expf(sc[0] - mx), e1 = expf(sc[1] - mx);
    float e2 = expf(sc[2] - mx), e3 = expf(sc[3] - mx);
    float inv = 1.0f / (e0 + e1 + e2 + e3);
    float a0 = e0 * inv, a1 = e1 * inv, a2 = e2 * inv, a3 = e3 * inv;

    float z0 = a0 * mr[0 * HD + d0] + a1 * mr[1 * HD + d0]
             + a2 * mr[2 * HD + d0] + a3 * mr[3 * HD + d0];
    float z1 = 0.f;
    if (has1)
        z1 = a0 * mr[0 * HD + d1] + a1 * mr[1 * HD + d1]
           + a2 * mr[2 * HD + d1] + a3 * mr[3 * HD + d1];

    float ss = z0 * z0 + z1 * z1;
    #pragma unroll
    for (int o = 16; o > 0; o >>= 1) ss += __shfl_xor_sync(0xffffffffu, ss, o);
    float scale = rsqrtf(ss * (1.0f / 57.0f) + 1e-6f) / (1.0f + (float)l);

    xout[t * C_DIM + l * HD + d0] = q0 + z0 * scale;
    if (has1) xout[t * C_DIM + l * HD + d1] = q1 + z1 * scale;
}

// ------------------------------------------------------------------
// Tiled fp32 GEMM.
//   AMODE 0: A[m,k]           AMODE 1: A[m,k] + (tt>=off ? A[m-off,k] : ident[k])
//   AMODE 2: A[m,k]*A2[m,k]
//   BNN 0: out[m,n]=sum_k A[m,k]*B[n*K+k]  (NT)   BNN 1: B[k*N+n]  (NN)
//   EPI 0: store   EPI 1: C += acc   EPI 2: C = gelu(acc)
// ------------------------------------------------------------------
template<int BM, int BN, int BK, int TM, int TN, int AMODE, int BNN, int EPI>
__global__ __launch_bounds__((BM/TM)*(BN/TN)) void gemm_k(
    const float* __restrict__ A, const float* __restrict__ A2,
    const float* __restrict__ B, float* __restrict__ Cc,
    int M, int N, int K, int off, const float* __restrict__ ident) {

    constexpr int THREADS = (BM / TM) * (BN / TN);
    __shared__ float As[BK][BM + 1];
    __shared__ float Bs[BK][BN + 1];

    const int tid = threadIdx.x;
    const int m0 = blockIdx.y * BM;
    const int n0 = blockIdx.x * BN;
    const int tx = tid % (BN / TN);
    const int ty = tid / (BN / TN);

    float acc[TM][TN];
    #pragma unroll
    for (int i = 0; i < TM; i++)
        #pragma unroll
        for (int j = 0; j < TN; j++) acc[i][j] = 0.f;

    for (int k0 = 0; k0 < K; k0 += BK) {
        // load A tile
        for (int i = tid; i < BM * BK; i += THREADS) {
            int row = i / BK, col = i % BK;
            int m = m0 + row, k = k0 + col;
            float val = 0.f;
            if (m < M && k < K) {
                if constexpr (AMODE == 0) {
                    val = A[m * K + k];
                } else if constexpr (AMODE == 1) {
                    int tt = m & (SEQ - 1);
                    float lv = (tt >= off) ? A[(m - off) * K + k] : ident[k];
                    val = A[m * K + k] + lv;
                } else {
                    val = A[m * K + k] * A2[m * K + k];
                }
            }
            As[col][row] = val;
        }
        // load B tile
        if constexpr (BNN == 0) {
            for (int i = tid; i < BK * BN; i += THREADS) {
                int n = i / BK, col = i % BK;
                int gn = n0 + n, k = k0 + col;
                Bs[col][n] = (gn < N && k < K) ? B[gn * K + k] : 0.f;
            }
        } else {
            for (int i = tid; i < BK * BN; i += THREADS) {
                int n = i % BN, row = i / BN;
                int gn = n0 + n, k = k0 + row;
                Bs[row][n] = (gn < N && k < K) ? B[k * N + gn] : 0.f;
            }
        }
        __syncthreads();

        #pragma unroll
        for (int kk = 0; kk < BK; kk++) {
            float ar[TM], br[TN];
            #pragma unroll
            for (int i = 0; i < TM; i++) ar[i] = As[kk][ty * TM + i];
            #pragma unroll
            for (int j = 0; j < TN; j++) br[j] = Bs[kk][tx * TN + j];
            #pragma unroll
            for (int i = 0; i < TM; i++)
                #pragma unroll
                for (int j = 0; j < TN; j++)
                    acc[i][j] += ar[i] * br[j];
        }
        __syncthreads();
    }

    #pragma unroll
    for (int i = 0; i < TM; i++) {
        int m = m0 + ty * TM + i;
        if (m >= M) continue;
        #pragma unroll
        for (int j = 0; j < TN; j++) {
            int n = n0 + tx * TN + j;
            if (n >= N) continue;
            float r = acc[i][j];
            if constexpr (EPI == 1) r += Cc[m * N + n];
            if constexpr (EPI == 2) r = gelu_f(r);
            Cc[m * N + n] = r;
        }
    }
}

// small-GEMM config
#define SBM 64
#define SBN 64
#define SBK 16
#define STM 4
#define STN 4
// big-GEMM config (lm_head)
#define LBM 128
#define LBN 128
#define LBK 16
#define LTM 8
#define LTN 8

static inline dim3 ggrid(int M, int N, int BM, int BN) {
    return dim3((N + BN - 1) / BN, (M + BM - 1) / BM);
}

// ------------------------------------------------------------------
extern "C" void kernel_launch(void* const* d_in, const int* in_sizes, int n_in,
                              void* d_out, int out_size) {
    const int*   idx    = (const int*)  d_in[0];
    const float* wte    = (const float*)d_in[1];
    const float* ln1_g  = (const float*)d_in[2];
    const float* ln2_g  = (const float*)d_in[3];
    const float* w_up   = (const float*)d_in[4];
    const float* w_v    = (const float*)d_in[5];
    const float* w_cpr  = (const float*)d_in[6];
    const float* w_scan = (const float*)d_in[7];
    const float* ident  = (const float*)d_in[8];
    const float* w_fc   = (const float*)d_in[9];
    const float* w_proj = (const float*)d_in[10];
    float* out = (float*)d_out;

    float *px, *ph, *pv, *pa, *pb, *pm, *pmlp;
    cudaGetSymbolAddress((void**)&px,   g_x);
    cudaGetSymbolAddress((void**)&ph,   g_h);
    cudaGetSymbolAddress((void**)&pv,   g_v);
    cudaGetSymbolAddress((void**)&pa,   g_bufA);
    cudaGetSymbolAddress((void**)&pb,   g_bufB);
    cudaGetSymbolAddress((void**)&pm,   g_mix);
    cudaGetSymbolAddress((void**)&pmlp, g_mlp);

    const int CC = C_DIM * C_DIM;      // 51984
    const int FC = FF * C_DIM;         // 207936

    embed_kernel<<<(TOKENS * C_DIM + 255) / 256, 256>>>(idx, wte, px);

    for (int L = 0; L < NLAYER; L++) {
        const float* wupL  = w_up   + L * CC;
        const float* wvL   = w_v    + L * CC;
        const float* wcprL = w_cpr  + L * CC;
        const float* wscL  = w_scan + L * CC;
        const float* idL   = ident  + L * C_DIM;
        const float* wfcL  = w_fc   + L * FC;
        const float* wprL  = w_proj + L * FC;

        // h = LN1(x)
        ln_kernel<<<(TOKENS * 32 + 255) / 256, 256>>>(px, ln1_g + L * C_DIM, ph);

        // qin = h @ w_up^T ;  v = h @ w_v^T
        gemm_k<SBM,SBN,SBK,STM,STN,0,0,0><<<ggrid(TOKENS, C_DIM, SBM, SBN), 256>>>(
            ph, nullptr, wupL, pa, TOKENS, C_DIM, C_DIM, 0, nullptr);
        gemm_k<SBM,SBN,SBK,STM,STN,0,0,0><<<ggrid(TOKENS, C_DIM, SBM, SBN), 256>>>(
            ph, nullptr, wvL, pv, TOKENS, C_DIM, C_DIM, 0, nullptr);

        // pscan: 10 Kogge-Stone steps, ping-pong pa <-> pb
        float* cur = pa;
        float* nxt = pb;
        for (int off = 1; off < SEQ; off <<= 1) {
            // mix = (left + right) @ w_scan   (NN, shift+ident fused into A-load)
            gemm_k<SBM,SBN,SBK,STM,STN,1,1,0><<<ggrid(TOKENS, C_DIM, SBM, SBN), 256>>>(
                cur, nullptr, wscL, pm, TOKENS, C_DIM, C_DIM, off, idL);
            combine_kernel<<<(TOKENS * LANES * 32 + 255) / 256, 256>>>(cur, pm, idL, nxt, off);
            float* t = cur; cur = nxt; nxt = t;
        }
        // after 10 steps, cur == pa

        // x += (q * v) @ w_cproj^T   (elementwise mult fused into A-load, residual in EPI)
        gemm_k<SBM,SBN,SBK,STM,STN,2,0,1><<<ggrid(TOKENS, C_DIM, SBM, SBN), 256>>>(
            cur, pv, wcprL, px, TOKENS, C_DIM, C_DIM, 0, nullptr);

        // h = LN2(x)
        ln_kernel<<<(TOKENS * 32 + 255) / 256, 256>>>(px, ln2_g + L * C_DIM, ph);

        // mlp = gelu(h @ w_fc^T)
        gemm_k<SBM,SBN,SBK,STM,STN,0,0,2><<<ggrid(TOKENS, FF, SBM, SBN), 256>>>(
            ph, nullptr, wfcL, pmlp, TOKENS, FF, C_DIM, 0, nullptr);
        // x += mlp @ w_proj^T
        gemm_k<SBM,SBN,SBK,STM,STN,0,0,1><<<ggrid(TOKENS, C_DIM, SBM, SBN), 256>>>(
            pmlp, nullptr, wprL, px, TOKENS, C_DIM, FF, 0, nullptr);
    }

    // logits = x @ wte^T
    gemm_k<LBM,LBN,LBK,LTM,LTN,0,0,0><<<ggrid(TOKENS, VOCAB, LBM, LBN), 256>>>(
        px, nullptr, wte, out, TOKENS, VOCAB, C_DIM, 0, nullptr);
}

// round 2
// speedup vs baseline: 2.3772x; 2.3772x over previous
#include <cuda_runtime.h>
#include <cstdint>
#include <math.h>

#define C_DIM 228
#define TOKENS 2048
#define SEQ 1024
#define HD 57
#define LANES 4
#define FF 912
#define NLAYER 4
#define VOCAB 50257

// ------------------------------------------------------------------
// Scratch
// ------------------------------------------------------------------
__device__ float g_x   [TOKENS * C_DIM];
__device__ float g_h   [TOKENS * C_DIM];
__device__ float g_v   [TOKENS * C_DIM];
__device__ float g_bufA[TOKENS * C_DIM];
__device__ float g_bufB[TOKENS * C_DIM];
__device__ float g_mlp [TOKENS * FF];

__device__ __forceinline__ float gelu_f(float x) {
    float x3 = x * x * x;
    return 0.5f * x * (1.0f + tanhf(0.7978845608028654f * (x + 0.044715f * x3)));
}

// ------------------------------------------------------------------
// Embedding gather (int32/int64 auto-detect)
// ------------------------------------------------------------------
__global__ __launch_bounds__(256) void embed_kernel(const int* __restrict__ idx32,
                                                    const float* __restrict__ wte,
                                                    float* __restrict__ x) {
    __shared__ int s_is64;
    if (threadIdx.x == 0) {
        int all0 = 1;
        #pragma unroll
        for (int i = 1; i < 16; i += 2)
            if (idx32[i] != 0) all0 = 0;
        s_is64 = all0;
    }
    __syncthreads();
    int gid = blockIdx.x * 256 + threadIdx.x;
    if (gid >= TOKENS * C_DIM) return;
    int t = gid / C_DIM;
    int c = gid - t * C_DIM;
    int id = s_is64 ? idx32[2 * t] : idx32[t];
    x[gid] = wte[id * C_DIM + c];
}

// ------------------------------------------------------------------
// LayerNorm, one warp per token
// ------------------------------------------------------------------
__global__ __launch_bounds__(256) void ln_kernel(const float* __restrict__ x,
                                                 const float* __restrict__ g,
                                                 float* __restrict__ out) {
    int w = (blockIdx.x * 256 + threadIdx.x) >> 5;
    int lane = threadIdx.x & 31;
    if (w >= TOKENS) return;
    const float* row = x + w * C_DIM;
    float s = 0.f, s2 = 0.f;
    for (int c = lane; c < C_DIM; c += 32) {
        float v = row[c];
        s += v; s2 += v * v;
    }
    #pragma unroll
    for (int o = 16; o > 0; o >>= 1) {
        s  += __shfl_xor_sync(0xffffffffu, s, o);
        s2 += __shfl_xor_sync(0xffffffffu, s2, o);
    }
    float mean = s * (1.0f / C_DIM);
    float var = s2 * (1.0f / C_DIM) - mean * mean;
    float rstd = rsqrtf(var + 1e-5f);
    float* orow = out + w * C_DIM;
    for (int c = lane; c < C_DIM; c += 32)
        orow[c] = (row[c] - mean) * rstd * g[c];
}

// ------------------------------------------------------------------
// Fused scan step: mix = (left+right) @ W_scan, then lane-attention
// combine, all in one kernel. 16 tokens/block, 128 blocks, 256 thr.
// smem (dynamic, 151264 B):
//   sT  [232][17]  (left+right, transposed, pad row 17)
//   rr  [16][232]  (right rows)
//   wc  [114][232] (W chunk)
//   mx  [16][232]  (mix output)
// ------------------------------------------------------------------
#define SCAN_SMEM_FLOATS (232*17 + 16*232 + 114*232 + 16*232)

__global__ __launch_bounds__(256) void scan_step_kernel(
    const float* __restrict__ xin, float* __restrict__ xout,
    const float* __restrict__ wsc, const float* __restrict__ ident, int off)
{
    extern __shared__ float sm[];
    float* sT = sm;                 // [c*17 + t]
    float* rr = sT + 232 * 17;      // [t*232 + c]
    float* wc = rr + 16 * 232;      // [kk*232 + c]
    float* mx = wc + 114 * 232;     // [t*232 + c]

    const int tid = threadIdx.x;
    const int T0 = blockIdx.x * 16;

    // ---- load phase ----
    if (tid < 232) {
        int c = tid;
        #pragma unroll
        for (int t = 0; t < 16; t++) {
            int tok = T0 + t;
            int tt = tok & (SEQ - 1);
            float rv = 0.f, lv = 0.f;
            if (c < C_DIM) {
                rv = xin[tok * C_DIM + c];
                lv = (tt >= off) ? xin[(tok - off) * C_DIM + c] : ident[c];
            }
            rr[t * 232 + c] = rv;
            sT[c * 17 + t] = lv + rv;
        }
    }

    // ---- GEMM phase: mix[t][c] = sum_k s[t][k] * W[k][c] ----
    const int tx = tid & 31;        // col group
    const int ty = tid >> 5;        // 0..7, tokens ty*2, ty*2+1
    const int t0 = ty * 2;
    const bool hiOK = (tx < 26);    // upper cols 128+tx*4 valid (<232)

    float acc[2][8];
    #pragma unroll
    for (int i = 0; i < 2; i++)
        #pragma unroll
        for (int j = 0; j < 8; j++) acc[i][j] = 0.f;

    for (int k0 = 0; k0 < C_DIM; k0 += 114) {
        __syncthreads();
        // stage W chunk (float4, zero-pad cols 228..231)
        for (int i = tid; i < 114 * 58; i += 256) {
            int kk = i / 58;
            int c4 = i - kk * 58;
            float4 v;
            if (c4 < 57) v = *(const float4*)&wsc[(k0 + kk) * C_DIM + c4 * 4];
            else v = make_float4(0.f, 0.f, 0.f, 0.f);
            *(float4*)&wc[kk * 232 + c4 * 4] = v;
        }
        __syncthreads();
        #pragma unroll 2
        for (int kk = 0; kk < 114; kk++) {
            int k = k0 + kk;
            float a0 = sT[k * 17 + t0];
            float a1 = sT[k * 17 + t0 + 1];
            float4 w0 = *(const float4*)&wc[kk * 232 + tx * 4];
            float4 w1 = hiOK ? *(const float4*)&wc[kk * 232 + 128 + tx * 4]
                             : make_float4(0.f, 0.f, 0.f, 0.f);
            acc[0][0] += a0 * w0.x; acc[0][1] += a0 * w0.y;
            acc[0][2] += a0 * w0.z; acc[0][3] += a0 * w0.w;
            acc[0][4] += a0 * w1.x; acc[0][5] += a0 * w1.y;
            acc[0][6] += a0 * w1.z; acc[0][7] += a0 * w1.w;
            acc[1][0] += a1 * w0.x; acc[1][1] += a1 * w0.y;
            acc[1][2] += a1 * w0.z; acc[1][3] += a1 * w0.w;
            acc[1][4] += a1 * w1.x; acc[1][5] += a1 * w1.y;
            acc[1][6] += a1 * w1.z; acc[1][7] += a1 * w1.w;
        }
    }
    // write mix
    *(float4*)&mx[t0 * 232 + tx * 4]       = make_float4(acc[0][0], acc[0][1], acc[0][2], acc[0][3]);
    *(float4*)&mx[(t0 + 1) * 232 + tx * 4] = make_float4(acc[1][0], acc[1][1], acc[1][2], acc[1][3]);
    if (hiOK) {
        *(float4*)&mx[t0 * 232 + 128 + tx * 4]       = make_float4(acc[0][4], acc[0][5], acc[0][6], acc[0][7]);
        *(float4*)&mx[(t0 + 1) * 232 + 128 + tx * 4] = make_float4(acc[1][4], acc[1][5], acc[1][6], acc[1][7]);
    }
    __syncthreads();

    // ---- combine phase: 64 (token,lane) pairs, 8 per warp ----
    const int lane = tx;
    const int d0 = lane;
    const int d1 = lane + 32;
    const bool has1 = (lane < HD - 32);   // lane < 25

    #pragma unroll
    for (int e = 0; e < 8; e++) {
        int p = ty * 8 + e;
        int t = p >> 2;
        int l = p & 3;
        int tok = T0 + t;

        float q0 = sT[(l * HD + d0) * 17 + t] - rr[t * 232 + l * HD + d0];
        float q1 = has1 ? (sT[(l * HD + d1) * 17 + t] - rr[t * 232 + l * HD + d1]) : 0.f;

        float sc[4];
        #pragma unroll
        for (int m = 0; m < 4; m++) {
            float pr = q0 * rr[t * 232 + m * HD + d0];
            if (has1) pr += q1 * rr[t * 232 + m * HD + d1];
            #pragma unroll
            for (int o = 16; o > 0; o >>= 1) pr += __shfl_xor_sync(0xffffffffu, pr, o);
            sc[m] = pr * 0.13245323570650439f;  // 1/sqrt(57)
        }
        float mxv = fmaxf(fmaxf(sc[0], sc[1]), fmaxf(sc[2], sc[3]));
        float e0 = expf(sc[0] - mxv), e1 = expf(sc[1] - mxv);
        float e2 = expf(sc[2] - mxv), e3 = expf(sc[3] - mxv);
        float inv = 1.0f / (e0 + e1 + e2 + e3);
        float a0 = e0 * inv, a1 = e1 * inv, a2 = e2 * inv, a3 = e3 * inv;

        float z0 = a0 * mx[t * 232 + 0 * HD + d0] + a1 * mx[t * 232 + 1 * HD + d0]
                 + a2 * mx[t * 232 + 2 * HD + d0] + a3 * mx[t * 232 + 3 * HD + d0];
        float z1 = 0.f;
        if (has1)
            z1 = a0 * mx[t * 232 + 0 * HD + d1] + a1 * mx[t * 232 + 1 * HD + d1]
               + a2 * mx[t * 232 + 2 * HD + d1] + a3 * mx[t * 232 + 3 * HD + d1];

        float ss = z0 * z0 + z1 * z1;
        #pragma unroll
        for (int o = 16; o > 0; o >>= 1) ss += __shfl_xor_sync(0xffffffffu, ss, o);
        float scale = rsqrtf(ss * (1.0f / 57.0f) + 1e-6f) / (1.0f + (float)l);

        xout[tok * C_DIM + l * HD + d0] = q0 + z0 * scale;
        if (has1) xout[tok * C_DIM + l * HD + d1] = q1 + z1 * scale;
    }
}

// ------------------------------------------------------------------
// fp32 GEMM (NT): out[m,n] = sum_k A[m,k] * B[n,k]
// BM=BN=64, BK=16, 256 threads, reg double-buffer, conflict-free frags.
// AMODE 0: A      AMODE 2: A*A2 elementwise
// EPI 0: store    EPI 1: +=     EPI 2: gelu
// ------------------------------------------------------------------
template<int AMODE, int EPI>
__global__ __launch_bounds__(256) void gemm2_k(
    const float* __restrict__ A, const float* __restrict__ A2,
    const float* __restrict__ B, float* __restrict__ Cc,
    int M, int N, int K)
{
    __shared__ float As[16][68];
    __shared__ float Bs[16][68];
    const int tid = threadIdx.x;
    const int m0 = blockIdx.y * 64, n0 = blockIdx.x * 64;
    const int tx = tid & 15, ty = tid >> 4;
    const int sr = tid >> 2;   // staging row 0..63
    const int sf = tid & 3;    // staging float4 slot

    float acc[4][4];
    #pragma unroll
    for (int i = 0; i < 4; i++)
        #pragma unroll
        for (int j = 0; j < 4; j++) acc[i][j] = 0.f;

    float4 ra, rb;
    int nchunk = (K + 15) / 16;

    // prefetch chunk 0
    {
        int k = sf * 4;
        float4 va = make_float4(0.f,0.f,0.f,0.f);
        if (k + 3 < K) {
            va = *(const float4*)&A[(m0 + sr) * K + k];
            if (AMODE == 2) {
                float4 u = *(const float4*)&A2[(m0 + sr) * K + k];
                va.x *= u.x; va.y *= u.y; va.z *= u.z; va.w *= u.w;
            }
        }
        float4 vb = make_float4(0.f,0.f,0.f,0.f);
        if (k + 3 < K && (n0 + sr) < N)
            vb = *(const float4*)&B[(n0 + sr) * K + k];
        ra = va; rb = vb;
    }

    for (int ch = 0; ch < nchunk; ch++) {
        __syncthreads();
        As[sf*4+0][sr] = ra.x; As[sf*4+1][sr] = ra.y;
        As[sf*4+2][sr] = ra.z; As[sf*4+3][sr] = ra.w;
        Bs[sf*4+0][sr] = rb.x; Bs[sf*4+1][sr] = rb.y;
        Bs[sf*4+2][sr] = rb.z; Bs[sf*4+3][sr] = rb.w;
        __syncthreads();
        if (ch + 1 < nchunk) {
            int k0 = (ch + 1) * 16;
            int k = k0 + sf * 4;
            float4 va = make_float4(0.f,0.f,0.f,0.f);
            if (k + 3 < K) {
                va = *(const float4*)&A[(m0 + sr) * K + k];
                if (AMODE == 2) {
                    float4 u = *(const float4*)&A2[(m0 + sr) * K + k];
                    va.x *= u.x; va.y *= u.y; va.z *= u.z; va.w *= u.w;
                }
            }
            float4 vb = make_float4(0.f,0.f,0.f,0.f);
            if (k + 3 < K && (n0 + sr) < N)
                vb = *(const float4*)&B[(n0 + sr) * K + k];
            ra = va; rb = vb;
        }
        #pragma unroll
        for (int kk = 0; kk < 16; kk++) {
            float4 av = *(const float4*)&As[kk][ty * 4];
            float4 bv = *(const float4*)&Bs[kk][tx * 4];
            acc[0][0] += av.x * bv.x; acc[0][1] += av.x * bv.y;
            acc[0][2] += av.x * bv.z; acc[0][3] += av.x * bv.w;
            acc[1][0] += av.y * bv.x; acc[1][1] += av.y * bv.y;
            acc[1][2] += av.y * bv.z; acc[1][3] += av.y * bv.w;
            acc[2][0] += av.z * bv.x; acc[2][1] += av.z * bv.y;
            acc[2][2] += av.z * bv.z; acc[2][3] += av.z * bv.w;
            acc[3][0] += av.w * bv.x; acc[3][1] += av.w * bv.y;
            acc[3][2] += av.w * bv.z; acc[3][3] += av.w * bv.w;
        }
    }

    #pragma unroll
    for (int i = 0; i < 4; i++) {
        int m = m0 + ty * 4 + i;
        #pragma unroll
        for (int j = 0; j < 4; j++) {
            int n = n0 + tx * 4 + j;
            if (n >= N) continue;
            float r = acc[i][j];
            if (EPI == 1) r += Cc[m * N + n];
            if (EPI == 2) r = gelu_f(r);
            Cc[m * N + n] = r;
        }
    }
}

// ------------------------------------------------------------------
// TF32 tensor-core lm_head: out[m,n] = sum_k A[m,k]*B[n,k]
// 128x128x32 tiles, 8 warps (2x4), warp tile 64x32, mma m16n8k8.
// ------------------------------------------------------------------
__device__ __forceinline__ uint32_t f2tf32(float x) {
    uint32_t r;
    asm("cvt.rna.tf32.f32 %0, %1;" : "=r"(r) : "f"(x));
    return r;
}

__device__ __forceinline__ void mma_tf32(float* c, const uint32_t* a, const uint32_t* b) {
    asm volatile("mma.sync.aligned.m16n8k8.row.col.f32.tf32.tf32.f32 "
        "{%0,%1,%2,%3}, {%4,%5,%6,%7}, {%8,%9}, {%0,%1,%2,%3};"
        : "+f"(c[0]), "+f"(c[1]), "+f"(c[2]), "+f"(c[3])
        : "r"(a[0]), "r"(a[1]), "r"(a[2]), "r"(a[3]), "r"(b[0]), "r"(b[1]));
}

__global__ __launch_bounds__(256) void lmhead_kernel(
    const float* __restrict__ A, const float* __restrict__ B,
    float* __restrict__ C, int M, int N, int K)
{
    __shared__ uint32_t As[128][36];
    __shared__ uint32_t Bs[128][36];
    const int tid = threadIdx.x;
    const int lane = tid & 31, wid = tid >> 5;
    const int wm = wid >> 2, wn = wid & 3;
    const int m0 = blockIdx.y * 128, n0 = blockIdx.x * 128;

    float acc[4][4][4];
    #pragma unroll
    for (int i = 0; i < 4; i++)
        #pragma unroll
        for (int j = 0; j < 4; j++)
            #pragma unroll
            for (int q = 0; q < 4; q++) acc[i][j][q] = 0.f;

    float4 pa[4], pb[4];
    const int nchunk = (K + 31) / 32;   // 8 for K=228

    // prefetch chunk 0
    #pragma unroll
    for (int i = 0; i < 4; i++) {
        int idx = tid + i * 256;
        int r = idx >> 3, f = idx & 7;
        int k = f * 4;
        float4 va = make_float4(0.f,0.f,0.f,0.f), vb = va;
        if (k < K) va = *(const float4*)&A[(m0 + r) * K + k];
        if (k < K && (n0 + r) < N) vb = *(const float4*)&B[(n0 + r) * K + k];
        pa[i] = va; pb[i] = vb;
    }

    for (int ch = 0; ch < nchunk; ch++) {
        __syncthreads();
        #pragma unroll
        for (int i = 0; i < 4; i++) {
            int idx = tid + i * 256;
            int r = idx >> 3, f = idx & 7;
            As[r][f*4+0] = f2tf32(pa[i].x); As[r][f*4+1] = f2tf32(pa[i].y);
            As[r][f*4+2] = f2tf32(pa[i].z); As[r][f*4+3] = f2tf32(pa[i].w);
            Bs[r][f*4+0] = f2tf32(pb[i].x); Bs[r][f*4+1] = f2tf32(pb[i].y);
            Bs[r][f*4+2] = f2tf32(pb[i].z); Bs[r][f*4+3] = f2tf32(pb[i].w);
        }
        __syncthreads();
        if (ch + 1 < nchunk) {
            int k0 = (ch + 1) * 32;
            #pragma unroll
            for (int i = 0; i < 4; i++) {
                int idx = tid + i * 256;
                int r = idx >> 3, f = idx & 7;
                int k = k0 + f * 4;
                float4 va = make_float4(0.f,0.f,0.f,0.f), vb = va;
                if (k < K) va = *(const float4*)&A[(m0 + r) * K + k];
                if (k < K && (n0 + r) < N) vb = *(const float4*)&B[(n0 + r) * K + k];
                pa[i] = va; pb[i] = vb;
            }
        }
        #pragma unroll
        for (int kc = 0; kc < 32; kc += 8) {
            uint32_t af[4][4], bf[4][2];
            #pragma unroll
            for (int mt = 0; mt < 4; mt++) {
                int rb_ = wm * 64 + mt * 16 + (lane >> 2);
                af[mt][0] = As[rb_    ][kc     + (lane & 3)];
                af[mt][1] = As[rb_ + 8][kc     + (lane & 3)];
                af[mt][2] = As[rb_    ][kc + 4 + (lane & 3)];
                af[mt][3] = As[rb_ + 8][kc + 4 + (lane & 3)];
            }
            #pragma unroll
            for (int nt = 0; nt < 4; nt++) {
                int cb = wn * 32 + nt * 8 + (lane >> 2);
                bf[nt][0] = Bs[cb][kc     + (lane & 3)];
                bf[nt][1] = Bs[cb][kc + 4 + (lane & 3)];
            }
            #pragma unroll
            for (int mt = 0; mt < 4; mt++)
                #pragma unroll
                for (int nt = 0; nt < 4; nt++)
                    mma_tf32(acc[mt][nt], af[mt], bf[nt]);
        }
    }

    #pragma unroll
    for (int mt = 0; mt < 4; mt++) {
        int m = m0 + wm * 64 + mt * 16 + (lane >> 2);
        #pragma unroll
        for (int nt = 0; nt < 4; nt++) {
            int n = n0 + wn * 32 + nt * 8 + (lane & 3) * 2;
            if (n     < N) C[m * N + n]           = acc[mt][nt][0];
            if (n + 1 < N) C[m * N + n + 1]       = acc[mt][nt][1];
            if (n     < N) C[(m + 8) * N + n]     = acc[mt][nt][2];
            if (n + 1 < N) C[(m + 8) * N + n + 1] = acc[mt][nt][3];
        }
    }
}

// ------------------------------------------------------------------
extern "C" void kernel_launch(void* const* d_in, const int* in_sizes, int n_in,
                              void* d_out, int out_size) {
    const int*   idx    = (const int*)  d_in[0];
    const float* wte    = (const float*)d_in[1];
    const float* ln1_g  = (const float*)d_in[2];
    const float* ln2_g  = (const float*)d_in[3];
    const float* w_up   = (const float*)d_in[4];
    const float* w_v    = (const float*)d_in[5];
    const float* w_cpr  = (const float*)d_in[6];
    const float* w_scan = (const float*)d_in[7];
    const float* ident  = (const float*)d_in[8];
    const float* w_fc   = (const float*)d_in[9];
    const float* w_proj = (const float*)d_in[10];
    float* out = (float*)d_out;

    float *px, *ph, *pv, *pa, *pb, *pmlp;
    cudaGetSymbolAddress((void**)&px,   g_x);
    cudaGetSymbolAddress((void**)&ph,   g_h);
    cudaGetSymbolAddress((void**)&pv,   g_v);
    cudaGetSymbolAddress((void**)&pa,   g_bufA);
    cudaGetSymbolAddress((void**)&pb,   g_bufB);
    cudaGetSymbolAddress((void**)&pmlp, g_mlp);

    const int scan_smem = SCAN_SMEM_FLOATS * 4;
    cudaFuncSetAttribute(scan_step_kernel,
                         cudaFuncAttributeMaxDynamicSharedMemorySize, scan_smem);

    const int CC = C_DIM * C_DIM;
    const int FC = FF * C_DIM;

    embed_kernel<<<(TOKENS * C_DIM + 255) / 256, 256>>>(idx, wte, px);

    for (int L = 0; L < NLAYER; L++) {
        const float* wupL  = w_up   + L * CC;
        const float* wvL   = w_v    + L * CC;
        const float* wcprL = w_cpr  + L * CC;
        const float* wscL  = w_scan + L * CC;
        const float* idL   = ident  + L * C_DIM;
        const float* wfcL  = w_fc   + L * FC;
        const float* wprL  = w_proj + L * FC;

        ln_kernel<<<(TOKENS * 32 + 255) / 256, 256>>>(px, ln1_g + L * C_DIM, ph);

        dim3 gs((C_DIM + 63) / 64, TOKENS / 64);
        gemm2_k<0,0><<<gs, 256>>>(ph, nullptr, wupL, pa, TOKENS, C_DIM, C_DIM);
        gemm2_k<0,0><<<gs, 256>>>(ph, nullptr, wvL,  pv, TOKENS, C_DIM, C_DIM);

        float* cur = pa;
        float* nxt = pb;
        for (int off = 1; off < SEQ; off <<= 1) {
            scan_step_kernel<<<TOKENS / 16, 256, scan_smem>>>(cur, nxt, wscL, idL, off);
            float* t = cur; cur = nxt; nxt = t;
        }
        // 10 steps (even) -> cur == pa

        gemm2_k<2,1><<<gs, 256>>>(cur, pv, wcprL, px, TOKENS, C_DIM, C_DIM);

        ln_kernel<<<(TOKENS * 32 + 255) / 256, 256>>>(px, ln2_g + L * C_DIM, ph);

        dim3 gf((FF + 63) / 64, TOKENS / 64);
        gemm2_k<0,2><<<gf, 256>>>(ph, nullptr, wfcL, pmlp, TOKENS, FF, C_DIM);
        gemm2_k<0,1><<<gs, 256>>>(pmlp, nullptr, wprL, px, TOKENS, C_DIM, FF);
    }

    dim3 gl((VOCAB + 127) / 128, TOKENS / 128);
    lmhead_kernel<<<gl, 256>>>(px, wte, out, TOKENS, VOCAB, C_DIM);
}

// round 3
// speedup vs baseline: 2.7252x; 1.1464x over previous
#include <cuda_runtime.h>
#include <cstdint>
#include <math.h>

#define C_DIM 228
#define TOKENS 2048
#define SEQ 1024
#define HD 57
#define LANES 4
#define FF 912
#define NLAYER 4
#define VOCAB 50257

// ------------------------------------------------------------------
// Scratch
// ------------------------------------------------------------------
__device__ float g_x   [TOKENS * C_DIM];
__device__ float g_h   [TOKENS * C_DIM];
__device__ float g_v   [TOKENS * C_DIM];
__device__ float g_bufA[TOKENS * C_DIM];
__device__ float g_bufB[TOKENS * C_DIM];
__device__ float g_mlp [TOKENS * FF];
__device__ unsigned g_bar_cnt = 0;
__device__ unsigned g_bar_gen = 0;

__device__ __forceinline__ float gelu_f(float x) {
    float x3 = x * x * x;
    return 0.5f * x * (1.0f + tanhf(0.7978845608028654f * (x + 0.044715f * x3)));
}

__device__ __forceinline__ uint32_t f2tf32(float x) {
    uint32_t r;
    asm("cvt.rna.tf32.f32 %0, %1;" : "=r"(r) : "f"(x));
    return r;
}
__device__ __forceinline__ void split_tf32(float x, uint32_t& hi, uint32_t& lo) {
    hi = f2tf32(x);
    lo = f2tf32(x - __uint_as_float(hi));
}
__device__ __forceinline__ void mma8(float* c, const uint32_t* a, const uint32_t* b) {
    asm volatile("mma.sync.aligned.m16n8k8.row.col.f32.tf32.tf32.f32 "
        "{%0,%1,%2,%3}, {%4,%5,%6,%7}, {%8,%9}, {%0,%1,%2,%3};"
        : "+f"(c[0]), "+f"(c[1]), "+f"(c[2]), "+f"(c[3])
        : "r"(a[0]), "r"(a[1]), "r"(a[2]), "r"(a[3]), "r"(b[0]), "r"(b[1]));
}

// ------------------------------------------------------------------
// Embedding gather (int32/int64 auto-detect)
// ------------------------------------------------------------------
__global__ __launch_bounds__(256) void embed_kernel(const int* __restrict__ idx32,
                                                    const float* __restrict__ wte,
                                                    float* __restrict__ x) {
    __shared__ int s_is64;
    if (threadIdx.x == 0) {
        int all0 = 1;
        #pragma unroll
        for (int i = 1; i < 16; i += 2)
            if (idx32[i] != 0) all0 = 0;
        s_is64 = all0;
    }
    __syncthreads();
    int gid = blockIdx.x * 256 + threadIdx.x;
    if (gid >= TOKENS * C_DIM) return;
    int t = gid / C_DIM;
    int c = gid - t * C_DIM;
    int id = s_is64 ? idx32[2 * t] : idx32[t];
    x[gid] = wte[id * C_DIM + c];
}

// ------------------------------------------------------------------
// LayerNorm, one warp per token
// ------------------------------------------------------------------
__global__ __launch_bounds__(256) void ln_kernel(const float* __restrict__ x,
                                                 const float* __restrict__ g,
                                                 float* __restrict__ out) {
    int w = (blockIdx.x * 256 + threadIdx.x) >> 5;
    int lane = threadIdx.x & 31;
    if (w >= TOKENS) return;
    const float* row = x + w * C_DIM;
    float s = 0.f, s2 = 0.f;
    for (int c = lane; c < C_DIM; c += 32) {
        float v = row[c];
        s += v; s2 += v * v;
    }
    #pragma unroll
    for (int o = 16; o > 0; o >>= 1) {
        s  += __shfl_xor_sync(0xffffffffu, s, o);
        s2 += __shfl_xor_sync(0xffffffffu, s2, o);
    }
    float mean = s * (1.0f / C_DIM);
    float var = s2 * (1.0f / C_DIM) - mean * mean;
    float rstd = rsqrtf(var + 1e-5f);
    float* orow = out + w * C_DIM;
    for (int c = lane; c < C_DIM; c += 32)
        orow[c] = (row[c] - mean) * rstd * g[c];
}

// ------------------------------------------------------------------
// Unified TF32 tensor GEMM (NT): out[m,n] = sum_k A[m,k]*B[n,k]
// COMP=1: 3xTF32 (fp32-accurate). AMODE 0: A; 2: A*A2. EPI 0/1/2.
// M must be a multiple of BM. Grid: (M/BM, ceil(N/BN)).
// ------------------------------------------------------------------
template<int BM, int BN, int WM, int WN, int COMP, int AMODE, int EPI>
__global__ __launch_bounds__((BM/WM)*(BN/WN)*32) void tc_gemm(
    const float* __restrict__ A, const float* __restrict__ A2,
    const float* __restrict__ B, float* __restrict__ Cc,
    int M, int N, int K)
{
    constexpr int NWARP = (BM / WM) * (BN / WN);
    constexpr int THREADS = NWARP * 32;
    constexpr int LA = BM * 8 / THREADS;
    constexpr int LB = BN * 8 / THREADS;
    constexpr int MT = WM / 16;
    constexpr int NT = WN / 8;

    __shared__ float As[BM][36];
    __shared__ float Bs[BN][36];

    const int tid = threadIdx.x;
    const int lane = tid & 31, wid = tid >> 5;
    const int wn = wid % (BN / WN), wm = wid / (BN / WN);
    const int m0 = blockIdx.x * BM, n0 = blockIdx.y * BN;

    float acc[MT][NT][4];
    #pragma unroll
    for (int i = 0; i < MT; i++)
        #pragma unroll
        for (int j = 0; j < NT; j++)
            #pragma unroll
            for (int q = 0; q < 4; q++) acc[i][j][q] = 0.f;

    float4 pa[LA], pb[LB];
    const int nchunk = (K + 31) / 32;

    // prefetch chunk 0
    #pragma unroll
    for (int i = 0; i < LA; i++) {
        int idx = tid + i * THREADS;
        int r = idx >> 3, f = idx & 7;
        int k = f * 4;
        float4 v = make_float4(0.f,0.f,0.f,0.f);
        if (k + 3 < K) {
            v = *(const float4*)&A[(m0 + r) * K + k];
            if (AMODE == 2) {
                float4 u = *(const float4*)&A2[(m0 + r) * K + k];
                v.x *= u.x; v.y *= u.y; v.z *= u.z; v.w *= u.w;
            }
        }
        pa[i] = v;
    }
    #pragma unroll
    for (int i = 0; i < LB; i++) {
        int idx = tid + i * THREADS;
        int r = idx >> 3, f = idx & 7;
        int k = f * 4;
        float4 v = make_float4(0.f,0.f,0.f,0.f);
        if (k + 3 < K && (n0 + r) < N)
            v = *(const float4*)&B[(n0 + r) * K + k];
        pb[i] = v;
    }

    for (int ch = 0; ch < nchunk; ch++) {
        __syncthreads();
        #pragma unroll
        for (int i = 0; i < LA; i++) {
            int idx = tid + i * THREADS;
            int r = idx >> 3, f = idx & 7;
            *(float4*)&As[r][f * 4] = pa[i];
        }
        #pragma unroll
        for (int i = 0; i < LB; i++) {
            int idx = tid + i * THREADS;
            int r = idx >> 3, f = idx & 7;
            *(float4*)&Bs[r][f * 4] = pb[i];
        }
        __syncthreads();
        if (ch + 1 < nchunk) {
            int k0 = (ch + 1) * 32;
            #pragma unroll
            for (int i = 0; i < LA; i++) {
                int idx = tid + i * THREADS;
                int r = idx >> 3, f = idx & 7;
                int k = k0 + f * 4;
                float4 v = make_float4(0.f,0.f,0.f,0.f);
                if (k + 3 < K) {
                    v = *(const float4*)&A[(m0 + r) * K + k];
                    if (AMODE == 2) {
                        float4 u = *(const float4*)&A2[(m0 + r) * K + k];
                        v.x *= u.x; v.y *= u.y; v.z *= u.z; v.w *= u.w;
                    }
                }
                pa[i] = v;
            }
            #pragma unroll
            for (int i = 0; i < LB; i++) {
                int idx = tid + i * THREADS;
                int r = idx >> 3, f = idx & 7;
                int k = k0 + f * 4;
                float4 v = make_float4(0.f,0.f,0.f,0.f);
                if (k + 3 < K && (n0 + r) < N)
                    v = *(const float4*)&B[(n0 + r) * K + k];
                pb[i] = v;
            }
        }
        #pragma unroll
        for (int kc = 0; kc < 32; kc += 8) {
            uint32_t ah[MT][4], al[MT][4], bh[NT][2], bl[NT][2];
            #pragma unroll
            for (int mt = 0; mt < MT; mt++) {
                int r = wm * WM + mt * 16 + (lane >> 2);
                float v0 = As[r    ][kc     + (lane & 3)];
                float v1 = As[r + 8][kc     + (lane & 3)];
                float v2 = As[r    ][kc + 4 + (lane & 3)];
                float v3 = As[r + 8][kc + 4 + (lane & 3)];
                if (COMP) {
                    split_tf32(v0, ah[mt][0], al[mt][0]);
                    split_tf32(v1, ah[mt][1], al[mt][1]);
                    split_tf32(v2, ah[mt][2], al[mt][2]);
                    split_tf32(v3, ah[mt][3], al[mt][3]);
                } else {
                    ah[mt][0] = f2tf32(v0); ah[mt][1] = f2tf32(v1);
                    ah[mt][2] = f2tf32(v2); ah[mt][3] = f2tf32(v3);
                }
            }
            #pragma unroll
            for (int nt = 0; nt < NT; nt++) {
                int n = wn * WN + nt * 8 + (lane >> 2);
                float u0 = Bs[n][kc     + (lane & 3)];
                float u1 = Bs[n][kc + 4 + (lane & 3)];
                if (COMP) {
                    split_tf32(u0, bh[nt][0], bl[nt][0]);
                    split_tf32(u1, bh[nt][1], bl[nt][1]);
                } else {
                    bh[nt][0] = f2tf32(u0); bh[nt][1] = f2tf32(u1);
                }
            }
            #pragma unroll
            for (int mt = 0; mt < MT; mt++)
                #pragma unroll
                for (int nt = 0; nt < NT; nt++) {
                    mma8(acc[mt][nt], ah[mt], bh[nt]);
                    if (COMP) {
                        mma8(acc[mt][nt], ah[mt], bl[nt]);
                        mma8(acc[mt][nt], al[mt], bh[nt]);
                    }
                }
        }
    }

    #pragma unroll
    for (int mt = 0; mt < MT; mt++) {
        int m = m0 + wm * WM + mt * 16 + (lane >> 2);
        #pragma unroll
        for (int nt = 0; nt < NT; nt++) {
            int n = n0 + wn * WN + nt * 8 + (lane & 3) * 2;
            #pragma unroll
            for (int half = 0; half < 2; half++) {
                int mm = m + half * 8;
                float r0 = acc[mt][nt][half * 2];
                float r1 = acc[mt][nt][half * 2 + 1];
                if (n < N) {
                    if (EPI == 1) r0 += Cc[mm * N + n];
                    if (EPI == 2) r0 = gelu_f(r0);
                    Cc[mm * N + n] = r0;
                }
                if (n + 1 < N) {
                    if (EPI == 1) r1 += Cc[mm * N + n + 1];
                    if (EPI == 2) r1 = gelu_f(r1);
                    Cc[mm * N + n + 1] = r1;
                }
            }
        }
    }
}

// ------------------------------------------------------------------
// Grid-wide barrier (all 128 blocks guaranteed resident)
// ------------------------------------------------------------------
__device__ __forceinline__ void grid_barrier() {
    __syncthreads();
    if (threadIdx.x == 0) {
        __threadfence();
        unsigned gen = atomicAdd(&g_bar_gen, 0u);
        unsigned t = atomicAdd(&g_bar_cnt, 1u);
        if (t == gridDim.x - 1) {
            atomicExch(&g_bar_cnt, 0u);
            __threadfence();
            atomicAdd(&g_bar_gen, 1u);
        } else {
            while (atomicAdd(&g_bar_gen, 0u) == gen) __nanosleep(64);
        }
    }
    __syncthreads();
}

// ------------------------------------------------------------------
// Persistent pscan: all 10 Kogge-Stone steps in one launch.
// 128 blocks x 256 threads, 16 tokens/block.
// mix GEMM (16x228 @ 228x228) via 3xTF32 mma, then combine.
// smem floats: mA[16][236], rr[16][232], mx[16][232], wc[120][260]
// ------------------------------------------------------------------
#define SC_MA  (16 * 236)
#define SC_RR  (16 * 232)
#define SC_MX  (16 * 232)
#define SC_WC  (120 * 260)
#define SC_SMEM_FLOATS (SC_MA + SC_RR + SC_MX + SC_WC)

__global__ __launch_bounds__(256) void scan_all_kernel(
    float* __restrict__ x0, float* __restrict__ x1,
    const float* __restrict__ wsc, const float* __restrict__ ident)
{
    extern __shared__ float sm[];
    float* mA = sm;                  // [t*236 + c]  (left+right)
    float* rr = mA + SC_MA;          // [t*232 + c]  (right)
    float* mx = rr + SC_RR;          // [t*232 + c]  (mix)
    float* wc = mx + SC_MX;          // [k*260 + c]  (W chunk, zero-padded)

    const int tid = threadIdx.x;
    const int lane = tid & 31, wid = tid >> 5;
    const int T0 = blockIdx.x * 16;

    int step = 0;
    for (int off = 1; off < SEQ; off <<= 1, step++) {
        const float* xin = (step & 1) ? x1 : x0;
        float* xout      = (step & 1) ? x0 : x1;

        // ---- load own tokens + shifted-left rows ----
        if (tid < 236) {
            int c = tid;
            #pragma unroll
            for (int t = 0; t < 16; t++) {
                int tok = T0 + t;
                int tt = tok & (SEQ - 1);
                float rv = 0.f, lv = 0.f;
                if (c < C_DIM) {
                    rv = xin[tok * C_DIM + c];
                    lv = (tt >= off) ? xin[(tok - off) * C_DIM + c] : ident[c];
                }
                if (c < 232) rr[t * 232 + c] = rv;
                mA[t * 236 + c] = lv + rv;
            }
        }
        __syncthreads();

        // ---- mix = mA @ W via 3xTF32 tensor MMA ----
        // warp wid covers cols [wid*32, wid*32+32); rows = the 16 tokens (one m16 tile)
        float acc[4][4];
        #pragma unroll
        for (int i = 0; i < 4; i++)
            #pragma unroll
            for (int j = 0; j < 4; j++) acc[i][j] = 0.f;

        #pragma unroll
        for (int ci = 0; ci < 2; ci++) {
            int k0 = ci * 114;
            // stage W chunk [114 rows -> padded 120][228 cols -> padded 260]
            for (int i = tid; i < 120 * 65; i += 256) {
                int kk = i / 65, c4 = i - kk * 65;
                float4 v = make_float4(0.f,0.f,0.f,0.f);
                if (kk < 114 && c4 < 57)
                    v = *(const float4*)&wsc[(k0 + kk) * C_DIM + c4 * 4];
                *(float4*)&wc[kk * 260 + c4 * 4] = v;
            }
            __syncthreads();
            #pragma unroll
            for (int kc8 = 0; kc8 < 15; kc8++) {
                int kloc = kc8 * 8;
                int kglob = k0 + kloc;
                uint32_t ah[4], al[4], bh[2], bl[2];
                {
                    int r = lane >> 2;
                    float v0 = mA[r * 236       + kglob     + (lane & 3)];
                    float v1 = mA[(r + 8) * 236 + kglob     + (lane & 3)];
                    float v2 = mA[r * 236       + kglob + 4 + (lane & 3)];
                    float v3 = mA[(r + 8) * 236 + kglob + 4 + (lane & 3)];
                    split_tf32(v0, ah[0], al[0]);
                    split_tf32(v1, ah[1], al[1]);
                    split_tf32(v2, ah[2], al[2]);
                    split_tf32(v3, ah[3], al[3]);
                }
                #pragma unroll
                for (int nt = 0; nt < 4; nt++) {
                    int n = wid * 32 + nt * 8 + (lane >> 2);
                    float u0 = wc[(kloc     + (lane & 3)) * 260 + n];
                    float u1 = wc[(kloc + 4 + (lane & 3)) * 260 + n];
                    split_tf32(u0, bh[0], bl[0]);
                    split_tf32(u1, bh[1], bl[1]);
                    mma8(acc[nt], ah, bh);
                    mma8(acc[nt], ah, bl);
                    mma8(acc[nt], al, bh);
                }
            }
            __syncthreads();  // all warps done with wc before reload
        }

        // ---- store mix to smem ----
        #pragma unroll
        for (int nt = 0; nt < 4; nt++) {
            int n = wid * 32 + nt * 8 + (lane & 3) * 2;
            int r = lane >> 2;
            if (n < C_DIM) {
                mx[r * 232 + n]           = acc[nt][0];
                mx[r * 232 + n + 1]       = acc[nt][1];
                mx[(r + 8) * 232 + n]     = acc[nt][2];
                mx[(r + 8) * 232 + n + 1] = acc[nt][3];
            }
        }
        __syncthreads();

        // ---- combine: 64 (token,lane-head) pairs, 8 per warp ----
        const int d0 = lane;
        const int d1 = lane + 32;
        const bool has1 = (lane < HD - 32);
        #pragma unroll
        for (int e = 0; e < 8; e++) {
            int p = wid * 8 + e;
            int t = p >> 2;
            int l = p & 3;
            int tok = T0 + t;

            float q0 = mA[t * 236 + l * HD + d0] - rr[t * 232 + l * HD + d0];
            float q1 = has1 ? (mA[t * 236 + l * HD + d1] - rr[t * 232 + l * HD + d1]) : 0.f;

            float sc[4];
            #pragma unroll
            for (int m = 0; m < 4; m++) {
                float pr = q0 * rr[t * 232 + m * HD + d0];
                if (has1) pr += q1 * rr[t * 232 + m * HD + d1];
                #pragma unroll
                for (int o = 16; o > 0; o >>= 1) pr += __shfl_xor_sync(0xffffffffu, pr, o);
                sc[m] = pr * 0.13245323570650439f;  // 1/sqrt(57)
            }
            float mxv = fmaxf(fmaxf(sc[0], sc[1]), fmaxf(sc[2], sc[3]));
            float e0 = expf(sc[0] - mxv), e1 = expf(sc[1] - mxv);
            float e2 = expf(sc[2] - mxv), e3 = expf(sc[3] - mxv);
            float inv = 1.0f / (e0 + e1 + e2 + e3);
            float a0 = e0 * inv, a1 = e1 * inv, a2 = e2 * inv, a3 = e3 * inv;

            float z0 = a0 * mx[t * 232 + 0 * HD + d0] + a1 * mx[t * 232 + 1 * HD + d0]
                     + a2 * mx[t * 232 + 2 * HD + d0] + a3 * mx[t * 232 + 3 * HD + d0];
            float z1 = 0.f;
            if (has1)
                z1 = a0 * mx[t * 232 + 0 * HD + d1] + a1 * mx[t * 232 + 1 * HD + d1]
                   + a2 * mx[t * 232 + 2 * HD + d1] + a3 * mx[t * 232 + 3 * HD + d1];

            float ss = z0 * z0 + z1 * z1;
            #pragma unroll
            for (int o = 16; o > 0; o >>= 1) ss += __shfl_xor_sync(0xffffffffu, ss, o);
            float scale = rsqrtf(ss * (1.0f / 57.0f) + 1e-6f) / (1.0f + (float)l);

            xout[tok * C_DIM + l * HD + d0] = q0 + z0 * scale;
            if (has1) xout[tok * C_DIM + l * HD + d1] = q1 + z1 * scale;
        }

        if ((off << 1) < SEQ) grid_barrier();
    }
}

// ------------------------------------------------------------------
extern "C" void kernel_launch(void* const* d_in, const int* in_sizes, int n_in,
                              void* d_out, int out_size) {
    const int*   idx    = (const int*)  d_in[0];
    const float* wte    = (const float*)d_in[1];
    const float* ln1_g  = (const float*)d_in[2];
    const float* ln2_g  = (const float*)d_in[3];
    const float* w_up   = (const float*)d_in[4];
    const float* w_v    = (const float*)d_in[5];
    const float* w_cpr  = (const float*)d_in[6];
    const float* w_scan = (const float*)d_in[7];
    const float* ident  = (const float*)d_in[8];
    const float* w_fc   = (const float*)d_in[9];
    const float* w_proj = (const float*)d_in[10];
    float* out = (float*)d_out;

    float *px, *ph, *pv, *pa, *pb, *pmlp;
    cudaGetSymbolAddress((void**)&px,   g_x);
    cudaGetSymbolAddress((void**)&ph,   g_h);
    cudaGetSymbolAddress((void**)&pv,   g_v);
    cudaGetSymbolAddress((void**)&pa,   g_bufA);
    cudaGetSymbolAddress((void**)&pb,   g_bufB);
    cudaGetSymbolAddress((void**)&pmlp, g_mlp);

    const int scan_smem = SC_SMEM_FLOATS * 4;
    cudaFuncSetAttribute(scan_all_kernel,
                         cudaFuncAttributeMaxDynamicSharedMemorySize, scan_smem);

    const int CC = C_DIM * C_DIM;
    const int FC = FF * C_DIM;

    embed_kernel<<<(TOKENS * C_DIM + 255) / 256, 256>>>(idx, wte, px);

    for (int L = 0; L < NLAYER; L++) {
        const float* wupL  = w_up   + L * CC;
        const float* wvL   = w_v    + L * CC;
        const float* wcprL = w_cpr  + L * CC;
        const float* wscL  = w_scan + L * CC;
        const float* idL   = ident  + L * C_DIM;
        const float* wfcL  = w_fc   + L * FC;
        const float* wprL  = w_proj + L * FC;

        ln_kernel<<<(TOKENS * 32 + 255) / 256, 256>>>(px, ln1_g + L * C_DIM, ph);

        dim3 gs(TOKENS / 64, (C_DIM + 63) / 64);
        tc_gemm<64,64,32,32,1,0,0><<<gs, 128>>>(ph, nullptr, wupL, pa, TOKENS, C_DIM, C_DIM);
        tc_gemm<64,64,32,32,1,0,0><<<gs, 128>>>(ph, nullptr, wvL,  pv, TOKENS, C_DIM, C_DIM);

        // persistent pscan: 10 steps, ends with result in pa
        scan_all_kernel<<<TOKENS / 16, 256, scan_smem>>>(pa, pb, wscL, idL);

        tc_gemm<64,64,32,32,1,2,1><<<gs, 128>>>(pa, pv, wcprL, px, TOKENS, C_DIM, C_DIM);

        ln_kernel<<<(TOKENS * 32 + 255) / 256, 256>>>(px, ln2_g + L * C_DIM, ph);

        dim3 gf(TOKENS / 64, (FF + 63) / 64);
        tc_gemm<64,64,32,32,1,0,2><<<gf, 128>>>(ph, nullptr, wfcL, pmlp, TOKENS, FF, C_DIM);
        tc_gemm<64,64,32,32,1,0,1><<<gs, 128>>>(pmlp, nullptr, wprL, px, TOKENS, C_DIM, FF);
    }

    dim3 gl(TOKENS / 128, (VOCAB + 127) / 128);
    tc_gemm<128,128,64,32,0,0,0><<<gl, 256>>>(px, nullptr, wte, out, TOKENS, VOCAB, C_DIM);
}

// round 6
// speedup vs baseline: 3.0145x; 1.1061x over previous
#include <cuda_runtime.h>
#include <cuda_fp16.h>
#include <cstdint>
#include <math.h>

#define C_DIM 228
#define TOKENS 2048
#define SEQ 1024
#define HD 57
#define LANES 4
#define FF 912
#define NLAYER 4
#define VOCAB 50257

// ------------------------------------------------------------------
// Scratch
// ------------------------------------------------------------------
__device__ float g_x   [TOKENS * C_DIM];
__device__ float g_h   [TOKENS * C_DIM];
__device__ float g_v   [TOKENS * C_DIM];
__device__ float g_bufA[TOKENS * C_DIM];
__device__ float g_bufB[TOKENS * C_DIM];
__device__ float g_mlp [TOKENS * FF];
__device__ unsigned g_bar_cnt = 0;
__device__ unsigned g_bar_gen = 0;

__device__ __forceinline__ float gelu_f(float x) {
    float x3 = x * x * x;
    return 0.5f * x * (1.0f + tanhf(0.7978845608028654f * (x + 0.044715f * x3)));
}

__device__ __forceinline__ uint32_t f2tf32(float x) {
    uint32_t r;
    asm("cvt.rna.tf32.f32 %0, %1;" : "=r"(r) : "f"(x));
    return r;
}
__device__ __forceinline__ void split_tf32(float x, uint32_t& hi, uint32_t& lo) {
    hi = f2tf32(x);
    lo = f2tf32(x - __uint_as_float(hi));
}
__device__ __forceinline__ void mma8(float* c, const uint32_t* a, const uint32_t* b) {
    asm volatile("mma.sync.aligned.m16n8k8.row.col.f32.tf32.tf32.f32 "
        "{%0,%1,%2,%3}, {%4,%5,%6,%7}, {%8,%9}, {%0,%1,%2,%3};"
        : "+f"(c[0]), "+f"(c[1]), "+f"(c[2]), "+f"(c[3])
        : "r"(a[0]), "r"(a[1]), "r"(a[2]), "r"(a[3]), "r"(b[0]), "r"(b[1]));
}
// fp16 m16n8k16 with fp32 accumulate
__device__ __forceinline__ void mma16(float* c, const uint32_t* a, const uint32_t* b) {
    asm volatile("mma.sync.aligned.m16n8k16.row.col.f32.f16.f16.f32 "
        "{%0,%1,%2,%3}, {%4,%5,%6,%7}, {%8,%9}, {%0,%1,%2,%3};"
        : "+f"(c[0]), "+f"(c[1]), "+f"(c[2]), "+f"(c[3])
        : "r"(a[0]), "r"(a[1]), "r"(a[2]), "r"(a[3]), "r"(b[0]), "r"(b[1]));
}
__device__ __forceinline__ uint32_t pack_h2(float x, float y) {
    __half2 h = __halves2half2(__float2half_rn(x), __float2half_rn(y));
    return *(uint32_t*)&h;
}
__device__ __forceinline__ void split_h2(float x, float y, uint32_t& hi, uint32_t& lo) {
    __half hx = __float2half_rn(x), hy = __float2half_rn(y);
    float rx = x - __half2float(hx), ry = y - __half2float(hy);
    __half2 h = __halves2half2(hx, hy);
    __half2 l = __halves2half2(__float2half_rn(rx), __float2half_rn(ry));
    hi = *(uint32_t*)&h;
    lo = *(uint32_t*)&l;
}

// ------------------------------------------------------------------
// Embedding gather (int32/int64 auto-detect)
// ------------------------------------------------------------------
__global__ __launch_bounds__(256) void embed_kernel(const int* __restrict__ idx32,
                                                    const float* __restrict__ wte,
                                                    float* __restrict__ x) {
    __shared__ int s_is64;
    if (threadIdx.x == 0) {
        int all0 = 1;
        #pragma unroll
        for (int i = 1; i < 16; i += 2)
            if (idx32[i] != 0) all0 = 0;
        s_is64 = all0;
    }
    __syncthreads();
    int gid = blockIdx.x * 256 + threadIdx.x;
    if (gid >= TOKENS * C_DIM) return;
    int t = gid / C_DIM;
    int c = gid - t * C_DIM;
    int id = s_is64 ? idx32[2 * t] : idx32[t];
    x[gid] = wte[id * C_DIM + c];
}

// ------------------------------------------------------------------
// LayerNorm, one warp per token
// ------------------------------------------------------------------
__global__ __launch_bounds__(256) void ln_kernel(const float* __restrict__ x,
                                                 const float* __restrict__ g,
                                                 float* __restrict__ out) {
    int w = (blockIdx.x * 256 + threadIdx.x) >> 5;
    int lane = threadIdx.x & 31;
    if (w >= TOKENS) return;
    const float* row = x + w * C_DIM;
    float s = 0.f, s2 = 0.f;
    for (int c = lane; c < C_DIM; c += 32) {
        float v = row[c];
        s += v; s2 += v * v;
    }
    #pragma unroll
    for (int o = 16; o > 0; o >>= 1) {
        s  += __shfl_xor_sync(0xffffffffu, s, o);
        s2 += __shfl_xor_sync(0xffffffffu, s2, o);
    }
    float mean = s * (1.0f / C_DIM);
    float var = s2 * (1.0f / C_DIM) - mean * mean;
    float rstd = rsqrtf(var + 1e-5f);
    float* orow = out + w * C_DIM;
    for (int c = lane; c < C_DIM; c += 32)
        orow[c] = (row[c] - mean) * rstd * g[c];
}

// ------------------------------------------------------------------
// Split-fp16 internal GEMM (NT): out[m,n] = sum_k A[m,k]*B[n,k]
// BM=64, BN=64, BK=32, 256 threads (8 warps, 2x4), warp tile 32x16.
// Each thread stages 2 float4 per operand (full 64x32 tile coverage).
// hi/lo split at staging; 3 MMAs per (mt,nt,k16) -> fp32-like accuracy.
// AMODE 0: A; 2: A*A2. EPI 0: store; 1: +=; 2: gelu.
// ------------------------------------------------------------------
template<int AMODE, int EPI>
__global__ __launch_bounds__(256) void hgemm(
    const float* __restrict__ A, const float* __restrict__ A2,
    const float* __restrict__ B, float* __restrict__ Cc,
    int M, int N, int K)
{
    __shared__ uint32_t Ah[64][20], Al[64][20], Bh[64][20], Bl[64][20];
    const int tid = threadIdx.x;
    const int lane = tid & 31, wid = tid >> 5;
    const int wm = wid >> 2, wn = wid & 3;
    const int l3 = lane & 3, lq = lane >> 2;
    const int m0 = blockIdx.x * 64, n0 = blockIdx.y * 64;

    float acc[2][2][4];
    #pragma unroll
    for (int i = 0; i < 2; i++)
        #pragma unroll
        for (int j = 0; j < 2; j++)
            #pragma unroll
            for (int q = 0; q < 4; q++) acc[i][j][q] = 0.f;

    const int nchunk = (K + 31) / 32;

    float4 pa[2], pb[2];
    #pragma unroll
    for (int i = 0; i < 2; i++) {
        int idx = tid + i * 256;
        int r = idx >> 3, f = idx & 7;
        int k = f * 4;
        float4 v = make_float4(0.f,0.f,0.f,0.f);
        if (k + 3 < K) {
            v = *(const float4*)&A[(m0 + r) * K + k];
            if (AMODE == 2) {
                float4 u = *(const float4*)&A2[(m0 + r) * K + k];
                v.x *= u.x; v.y *= u.y; v.z *= u.z; v.w *= u.w;
            }
        }
        pa[i] = v;
        v = make_float4(0.f,0.f,0.f,0.f);
        if (k + 3 < K && (n0 + r) < N)
            v = *(const float4*)&B[(n0 + r) * K + k];
        pb[i] = v;
    }

    for (int ch = 0; ch < nchunk; ch++) {
        __syncthreads();
        #pragma unroll
        for (int i = 0; i < 2; i++) {
            int idx = tid + i * 256;
            int r = idx >> 3, f = idx & 7;
            uint32_t h0, l0, h1, l1;
            split_h2(pa[i].x, pa[i].y, h0, l0);
            split_h2(pa[i].z, pa[i].w, h1, l1);
            Ah[r][f*2] = h0; Ah[r][f*2+1] = h1;
            Al[r][f*2] = l0; Al[r][f*2+1] = l1;
            split_h2(pb[i].x, pb[i].y, h0, l0);
            split_h2(pb[i].z, pb[i].w, h1, l1);
            Bh[r][f*2] = h0; Bh[r][f*2+1] = h1;
            Bl[r][f*2] = l0; Bl[r][f*2+1] = l1;
        }
        __syncthreads();
        if (ch + 1 < nchunk) {
            int k0 = (ch + 1) * 32;
            #pragma unroll
            for (int i = 0; i < 2; i++) {
                int idx = tid + i * 256;
                int r = idx >> 3, f = idx & 7;
                int k = k0 + f * 4;
                float4 v = make_float4(0.f,0.f,0.f,0.f);
                if (k + 3 < K) {
                    v = *(const float4*)&A[(m0 + r) * K + k];
                    if (AMODE == 2) {
                        float4 u = *(const float4*)&A2[(m0 + r) * K + k];
                        v.x *= u.x; v.y *= u.y; v.z *= u.z; v.w *= u.w;
                    }
                }
                pa[i] = v;
                v = make_float4(0.f,0.f,0.f,0.f);
                if (k + 3 < K && (n0 + r) < N)
                    v = *(const float4*)&B[(n0 + r) * K + k];
                pb[i] = v;
            }
        }
        #pragma unroll
        for (int kc2 = 0; kc2 < 16; kc2 += 8) {
            uint32_t ah[2][4], al[2][4], bh[2][2], bl[2][2];
            #pragma unroll
            for (int mt = 0; mt < 2; mt++) {
                int r = wm * 32 + mt * 16 + lq;
                ah[mt][0] = Ah[r    ][kc2 + l3];
                ah[mt][1] = Ah[r + 8][kc2 + l3];
                ah[mt][2] = Ah[r    ][kc2 + 4 + l3];
                ah[mt][3] = Ah[r + 8][kc2 + 4 + l3];
                al[mt][0] = Al[r    ][kc2 + l3];
                al[mt][1] = Al[r + 8][kc2 + l3];
                al[mt][2] = Al[r    ][kc2 + 4 + l3];
                al[mt][3] = Al[r + 8][kc2 + 4 + l3];
            }
            #pragma unroll
            for (int nt = 0; nt < 2; nt++) {
                int n = wn * 16 + nt * 8 + lq;
                bh[nt][0] = Bh[n][kc2 + l3];
                bh[nt][1] = Bh[n][kc2 + 4 + l3];
                bl[nt][0] = Bl[n][kc2 + l3];
                bl[nt][1] = Bl[n][kc2 + 4 + l3];
            }
            #pragma unroll
            for (int mt = 0; mt < 2; mt++)
                #pragma unroll
                for (int nt = 0; nt < 2; nt++) {
                    mma16(acc[mt][nt], ah[mt], bh[nt]);
                    mma16(acc[mt][nt], ah[mt], bl[nt]);
                    mma16(acc[mt][nt], al[mt], bh[nt]);
                }
        }
    }

    #pragma unroll
    for (int mt = 0; mt < 2; mt++) {
        #pragma unroll
        for (int nt = 0; nt < 2; nt++) {
            int n = n0 + wn * 16 + nt * 8 + l3 * 2;
            #pragma unroll
            for (int half = 0; half < 2; half++) {
                int mm = m0 + wm * 32 + mt * 16 + lq + half * 8;
                float r0 = acc[mt][nt][half * 2];
                float r1 = acc[mt][nt][half * 2 + 1];
                if (n < N) {
                    if (EPI == 1) r0 += Cc[mm * N + n];
                    if (EPI == 2) r0 = gelu_f(r0);
                    Cc[mm * N + n] = r0;
                }
                if (n + 1 < N) {
                    if (EPI == 1) r1 += Cc[mm * N + n + 1];
                    if (EPI == 2) r1 = gelu_f(r1);
                    Cc[mm * N + n + 1] = r1;
                }
            }
        }
    }
}

// ------------------------------------------------------------------
// fp16 lm_head (NT): out[m,n] = sum_k A[m,k]*wte[n,k]; fp32 accumulate.
// BM=128, BN=128, BK=128 (2 chunks for K=228). 256 threads, 8 warps
// (2x4), warp tile 64x32. Convert f32->half2 once at staging.
// dyn smem: As2[128][68] + Bs2[128][68] u32 = 69632 B.
// ------------------------------------------------------------------
#define LMH_SMEM (2 * 128 * 68 * 4)

__global__ __launch_bounds__(256) void lmhead_h(
    const float* __restrict__ A, const float* __restrict__ B,
    float* __restrict__ C)
{
    extern __shared__ uint32_t dsm[];
    uint32_t* As2 = dsm;               // [r*68 + c2]
    uint32_t* Bs2 = dsm + 128 * 68;

    const int tid = threadIdx.x;
    const int lane = tid & 31, wid = tid >> 5;
    const int wm = wid >> 2, wn = wid & 3;
    const int l3 = lane & 3, lq = lane >> 2;
    const int m0 = blockIdx.x * 128, n0 = blockIdx.y * 128;

    float acc[4][4][4];
    #pragma unroll
    for (int i = 0; i < 4; i++)
        #pragma unroll
        for (int j = 0; j < 4; j++)
            #pragma unroll
            for (int q = 0; q < 4; q++) acc[i][j][q] = 0.f;

    #pragma unroll 1
    for (int kc = 0; kc < 2; kc++) {
        __syncthreads();
        #pragma unroll
        for (int i = 0; i < 16; i++) {
            int idx = tid + i * 256;
            int r = idx >> 5, f4 = idx & 31;
            int k = kc * 128 + f4 * 4;
            float4 va = make_float4(0.f,0.f,0.f,0.f);
            float4 vb = make_float4(0.f,0.f,0.f,0.f);
            if (k + 3 < C_DIM) {
                va = *(const float4*)&A[(m0 + r) * C_DIM + k];
                if (n0 + r < VOCAB)
                    vb = *(const float4*)&B[(n0 + r) * C_DIM + k];
            }
            As2[r * 68 + f4 * 2]     = pack_h2(va.x, va.y);
            As2[r * 68 + f4 * 2 + 1] = pack_h2(va.z, va.w);
            Bs2[r * 68 + f4 * 2]     = pack_h2(vb.x, vb.y);
            Bs2[r * 68 + f4 * 2 + 1] = pack_h2(vb.z, vb.w);
        }
        __syncthreads();
        #pragma unroll
        for (int kc2 = 0; kc2 < 64; kc2 += 8) {
            uint32_t af[4][4], bf[4][2];
            #pragma unroll
            for (int mt = 0; mt < 4; mt++) {
                int r = wm * 64 + mt * 16 + lq;
                af[mt][0] = As2[r * 68 + kc2 + l3];
                af[mt][1] = As2[(r + 8) * 68 + kc2 + l3];
                af[mt][2] = As2[r * 68 + kc2 + 4 + l3];
                af[mt][3] = As2[(r + 8) * 68 + kc2 + 4 + l3];
            }
            #pragma unroll
            for (int nt = 0; nt < 4; nt++) {
                int n = wn * 32 + nt * 8 + lq;
                bf[nt][0] = Bs2[n * 68 + kc2 + l3];
                bf[nt][1] = Bs2[n * 68 + kc2 + 4 + l3];
            }
            #pragma unroll
            for (int mt = 0; mt < 4; mt++)
                #pragma unroll
                for (int nt = 0; nt < 4; nt++)
                    mma16(acc[mt][nt], af[mt], bf[nt]);
        }
    }

    #pragma unroll
    for (int mt = 0; mt < 4; mt++) {
        #pragma unroll
        for (int nt = 0; nt < 4; nt++) {
            int n = n0 + wn * 32 + nt * 8 + l3 * 2;
            #pragma unroll
            for (int half = 0; half < 2; half++) {
                int mm = m0 + wm * 64 + mt * 16 + lq + half * 8;
                float* dst = &C[(size_t)mm * VOCAB + n];
                if (n     < VOCAB) dst[0] = acc[mt][nt][half * 2];
                if (n + 1 < VOCAB) dst[1] = acc[mt][nt][half * 2 + 1];
            }
        }
    }
}

// ------------------------------------------------------------------
// Grid-wide barrier (all 128 blocks resident)
// ------------------------------------------------------------------
__device__ __forceinline__ void grid_barrier() {
    __syncthreads();
    if (threadIdx.x == 0) {
        __threadfence();
        unsigned gen = atomicAdd(&g_bar_gen, 0u);
        unsigned t = atomicAdd(&g_bar_cnt, 1u);
        if (t == gridDim.x - 1) {
            atomicExch(&g_bar_cnt, 0u);
            __threadfence();
            atomicAdd(&g_bar_gen, 1u);
        } else {
            while (atomicAdd(&g_bar_gen, 0u) == gen) __nanosleep(64);
        }
    }
    __syncthreads();
}

// ------------------------------------------------------------------
// Persistent pscan (R3-proven): 10 Kogge-Stone steps, 3xTF32 mix GEMM
// 128 blocks x 256 threads, 16 tokens/block.
// ------------------------------------------------------------------
#define SC_MA  (16 * 236)
#define SC_RR  (16 * 232)
#define SC_MX  (16 * 232)
#define SC_WC  (120 * 260)
#define SC_SMEM_FLOATS (SC_MA + SC_RR + SC_MX + SC_WC)

__global__ __launch_bounds__(256) void scan_all_kernel(
    float* __restrict__ x0, float* __restrict__ x1,
    const float* __restrict__ wsc, const float* __restrict__ ident)
{
    extern __shared__ float sm[];
    float* mA = sm;
    float* rr = mA + SC_MA;
    float* mx = rr + SC_RR;
    float* wc = mx + SC_MX;

    const int tid = threadIdx.x;
    const int lane = tid & 31, wid = tid >> 5;
    const int T0 = blockIdx.x * 16;

    int step = 0;
    for (int off = 1; off < SEQ; off <<= 1, step++) {
        const float* xin = (step & 1) ? x1 : x0;
        float* xout      = (step & 1) ? x0 : x1;

        if (tid < 236) {
            int c = tid;
            #pragma unroll
            for (int t = 0; t < 16; t++) {
                int tok = T0 + t;
                int tt = tok & (SEQ - 1);
                float rv = 0.f, lv = 0.f;
                if (c < C_DIM) {
                    rv = xin[tok * C_DIM + c];
                    lv = (tt >= off) ? xin[(tok - off) * C_DIM + c] : ident[c];
                }
                if (c < 232) rr[t * 232 + c] = rv;
                mA[t * 236 + c] = lv + rv;
            }
        }
        __syncthreads();

        float acc[4][4];
        #pragma unroll
        for (int i = 0; i < 4; i++)
            #pragma unroll
            for (int j = 0; j < 4; j++) acc[i][j] = 0.f;

        #pragma unroll
        for (int ci = 0; ci < 2; ci++) {
            int k0 = ci * 114;
            for (int i = tid; i < 120 * 65; i += 256) {
                int kk = i / 65, c4 = i - kk * 65;
                float4 v = make_float4(0.f,0.f,0.f,0.f);
                if (kk < 114 && c4 < 57)
                    v = *(const float4*)&wsc[(k0 + kk) * C_DIM + c4 * 4];
                *(float4*)&wc[kk * 260 + c4 * 4] = v;
            }
            __syncthreads();
            #pragma unroll
            for (int kc8 = 0; kc8 < 15; kc8++) {
                int kloc = kc8 * 8;
                int kglob = k0 + kloc;
                uint32_t ah[4], al[4], bh[2], bl[2];
                {
                    int r = lane >> 2;
                    float v0 = mA[r * 236       + kglob     + (lane & 3)];
                    float v1 = mA[(r + 8) * 236 + kglob     + (lane & 3)];
                    float v2 = mA[r * 236       + kglob + 4 + (lane & 3)];
                    float v3 = mA[(r + 8) * 236 + kglob + 4 + (lane & 3)];
                    split_tf32(v0, ah[0], al[0]);
                    split_tf32(v1, ah[1], al[1]);
                    split_tf32(v2, ah[2], al[2]);
                    split_tf32(v3, ah[3], al[3]);
                }
                #pragma unroll
                for (int nt = 0; nt < 4; nt++) {
                    int n = wid * 32 + nt * 8 + (lane >> 2);
                    float u0 = wc[(kloc     + (lane & 3)) * 260 + n];
                    float u1 = wc[(kloc + 4 + (lane & 3)) * 260 + n];
                    split_tf32(u0, bh[0], bl[0]);
                    split_tf32(u1, bh[1], bl[1]);
                    mma8(acc[nt], ah, bh);
                    mma8(acc[nt], ah, bl);
                    mma8(acc[nt], al, bh);
                }
            }
            __syncthreads();
        }

        #pragma unroll
        for (int nt = 0; nt < 4; nt++) {
            int n = wid * 32 + nt * 8 + (lane & 3) * 2;
            int r = lane >> 2;
            if (n < C_DIM) {
                mx[r * 232 + n]           = acc[nt][0];
                mx[r * 232 + n + 1]       = acc[nt][1];
                mx[(r + 8) * 232 + n]     = acc[nt][2];
                mx[(r + 8) * 232 + n + 1] = acc[nt][3];
            }
        }
        __syncthreads();

        const int d0 = lane;
        const int d1 = lane + 32;
        const bool has1 = (lane < HD - 32);
        #pragma unroll
        for (int e = 0; e < 8; e++) {
            int p = wid * 8 + e;
            int t = p >> 2;
            int l = p & 3;
            int tok = T0 + t;

            float q0 = mA[t * 236 + l * HD + d0] - rr[t * 232 + l * HD + d0];
            float q1 = has1 ? (mA[t * 236 + l * HD + d1] - rr[t * 232 + l * HD + d1]) : 0.f;

            float sc[4];
            #pragma unroll
            for (int m = 0; m < 4; m++) {
                float pr = q0 * rr[t * 232 + m * HD + d0];
                if (has1) pr += q1 * rr[t * 232 + m * HD + d1];
                #pragma unroll
                for (int o = 16; o > 0; o >>= 1) pr += __shfl_xor_sync(0xffffffffu, pr, o);
                sc[m] = pr * 0.13245323570650439f;
            }
            float mxv = fmaxf(fmaxf(sc[0], sc[1]), fmaxf(sc[2], sc[3]));
            float e0 = expf(sc[0] - mxv), e1 = expf(sc[1] - mxv);
            float e2 = expf(sc[2] - mxv), e3 = expf(sc[3] - mxv);
            float inv = 1.0f / (e0 + e1 + e2 + e3);
            float a0 = e0 * inv, a1 = e1 * inv, a2 = e2 * inv, a3 = e3 * inv;

            float z0 = a0 * mx[t * 232 + 0 * HD + d0] + a1 * mx[t * 232 + 1 * HD + d0]
                     + a2 * mx[t * 232 + 2 * HD + d0] + a3 * mx[t * 232 + 3 * HD + d0];
            float z1 = 0.f;
            if (has1)
                z1 = a0 * mx[t * 232 + 0 * HD + d1] + a1 * mx[t * 232 + 1 * HD + d1]
                   + a2 * mx[t * 232 + 2 * HD + d1] + a3 * mx[t * 232 + 3 * HD + d1];

            float ss = z0 * z0 + z1 * z1;
            #pragma unroll
            for (int o = 16; o > 0; o >>= 1) ss += __shfl_xor_sync(0xffffffffu, ss, o);
            float scale = rsqrtf(ss * (1.0f / 57.0f) + 1e-6f) / (1.0f + (float)l);

            xout[tok * C_DIM + l * HD + d0] = q0 + z0 * scale;
            if (has1) xout[tok * C_DIM + l * HD + d1] = q1 + z1 * scale;
        }

        if ((off << 1) < SEQ) grid_barrier();
    }
}

// ------------------------------------------------------------------
extern "C" void kernel_launch(void* const* d_in, const int* in_sizes, int n_in,
                              void* d_out, int out_size) {
    const int*   idx    = (const int*)  d_in[0];
    const float* wte    = (const float*)d_in[1];
    const float* ln1_g  = (const float*)d_in[2];
    const float* ln2_g  = (const float*)d_in[3];
    const float* w_up   = (const float*)d_in[4];
    const float* w_v    = (const float*)d_in[5];
    const float* w_cpr  = (const float*)d_in[6];
    const float* w_scan = (const float*)d_in[7];
    const float* ident  = (const float*)d_in[8];
    const float* w_fc   = (const float*)d_in[9];
    const float* w_proj = (const float*)d_in[10];
    float* out = (float*)d_out;

    float *px, *ph, *pv, *pa, *pb, *pmlp;
    cudaGetSymbolAddress((void**)&px,   g_x);
    cudaGetSymbolAddress((void**)&ph,   g_h);
    cudaGetSymbolAddress((void**)&pv,   g_v);
    cudaGetSymbolAddress((void**)&pa,   g_bufA);
    cudaGetSymbolAddress((void**)&pb,   g_bufB);
    cudaGetSymbolAddress((void**)&pmlp, g_mlp);

    const int scan_smem = SC_SMEM_FLOATS * 4;
    cudaFuncSetAttribute(scan_all_kernel,
                         cudaFuncAttributeMaxDynamicSharedMemorySize, scan_smem);
    cudaFuncSetAttribute(lmhead_h,
                         cudaFuncAttributeMaxDynamicSharedMemorySize, LMH_SMEM);

    const int CC = C_DIM * C_DIM;
    const int FC = FF * C_DIM;

    embed_kernel<<<(TOKENS * C_DIM + 255) / 256, 256>>>(idx, wte, px);

    for (int L = 0; L < NLAYER; L++) {
        const float* wupL  = w_up   + L * CC;
        const float* wvL   = w_v    + L * CC;
        const float* wcprL = w_cpr  + L * CC;
        const float* wscL  = w_scan + L * CC;
        const float* idL   = ident  + L * C_DIM;
        const float* wfcL  = w_fc   + L * FC;
        const float* wprL  = w_proj + L * FC;

        ln_kernel<<<(TOKENS * 32 + 255) / 256, 256>>>(px, ln1_g + L * C_DIM, ph);

        dim3 gs(TOKENS / 64, (C_DIM + 63) / 64);
        hgemm<0,0><<<gs, 256>>>(ph, nullptr, wupL, pa, TOKENS, C_DIM, C_DIM);
        hgemm<0,0><<<gs, 256>>>(ph, nullptr, wvL,  pv, TOKENS, C_DIM, C_DIM);

        scan_all_kernel<<<TOKENS / 16, 256, scan_smem>>>(pa, pb, wscL, idL);

        hgemm<2,1><<<gs, 256>>>(pa, pv, wcprL, px, TOKENS, C_DIM, C_DIM);

        ln_kernel<<<(TOKENS * 32 + 255) / 256, 256>>>(px, ln2_g + L * C_DIM, ph);

        dim3 gf(TOKENS / 64, (FF + 63) / 64);
        hgemm<0,2><<<gf, 256>>>(ph, nullptr, wfcL, pmlp, TOKENS, FF, C_DIM);
        hgemm<0,1><<<gs, 256>>>(pmlp, nullptr, wprL, px, TOKENS, C_DIM, FF);
    }

    dim3 gl(TOKENS / 128, (VOCAB + 127) / 128);
    lmhead_h<<<gl, 256, LMH_SMEM>>>(px, wte, out);
}

// round 8
// speedup vs baseline: 3.3505x; 1.1115x over previous
#include <cuda_runtime.h>
#include <cuda_fp16.h>
#include <cstdint>
#include <math.h>

#define C_DIM 228
#define TOKENS 2048
#define SEQ 1024
#define HD 57
#define LANES 4
#define FF 912
#define NLAYER 4
#define VOCAB 50257
#define VPAD 50304          // 393*128, padded vocab rows
#define KPAD 256            // padded K row stride for half buffers

// ------------------------------------------------------------------
// Scratch
// ------------------------------------------------------------------
__device__ float g_x   [TOKENS * C_DIM];
__device__ float g_h   [TOKENS * C_DIM];
__device__ float g_v   [TOKENS * C_DIM];
__device__ float g_bufA[TOKENS * C_DIM];
__device__ float g_bufB[TOKENS * C_DIM];
__device__ float g_mlp [TOKENS * FF];
__device__ __half g_wte_h[VPAD * KPAD];     // fp16 wte, padded
__device__ __half g_x_h  [TOKENS * KPAD];   // fp16 final x, padded
__device__ unsigned g_bar_cnt = 0;
__device__ unsigned g_bar_gen = 0;

__device__ __forceinline__ float gelu_f(float x) {
    float x3 = x * x * x;
    return 0.5f * x * (1.0f + tanhf(0.7978845608028654f * (x + 0.044715f * x3)));
}

__device__ __forceinline__ uint32_t f2tf32(float x) {
    uint32_t r;
    asm("cvt.rna.tf32.f32 %0, %1;" : "=r"(r) : "f"(x));
    return r;
}
__device__ __forceinline__ void split_tf32(float x, uint32_t& hi, uint32_t& lo) {
    hi = f2tf32(x);
    lo = f2tf32(x - __uint_as_float(hi));
}
__device__ __forceinline__ void mma8(float* c, const uint32_t* a, const uint32_t* b) {
    asm volatile("mma.sync.aligned.m16n8k8.row.col.f32.tf32.tf32.f32 "
        "{%0,%1,%2,%3}, {%4,%5,%6,%7}, {%8,%9}, {%0,%1,%2,%3};"
        : "+f"(c[0]), "+f"(c[1]), "+f"(c[2]), "+f"(c[3])
        : "r"(a[0]), "r"(a[1]), "r"(a[2]), "r"(a[3]), "r"(b[0]), "r"(b[1]));
}
__device__ __forceinline__ void mma16(float* c, const uint32_t* a, const uint32_t* b) {
    asm volatile("mma.sync.aligned.m16n8k16.row.col.f32.f16.f16.f32 "
        "{%0,%1,%2,%3}, {%4,%5,%6,%7}, {%8,%9}, {%0,%1,%2,%3};"
        : "+f"(c[0]), "+f"(c[1]), "+f"(c[2]), "+f"(c[3])
        : "r"(a[0]), "r"(a[1]), "r"(a[2]), "r"(a[3]), "r"(b[0]), "r"(b[1]));
}
__device__ __forceinline__ uint32_t pack_h2(float x, float y) {
    __half2 h = __halves2half2(__float2half_rn(x), __float2half_rn(y));
    return *(uint32_t*)&h;
}
__device__ __forceinline__ void split_h2(float x, float y, uint32_t& hi, uint32_t& lo) {
    __half hx = __float2half_rn(x), hy = __float2half_rn(y);
    float rx = x - __half2float(hx), ry = y - __half2float(hy);
    __half2 h = __halves2half2(hx, hy);
    __half2 l = __halves2half2(__float2half_rn(rx), __float2half_rn(ry));
    hi = *(uint32_t*)&h;
    lo = *(uint32_t*)&l;
}
__device__ __forceinline__ uint32_t smem_u32(const void* p) {
    uint32_t a;
    asm("{ .reg .u64 t; cvta.to.shared.u64 t, %1; cvt.u32.u64 %0, t; }" : "=r"(a) : "l"(p));
    return a;
}
__device__ __forceinline__ void cp_async16(uint32_t dst, const void* src) {
    asm volatile("cp.async.cg.shared.global [%0], [%1], 16;" :: "r"(dst), "l"(src));
}

// ------------------------------------------------------------------
// Embedding gather (int32/int64 auto-detect)
// ------------------------------------------------------------------
__global__ __launch_bounds__(256) void embed_kernel(const int* __restrict__ idx32,
                                                    const float* __restrict__ wte,
                                                    float* __restrict__ x) {
    __shared__ int s_is64;
    if (threadIdx.x == 0) {
        int all0 = 1;
        #pragma unroll
        for (int i = 1; i < 16; i += 2)
            if (idx32[i] != 0) all0 = 0;
        s_is64 = all0;
    }
    __syncthreads();
    int gid = blockIdx.x * 256 + threadIdx.x;
    if (gid >= TOKENS * C_DIM) return;
    int t = gid / C_DIM;
    int c = gid - t * C_DIM;
    int id = s_is64 ? idx32[2 * t] : idx32[t];
    x[gid] = wte[id * C_DIM + c];
}

// ------------------------------------------------------------------
// f32 -> padded f16 conversion. src stride C_DIM, dst KPAD.
// One thread = 4 cols (uint2 store). Pads cols >= 228 and rows >= srcRows.
// ------------------------------------------------------------------
__global__ __launch_bounds__(256) void cvt_half_kernel(const float* __restrict__ src,
                                                       __half* __restrict__ dst,
                                                       int dstRows, int srcRows) {
    int idx = blockIdx.x * 256 + threadIdx.x;       // dstRows * 64
    if (idx >= dstRows * 64) return;
    int r = idx >> 6, c4 = idx & 63;                // c4: which 4-col group
    uint32_t p[2];
    if (c4 < 57 && r < srcRows) {
        float4 v = *(const float4*)&src[r * C_DIM + c4 * 4];
        p[0] = pack_h2(v.x, v.y);
        p[1] = pack_h2(v.z, v.w);
    } else {
        p[0] = 0u; p[1] = 0u;
    }
    *(uint2*)&dst[r * KPAD + c4 * 4] = *(uint2*)p;
}

// ------------------------------------------------------------------
// LayerNorm, one warp per token
// ------------------------------------------------------------------
__global__ __launch_bounds__(256) void ln_kernel(const float* __restrict__ x,
                                                 const float* __restrict__ g,
                                                 float* __restrict__ out) {
    int w = (blockIdx.x * 256 + threadIdx.x) >> 5;
    int lane = threadIdx.x & 31;
    if (w >= TOKENS) return;
    const float* row = x + w * C_DIM;
    float s = 0.f, s2 = 0.f;
    for (int c = lane; c < C_DIM; c += 32) {
        float v = row[c];
        s += v; s2 += v * v;
    }
    #pragma unroll
    for (int o = 16; o > 0; o >>= 1) {
        s  += __shfl_xor_sync(0xffffffffu, s, o);
        s2 += __shfl_xor_sync(0xffffffffu, s2, o);
    }
    float mean = s * (1.0f / C_DIM);
    float var = s2 * (1.0f / C_DIM) - mean * mean;
    float rstd = rsqrtf(var + 1e-5f);
    float* orow = out + w * C_DIM;
    for (int c = lane; c < C_DIM; c += 32)
        orow[c] = (row[c] - mean) * rstd * g[c];
}

// ------------------------------------------------------------------
// Split-fp16 internal GEMM (NT) — R6-proven.
// ------------------------------------------------------------------
template<int AMODE, int EPI>
__global__ __launch_bounds__(256) void hgemm(
    const float* __restrict__ A, const float* __restrict__ A2,
    const float* __restrict__ B, float* __restrict__ Cc,
    int M, int N, int K)
{
    __shared__ uint32_t Ah[64][20], Al[64][20], Bh[64][20], Bl[64][20];
    const int tid = threadIdx.x;
    const int lane = tid & 31, wid = tid >> 5;
    const int wm = wid >> 2, wn = wid & 3;
    const int l3 = lane & 3, lq = lane >> 2;
    const int m0 = blockIdx.x * 64, n0 = blockIdx.y * 64;

    float acc[2][2][4];
    #pragma unroll
    for (int i = 0; i < 2; i++)
        #pragma unroll
        for (int j = 0; j < 2; j++)
            #pragma unroll
            for (int q = 0; q < 4; q++) acc[i][j][q] = 0.f;

    const int nchunk = (K + 31) / 32;

    float4 pa[2], pb[2];
    #pragma unroll
    for (int i = 0; i < 2; i++) {
        int idx = tid + i * 256;
        int r = idx >> 3, f = idx & 7;
        int k = f * 4;
        float4 v = make_float4(0.f,0.f,0.f,0.f);
        if (k + 3 < K) {
            v = *(const float4*)&A[(m0 + r) * K + k];
            if (AMODE == 2) {
                float4 u = *(const float4*)&A2[(m0 + r) * K + k];
                v.x *= u.x; v.y *= u.y; v.z *= u.z; v.w *= u.w;
            }
        }
        pa[i] = v;
        v = make_float4(0.f,0.f,0.f,0.f);
        if (k + 3 < K && (n0 + r) < N)
            v = *(const float4*)&B[(n0 + r) * K + k];
        pb[i] = v;
    }

    for (int ch = 0; ch < nchunk; ch++) {
        __syncthreads();
        #pragma unroll
        for (int i = 0; i < 2; i++) {
            int idx = tid + i * 256;
            int r = idx >> 3, f = idx & 7;
            uint32_t h0, l0, h1, l1;
            split_h2(pa[i].x, pa[i].y, h0, l0);
            split_h2(pa[i].z, pa[i].w, h1, l1);
            Ah[r][f*2] = h0; Ah[r][f*2+1] = h1;
            Al[r][f*2] = l0; Al[r][f*2+1] = l1;
            split_h2(pb[i].x, pb[i].y, h0, l0);
            split_h2(pb[i].z, pb[i].w, h1, l1);
            Bh[r][f*2] = h0; Bh[r][f*2+1] = h1;
            Bl[r][f*2] = l0; Bl[r][f*2+1] = l1;
        }
        __syncthreads();
        if (ch + 1 < nchunk) {
            int k0 = (ch + 1) * 32;
            #pragma unroll
            for (int i = 0; i < 2; i++) {
                int idx = tid + i * 256;
                int r = idx >> 3, f = idx & 7;
                int k = k0 + f * 4;
                float4 v = make_float4(0.f,0.f,0.f,0.f);
                if (k + 3 < K) {
                    v = *(const float4*)&A[(m0 + r) * K + k];
                    if (AMODE == 2) {
                        float4 u = *(const float4*)&A2[(m0 + r) * K + k];
                        v.x *= u.x; v.y *= u.y; v.z *= u.z; v.w *= u.w;
                    }
                }
                pa[i] = v;
                v = make_float4(0.f,0.f,0.f,0.f);
                if (k + 3 < K && (n0 + r) < N)
                    v = *(const float4*)&B[(n0 + r) * K + k];
                pb[i] = v;
            }
        }
        #pragma unroll
        for (int kc2 = 0; kc2 < 16; kc2 += 8) {
            uint32_t ah[2][4], al[2][4], bh[2][2], bl[2][2];
            #pragma unroll
            for (int mt = 0; mt < 2; mt++) {
                int r = wm * 32 + mt * 16 + lq;
                ah[mt][0] = Ah[r    ][kc2 + l3];
                ah[mt][1] = Ah[r + 8][kc2 + l3];
                ah[mt][2] = Ah[r    ][kc2 + 4 + l3];
                ah[mt][3] = Ah[r + 8][kc2 + 4 + l3];
                al[mt][0] = Al[r    ][kc2 + l3];
                al[mt][1] = Al[r + 8][kc2 + l3];
                al[mt][2] = Al[r    ][kc2 + 4 + l3];
                al[mt][3] = Al[r + 8][kc2 + 4 + l3];
            }
            #pragma unroll
            for (int nt = 0; nt < 2; nt++) {
                int n = wn * 16 + nt * 8 + lq;
                bh[nt][0] = Bh[n][kc2 + l3];
                bh[nt][1] = Bh[n][kc2 + 4 + l3];
                bl[nt][0] = Bl[n][kc2 + l3];
                bl[nt][1] = Bl[n][kc2 + 4 + l3];
            }
            #pragma unroll
            for (int mt = 0; mt < 2; mt++)
                #pragma unroll
                for (int nt = 0; nt < 2; nt++) {
                    mma16(acc[mt][nt], ah[mt], bh[nt]);
                    mma16(acc[mt][nt], ah[mt], bl[nt]);
                    mma16(acc[mt][nt], al[mt], bh[nt]);
                }
        }
    }

    #pragma unroll
    for (int mt = 0; mt < 2; mt++) {
        #pragma unroll
        for (int nt = 0; nt < 2; nt++) {
            int n = n0 + wn * 16 + nt * 8 + l3 * 2;
            #pragma unroll
            for (int half = 0; half < 2; half++) {
                int mm = m0 + wm * 32 + mt * 16 + lq + half * 8;
                float r0 = acc[mt][nt][half * 2];
                float r1 = acc[mt][nt][half * 2 + 1];
                if (n < N) {
                    if (EPI == 1) r0 += Cc[mm * N + n];
                    if (EPI == 2) r0 = gelu_f(r0);
                    Cc[mm * N + n] = r0;
                }
                if (n + 1 < N) {
                    if (EPI == 1) r1 += Cc[mm * N + n + 1];
                    if (EPI == 2) r1 = gelu_f(r1);
                    Cc[mm * N + n + 1] = r1;
                }
            }
        }
    }
}

// ------------------------------------------------------------------
// Pipelined fp16 lm_head: C[m,n] = sum_k x_h[m,k]*wte_h[n,k]
// BM=BN=128, BK=64 halves, 4 chunks, cp.async double-buffer.
// smem per stage: A[128][36]w + B[128][36]w; 2 stages = 73728 B.
// 256 threads, 8 warps (2x4), warp tile 64x32.
// ------------------------------------------------------------------
#define LMH_AW   (128 * 36)                 // words per operand
#define LMH_SW   (2 * LMH_AW)               // words per stage
#define LMH_SMEM (2 * LMH_SW * 4)           // bytes total

__global__ __launch_bounds__(256) void lmhead_h2(
    const __half* __restrict__ Ah_g, const __half* __restrict__ Bh_g,
    float* __restrict__ C)
{
    extern __shared__ uint32_t dsm[];
    const uint32_t smem_base = smem_u32(dsm);

    const int tid = threadIdx.x;
    const int lane = tid & 31, wid = tid >> 5;
    const int wm = wid >> 2, wn = wid & 3;
    const int l3 = lane & 3, lq = lane >> 2;
    const int m0 = blockIdx.x * 128, n0 = blockIdx.y * 128;

    float acc[4][4][4];
    #pragma unroll
    for (int i = 0; i < 4; i++)
        #pragma unroll
        for (int j = 0; j < 4; j++)
            #pragma unroll
            for (int q = 0; q < 4; q++) acc[i][j][q] = 0.f;

    const int r_ld = tid >> 3;        // 0..31 (x4 via i-loop -> 0..127)
    const int c16  = tid & 7;         // 16B slot within 128B row chunk

    // issue chunk kc into stage buffer bi
    auto issue = [&](int kc, int bi) {
        uint32_t ab = smem_base + (uint32_t)bi * (LMH_SW * 4);
        uint32_t bb = ab + LMH_AW * 4;
        const __half* asrc = Ah_g + (size_t)(m0 + r_ld) * KPAD + kc * 64 + c16 * 8;
        const __half* bsrc = Bh_g + (size_t)(n0 + r_ld) * KPAD + kc * 64 + c16 * 8;
        #pragma unroll
        for (int i = 0; i < 4; i++) {
            int r = r_ld + i * 32;
            cp_async16(ab + (uint32_t)(r * 36 + c16 * 4) * 4,
                       asrc + (size_t)(i * 32) * KPAD);
            cp_async16(bb + (uint32_t)(r * 36 + c16 * 4) * 4,
                       bsrc + (size_t)(i * 32) * KPAD);
        }
        asm volatile("cp.async.commit_group;" ::: "memory");
    };

    issue(0, 0);

    #pragma unroll 1
    for (int kc = 0; kc < 4; kc++) {
        if (kc + 1 < 4) {
            issue(kc + 1, (kc + 1) & 1);
            asm volatile("cp.async.wait_group 1;" ::: "memory");
        } else {
            asm volatile("cp.async.wait_group 0;" ::: "memory");
        }
        __syncthreads();

        const uint32_t* As2 = dsm + (kc & 1) * LMH_SW;
        const uint32_t* Bs2 = As2 + LMH_AW;

        #pragma unroll
        for (int kc2 = 0; kc2 < 32; kc2 += 8) {
            uint32_t af[4][4], bf[4][2];
            #pragma unroll
            for (int mt = 0; mt < 4; mt++) {
                int r = wm * 64 + mt * 16 + lq;
                af[mt][0] = As2[r * 36 + kc2 + l3];
                af[mt][1] = As2[(r + 8) * 36 + kc2 + l3];
                af[mt][2] = As2[r * 36 + kc2 + 4 + l3];
                af[mt][3] = As2[(r + 8) * 36 + kc2 + 4 + l3];
            }
            #pragma unroll
            for (int nt = 0; nt < 4; nt++) {
                int n = wn * 32 + nt * 8 + lq;
                bf[nt][0] = Bs2[n * 36 + kc2 + l3];
                bf[nt][1] = Bs2[n * 36 + kc2 + 4 + l3];
            }
            #pragma unroll
            for (int mt = 0; mt < 4; mt++)
                #pragma unroll
                for (int nt = 0; nt < 4; nt++)
                    mma16(acc[mt][nt], af[mt], bf[nt]);
        }
        __syncthreads();
    }

    #pragma unroll
    for (int mt = 0; mt < 4; mt++) {
        #pragma unroll
        for (int nt = 0; nt < 4; nt++) {
            int n = n0 + wn * 32 + nt * 8 + l3 * 2;
            #pragma unroll
            for (int half = 0; half < 2; half++) {
                int mm = m0 + wm * 64 + mt * 16 + lq + half * 8;
                float* dst = &C[(size_t)mm * VOCAB + n];
                if (n     < VOCAB) dst[0] = acc[mt][nt][half * 2];
                if (n + 1 < VOCAB) dst[1] = acc[mt][nt][half * 2 + 1];
            }
        }
    }
}

// ------------------------------------------------------------------
// Grid-wide barrier (all 128 blocks resident)
// ------------------------------------------------------------------
__device__ __forceinline__ void grid_barrier() {
    __syncthreads();
    if (threadIdx.x == 0) {
        __threadfence();
        unsigned gen = atomicAdd(&g_bar_gen, 0u);
        unsigned t = atomicAdd(&g_bar_cnt, 1u);
        if (t == gridDim.x - 1) {
            atomicExch(&g_bar_cnt, 0u);
            __threadfence();
            atomicAdd(&g_bar_gen, 1u);
        } else {
            while (atomicAdd(&g_bar_gen, 0u) == gen) __nanosleep(64);
        }
    }
    __syncthreads();
}

// ------------------------------------------------------------------
// Persistent pscan (R3-proven): 10 Kogge-Stone steps, 3xTF32 mix GEMM
// ------------------------------------------------------------------
#define SC_MA  (16 * 236)
#define SC_RR  (16 * 232)
#define SC_MX  (16 * 232)
#define SC_WC  (120 * 260)
#define SC_SMEM_FLOATS (SC_MA + SC_RR + SC_MX + SC_WC)

__global__ __launch_bounds__(256) void scan_all_kernel(
    float* __restrict__ x0, float* __restrict__ x1,
    const float* __restrict__ wsc, const float* __restrict__ ident)
{
    extern __shared__ float sm[];
    float* mA = sm;
    float* rr = mA + SC_MA;
    float* mx = rr + SC_RR;
    float* wc = mx + SC_MX;

    const int tid = threadIdx.x;
    const int lane = tid & 31, wid = tid >> 5;
    const int T0 = blockIdx.x * 16;

    int step = 0;
    for (int off = 1; off < SEQ; off <<= 1, step++) {
        const float* xin = (step & 1) ? x1 : x0;
        float* xout      = (step & 1) ? x0 : x1;

        if (tid < 236) {
            int c = tid;
            #pragma unroll
            for (int t = 0; t < 16; t++) {
                int tok = T0 + t;
                int tt = tok & (SEQ - 1);
                float rv = 0.f, lv = 0.f;
                if (c < C_DIM) {
                    rv = xin[tok * C_DIM + c];
                    lv = (tt >= off) ? xin[(tok - off) * C_DIM + c] : ident[c];
                }
                if (c < 232) rr[t * 232 + c] = rv;
                mA[t * 236 + c] = lv + rv;
            }
        }
        __syncthreads();

        float acc[4][4];
        #pragma unroll
        for (int i = 0; i < 4; i++)
            #pragma unroll
            for (int j = 0; j < 4; j++) acc[i][j] = 0.f;

        #pragma unroll
        for (int ci = 0; ci < 2; ci++) {
            int k0 = ci * 114;
            for (int i = tid; i < 120 * 65; i += 256) {
                int kk = i / 65, c4 = i - kk * 65;
                float4 v = make_float4(0.f,0.f,0.f,0.f);
                if (kk < 114 && c4 < 57)
                    v = *(const float4*)&wsc[(k0 + kk) * C_DIM + c4 * 4];
                *(float4*)&wc[kk * 260 + c4 * 4] = v;
            }
            __syncthreads();
            #pragma unroll
            for (int kc8 = 0; kc8 < 15; kc8++) {
                int kloc = kc8 * 8;
                int kglob = k0 + kloc;
                uint32_t ah[4], al[4], bh[2], bl[2];
                {
                    int r = lane >> 2;
                    float v0 = mA[r * 236       + kglob     + (lane & 3)];
                    float v1 = mA[(r + 8) * 236 + kglob     + (lane & 3)];
                    float v2 = mA[r * 236       + kglob + 4 + (lane & 3)];
                    float v3 = mA[(r + 8) * 236 + kglob + 4 + (lane & 3)];
                    split_tf32(v0, ah[0], al[0]);
                    split_tf32(v1, ah[1], al[1]);
                    split_tf32(v2, ah[2], al[2]);
                    split_tf32(v3, ah[3], al[3]);
                }
                #pragma unroll
                for (int nt = 0; nt < 4; nt++) {
                    int n = wid * 32 + nt * 8 + (lane >> 2);
                    float u0 = wc[(kloc     + (lane & 3)) * 260 + n];
                    float u1 = wc[(kloc + 4 + (lane & 3)) * 260 + n];
                    split_tf32(u0, bh[0], bl[0]);
                    split_tf32(u1, bh[1], bl[1]);
                    mma8(acc[nt], ah, bh);
                    mma8(acc[nt], ah, bl);
                    mma8(acc[nt], al, bh);
                }
            }
            __syncthreads();
        }

        #pragma unroll
        for (int nt = 0; nt < 4; nt++) {
            int n = wid * 32 + nt * 8 + (lane & 3) * 2;
            int r = lane >> 2;
            if (n < C_DIM) {
                mx[r * 232 + n]           = acc[nt][0];
                mx[r * 232 + n + 1]       = acc[nt][1];
                mx[(r + 8) * 232 + n]     = acc[nt][2];
                mx[(r + 8) * 232 + n + 1] = acc[nt][3];
            }
        }
        __syncthreads();

        const int d0 = lane;
        const int d1 = lane + 32;
        const bool has1 = (lane < HD - 32);
        #pragma unroll
        for (int e = 0; e < 8; e++) {
            int p = wid * 8 + e;
            int t = p >> 2;
            int l = p & 3;
            int tok = T0 + t;

            float q0 = mA[t * 236 + l * HD + d0] - rr[t * 232 + l * HD + d0];
            float q1 = has1 ? (mA[t * 236 + l * HD + d1] - rr[t * 232 + l * HD + d1]) : 0.f;

            float sc[4];
            #pragma unroll
            for (int m = 0; m < 4; m++) {
                float pr = q0 * rr[t * 232 + m * HD + d0];
                if (has1) pr += q1 * rr[t * 232 + m * HD + d1];
                #pragma unroll
                for (int o = 16; o > 0; o >>= 1) pr += __shfl_xor_sync(0xffffffffu, pr, o);
                sc[m] = pr * 0.13245323570650439f;
            }
            float mxv = fmaxf(fmaxf(sc[0], sc[1]), fmaxf(sc[2], sc[3]));
            float e0 = expf(sc[0] - mxv), e1 = expf(sc[1] - mxv);
            float e2 = expf(sc[2] - mxv), e3 = expf(sc[3] - mxv);
            float inv = 1.0f / (e0 + e1 + e2 + e3);
            float a0 = e0 * inv, a1 = e1 * inv, a2 = e2 * inv, a3 = e3 * inv;

            float z0 = a0 * mx[t * 232 + 0 * HD + d0] + a1 * mx[t * 232 + 1 * HD + d0]
                     + a2 * mx[t * 232 + 2 * HD + d0] + a3 * mx[t * 232 + 3 * HD + d0];
            float z1 = 0.f;
            if (has1)
                z1 = a0 * mx[t * 232 + 0 * HD + d1] + a1 * mx[t * 232 + 1 * HD + d1]
                   + a2 * mx[t * 232 + 2 * HD + d1] + a3 * mx[t * 232 + 3 * HD + d1];

            float ss = z0 * z0 + z1 * z1;
            #pragma unroll
            for (int o = 16; o > 0; o >>= 1) ss += __shfl_xor_sync(0xffffffffu, ss, o);
            float scale = rsqrtf(ss * (1.0f / 57.0f) + 1e-6f) / (1.0f + (float)l);

            xout[tok * C_DIM + l * HD + d0] = q0 + z0 * scale;
            if (has1) xout[tok * C_DIM + l * HD + d1] = q1 + z1 * scale;
        }

        if ((off << 1) < SEQ) grid_barrier();
    }
}

// ------------------------------------------------------------------
extern "C" void kernel_launch(void* const* d_in, const int* in_sizes, int n_in,
                              void* d_out, int out_size) {
    const int*   idx    = (const int*)  d_in[0];
    const float* wte    = (const float*)d_in[1];
    const float* ln1_g  = (const float*)d_in[2];
    const float* ln2_g  = (const float*)d_in[3];
    const float* w_up   = (const float*)d_in[4];
    const float* w_v    = (const float*)d_in[5];
    const float* w_cpr  = (const float*)d_in[6];
    const float* w_scan = (const float*)d_in[7];
    const float* ident  = (const float*)d_in[8];
    const float* w_fc   = (const float*)d_in[9];
    const float* w_proj = (const float*)d_in[10];
    float* out = (float*)d_out;

    float *px, *ph, *pv, *pa, *pb, *pmlp;
    __half *pwh, *pxh;
    cudaGetSymbolAddress((void**)&px,   g_x);
    cudaGetSymbolAddress((void**)&ph,   g_h);
    cudaGetSymbolAddress((void**)&pv,   g_v);
    cudaGetSymbolAddress((void**)&pa,   g_bufA);
    cudaGetSymbolAddress((void**)&pb,   g_bufB);
    cudaGetSymbolAddress((void**)&pmlp, g_mlp);
    cudaGetSymbolAddress((void**)&pwh,  g_wte_h);
    cudaGetSymbolAddress((void**)&pxh,  g_x_h);

    const int scan_smem = SC_SMEM_FLOATS * 4;
    cudaFuncSetAttribute(scan_all_kernel,
                         cudaFuncAttributeMaxDynamicSharedMemorySize, scan_smem);
    cudaFuncSetAttribute(lmhead_h2,
                         cudaFuncAttributeMaxDynamicSharedMemorySize, LMH_SMEM);

    const int CC = C_DIM * C_DIM;
    const int FC = FF * C_DIM;

    embed_kernel<<<(TOKENS * C_DIM + 255) / 256, 256>>>(idx, wte, px);

    // convert wte -> padded fp16 (independent of layers; do it early)
    cvt_half_kernel<<<(VPAD * 64 + 255) / 256, 256>>>(wte, pwh, VPAD, VOCAB);

    for (int L = 0; L < NLAYER; L++) {
        const float* wupL  = w_up   + L * CC;
        const float* wvL   = w_v    + L * CC;
        const float* wcprL = w_cpr  + L * CC;
        const float* wscL  = w_scan + L * CC;
        const float* idL   = ident  + L * C_DIM;
        const float* wfcL  = w_fc   + L * FC;
        const float* wprL  = w_proj + L * FC;

        ln_kernel<<<(TOKENS * 32 + 255) / 256, 256>>>(px, ln1_g + L * C_DIM, ph);

        dim3 gs(TOKENS / 64, (C_DIM + 63) / 64);
        hgemm<0,0><<<gs, 256>>>(ph, nullptr, wupL, pa, TOKENS, C_DIM, C_DIM);
        hgemm<0,0><<<gs, 256>>>(ph, nullptr, wvL,  pv, TOKENS, C_DIM, C_DIM);

        scan_all_kernel<<<TOKENS / 16, 256, scan_smem>>>(pa, pb, wscL, idL);

        hgemm<2,1><<<gs, 256>>>(pa, pv, wcprL, px, TOKENS, C_DIM, C_DIM);

        ln_kernel<<<(TOKENS * 32 + 255) / 256, 256>>>(px, ln2_g + L * C_DIM, ph);

        dim3 gf(TOKENS / 64, (FF + 63) / 64);
        hgemm<0,2><<<gf, 256>>>(ph, nullptr, wfcL, pmlp, TOKENS, FF, C_DIM);
        hgemm<0,1><<<gs, 256>>>(pmlp, nullptr, wprL, px, TOKENS, C_DIM, FF);
    }

    // convert final x -> padded fp16
    cvt_half_kernel<<<(TOKENS * 64 + 255) / 256, 256>>>(px, pxh, TOKENS, TOKENS);

    dim3 gl(TOKENS / 128, VPAD / 128);
    lmhead_h2<<<gl, 256, LMH_SMEM>>>(pxh, pwh, out);
}

// round 10
// speedup vs baseline: 4.0952x; 1.2223x over previous
#include <cuda_runtime.h>
#include <cuda_fp16.h>
#include <cstdint>
#include <math.h>

#define C_DIM 228
#define TOKENS 2048
#define SEQ 1024
#define HD 57
#define LANES 4
#define FF 912
#define NLAYER 4
#define VOCAB 50257
#define VPAD 50304          // 393*128, padded vocab rows
#define KPAD 256            // padded K row stride for half buffers (lmhead)
#define WKP 240             // padded K stride for w_scan half buffers
#define WNP 256             // padded N rows for w_scan half buffers

// ------------------------------------------------------------------
// Scratch
// ------------------------------------------------------------------
__device__ float g_x   [TOKENS * C_DIM];
__device__ float g_h   [TOKENS * C_DIM];
__device__ float g_v   [TOKENS * C_DIM];
__device__ float g_bufA[TOKENS * C_DIM];
__device__ float g_bufB[TOKENS * C_DIM];
__device__ float g_mlp [TOKENS * FF];
__device__ __half g_wte_h[VPAD * KPAD];         // fp16 wte, padded
__device__ __half g_x_h  [TOKENS * KPAD];       // fp16 final x, padded
__device__ __half g_wsh  [NLAYER * WNP * WKP];  // w_scan^T hi (zero-init pads)
__device__ __half g_wsl  [NLAYER * WNP * WKP];  // w_scan^T lo
__device__ unsigned g_bar_cnt = 0;
__device__ unsigned g_bar_gen = 0;

__device__ __forceinline__ float gelu_f(float x) {
    float x3 = x * x * x;
    return 0.5f * x * (1.0f + tanhf(0.7978845608028654f * (x + 0.044715f * x3)));
}
__device__ __forceinline__ void mma16(float* c, const uint32_t* a, const uint32_t* b) {
    asm volatile("mma.sync.aligned.m16n8k16.row.col.f32.f16.f16.f32 "
        "{%0,%1,%2,%3}, {%4,%5,%6,%7}, {%8,%9}, {%0,%1,%2,%3};"
        : "+f"(c[0]), "+f"(c[1]), "+f"(c[2]), "+f"(c[3])
        : "r"(a[0]), "r"(a[1]), "r"(a[2]), "r"(a[3]), "r"(b[0]), "r"(b[1]));
}
__device__ __forceinline__ uint32_t pack_h2(float x, float y) {
    __half2 h = __halves2half2(__float2half_rn(x), __float2half_rn(y));
    return *(uint32_t*)&h;
}
__device__ __forceinline__ void split_h2(float x, float y, uint32_t& hi, uint32_t& lo) {
    __half hx = __float2half_rn(x), hy = __float2half_rn(y);
    float rx = x - __half2float(hx), ry = y - __half2float(hy);
    __half2 h = __halves2half2(hx, hy);
    __half2 l = __halves2half2(__float2half_rn(rx), __float2half_rn(ry));
    hi = *(uint32_t*)&h;
    lo = *(uint32_t*)&l;
}
__device__ __forceinline__ uint32_t smem_u32(const void* p) {
    uint32_t a;
    asm("{ .reg .u64 t; cvta.to.shared.u64 t, %1; cvt.u32.u64 %0, t; }" : "=r"(a) : "l"(p));
    return a;
}
__device__ __forceinline__ void cp_async16(uint32_t dst, const void* src) {
    asm volatile("cp.async.cg.shared.global [%0], [%1], 16;" :: "r"(dst), "l"(src));
}

// ------------------------------------------------------------------
// Embedding gather (int32/int64 auto-detect)
// ------------------------------------------------------------------
__global__ __launch_bounds__(256) void embed_kernel(const int* __restrict__ idx32,
                                                    const float* __restrict__ wte,
                                                    float* __restrict__ x) {
    __shared__ int s_is64;
    if (threadIdx.x == 0) {
        int all0 = 1;
        #pragma unroll
        for (int i = 1; i < 16; i += 2)
            if (idx32[i] != 0) all0 = 0;
        s_is64 = all0;
    }
    __syncthreads();
    int gid = blockIdx.x * 256 + threadIdx.x;
    if (gid >= TOKENS * C_DIM) return;
    int t = gid / C_DIM;
    int c = gid - t * C_DIM;
    int id = s_is64 ? idx32[2 * t] : idx32[t];
    x[gid] = wte[id * C_DIM + c];
}

// ------------------------------------------------------------------
// f32 -> padded f16 conversion (wte / final x)
// ------------------------------------------------------------------
__global__ __launch_bounds__(256) void cvt_half_kernel(const float* __restrict__ src,
                                                       __half* __restrict__ dst,
                                                       int dstRows, int srcRows) {
    int idx = blockIdx.x * 256 + threadIdx.x;
    if (idx >= dstRows * 64) return;
    int r = idx >> 6, c4 = idx & 63;
    uint32_t p[2];
    if (c4 < 57 && r < srcRows) {
        float4 v = *(const float4*)&src[r * C_DIM + c4 * 4];
        p[0] = pack_h2(v.x, v.y);
        p[1] = pack_h2(v.z, v.w);
    } else {
        p[0] = 0u; p[1] = 0u;
    }
    *(uint2*)&dst[r * KPAD + c4 * 4] = *(uint2*)p;
}

// ------------------------------------------------------------------
// w_scan (all layers) -> transposed fp16 hi/lo, zero-padded.
// Wh[L][n][k] = W[L][k][n] split. Thread per (L, k, n4-group).
// Rows n>=228 never written (zero-init device global).
// ------------------------------------------------------------------
__global__ __launch_bounds__(256) void cvt_wscan_kernel(const float* __restrict__ wsc,
                                                        __half* __restrict__ WhT,
                                                        __half* __restrict__ WlT) {
    int idx = blockIdx.x * 256 + threadIdx.x;
    if (idx >= NLAYER * WKP * 57) return;
    int L = idx / (WKP * 57);
    int rem = idx - L * (WKP * 57);
    int k = rem / 57, n4 = rem - (rem / 57) * 57;
    float4 v = make_float4(0.f, 0.f, 0.f, 0.f);
    if (k < C_DIM)
        v = *(const float4*)&wsc[L * C_DIM * C_DIM + k * C_DIM + n4 * 4];
    __half* wh = WhT + L * WNP * WKP;
    __half* wl = WlT + L * WNP * WKP;
    const float* vv = (const float*)&v;
    #pragma unroll
    for (int j = 0; j < 4; j++) {
        float x = vv[j];
        __half hi = __float2half_rn(x);
        __half lo = __float2half_rn(x - __half2float(hi));
        wh[(n4 * 4 + j) * WKP + k] = hi;
        wl[(n4 * 4 + j) * WKP + k] = lo;
    }
}

// ------------------------------------------------------------------
// LayerNorm, one warp per token
// ------------------------------------------------------------------
__global__ __launch_bounds__(256) void ln_kernel(const float* __restrict__ x,
                                                 const float* __restrict__ g,
                                                 float* __restrict__ out) {
    int w = (blockIdx.x * 256 + threadIdx.x) >> 5;
    int lane = threadIdx.x & 31;
    if (w >= TOKENS) return;
    const float* row = x + w * C_DIM;
    float s = 0.f, s2 = 0.f;
    for (int c = lane; c < C_DIM; c += 32) {
        float v = row[c];
        s += v; s2 += v * v;
    }
    #pragma unroll
    for (int o = 16; o > 0; o >>= 1) {
        s  += __shfl_xor_sync(0xffffffffu, s, o);
        s2 += __shfl_xor_sync(0xffffffffu, s2, o);
    }
    float mean = s * (1.0f / C_DIM);
    float var = s2 * (1.0f / C_DIM) - mean * mean;
    float rstd = rsqrtf(var + 1e-5f);
    float* orow = out + w * C_DIM;
    for (int c = lane; c < C_DIM; c += 32)
        orow[c] = (row[c] - mean) * rstd * g[c];
}

// ------------------------------------------------------------------
// Split-fp16 internal GEMM (NT) — R6-proven.
// ------------------------------------------------------------------
template<int AMODE, int EPI>
__global__ __launch_bounds__(256) void hgemm(
    const float* __restrict__ A, const float* __restrict__ A2,
    const float* __restrict__ B, float* __restrict__ Cc,
    int M, int N, int K)
{
    __shared__ uint32_t Ah[64][20], Al[64][20], Bh[64][20], Bl[64][20];
    const int tid = threadIdx.x;
    const int lane = tid & 31, wid = tid >> 5;
    const int wm = wid >> 2, wn = wid & 3;
    const int l3 = lane & 3, lq = lane >> 2;
    const int m0 = blockIdx.x * 64, n0 = blockIdx.y * 64;

    float acc[2][2][4];
    #pragma unroll
    for (int i = 0; i < 2; i++)
        #pragma unroll
        for (int j = 0; j < 2; j++)
            #pragma unroll
            for (int q = 0; q < 4; q++) acc[i][j][q] = 0.f;

    const int nchunk = (K + 31) / 32;

    float4 pa[2], pb[2];
    #pragma unroll
    for (int i = 0; i < 2; i++) {
        int idx = tid + i * 256;
        int r = idx >> 3, f = idx & 7;
        int k = f * 4;
        float4 v = make_float4(0.f,0.f,0.f,0.f);
        if (k + 3 < K) {
            v = *(const float4*)&A[(m0 + r) * K + k];
            if (AMODE == 2) {
                float4 u = *(const float4*)&A2[(m0 + r) * K + k];
                v.x *= u.x; v.y *= u.y; v.z *= u.z; v.w *= u.w;
            }
        }
        pa[i] = v;
        v = make_float4(0.f,0.f,0.f,0.f);
        if (k + 3 < K && (n0 + r) < N)
            v = *(const float4*)&B[(n0 + r) * K + k];
        pb[i] = v;
    }

    for (int ch = 0; ch < nchunk; ch++) {
        __syncthreads();
        #pragma unroll
        for (int i = 0; i < 2; i++) {
            int idx = tid + i * 256;
            int r = idx >> 3, f = idx & 7;
            uint32_t h0, l0, h1, l1;
            split_h2(pa[i].x, pa[i].y, h0, l0);
            split_h2(pa[i].z, pa[i].w, h1, l1);
            Ah[r][f*2] = h0; Ah[r][f*2+1] = h1;
            Al[r][f*2] = l0; Al[r][f*2+1] = l1;
            split_h2(pb[i].x, pb[i].y, h0, l0);
            split_h2(pb[i].z, pb[i].w, h1, l1);
            Bh[r][f*2] = h0; Bh[r][f*2+1] = h1;
            Bl[r][f*2] = l0; Bl[r][f*2+1] = l1;
        }
        __syncthreads();
        if (ch + 1 < nchunk) {
            int k0 = (ch + 1) * 32;
            #pragma unroll
            for (int i = 0; i < 2; i++) {
                int idx = tid + i * 256;
                int r = idx >> 3, f = idx & 7;
                int k = k0 + f * 4;
                float4 v = make_float4(0.f,0.f,0.f,0.f);
                if (k + 3 < K) {
                    v = *(const float4*)&A[(m0 + r) * K + k];
                    if (AMODE == 2) {
                        float4 u = *(const float4*)&A2[(m0 + r) * K + k];
                        v.x *= u.x; v.y *= u.y; v.z *= u.z; v.w *= u.w;
                    }
                }
                pa[i] = v;
                v = make_float4(0.f,0.f,0.f,0.f);
                if (k + 3 < K && (n0 + r) < N)
                    v = *(const float4*)&B[(n0 + r) * K + k];
                pb[i] = v;
            }
        }
        #pragma unroll
        for (int kc2 = 0; kc2 < 16; kc2 += 8) {
            uint32_t ah[2][4], al[2][4], bh[2][2], bl[2][2];
            #pragma unroll
            for (int mt = 0; mt < 2; mt++) {
                int r = wm * 32 + mt * 16 + lq;
                ah[mt][0] = Ah[r    ][kc2 + l3];
                ah[mt][1] = Ah[r + 8][kc2 + l3];
                ah[mt][2] = Ah[r    ][kc2 + 4 + l3];
                ah[mt][3] = Ah[r + 8][kc2 + 4 + l3];
                al[mt][0] = Al[r    ][kc2 + l3];
                al[mt][1] = Al[r + 8][kc2 + l3];
                al[mt][2] = Al[r    ][kc2 + 4 + l3];
                al[mt][3] = Al[r + 8][kc2 + 4 + l3];
            }
            #pragma unroll
            for (int nt = 0; nt < 2; nt++) {
                int n = wn * 16 + nt * 8 + lq;
                bh[nt][0] = Bh[n][kc2 + l3];
                bh[nt][1] = Bh[n][kc2 + 4 + l3];
                bl[nt][0] = Bl[n][kc2 + l3];
                bl[nt][1] = Bl[n][kc2 + 4 + l3];
            }
            #pragma unroll
            for (int mt = 0; mt < 2; mt++)
                #pragma unroll
                for (int nt = 0; nt < 2; nt++) {
                    mma16(acc[mt][nt], ah[mt], bh[nt]);
                    mma16(acc[mt][nt], ah[mt], bl[nt]);
                    mma16(acc[mt][nt], al[mt], bh[nt]);
                }
        }
    }

    #pragma unroll
    for (int mt = 0; mt < 2; mt++) {
        #pragma unroll
        for (int nt = 0; nt < 2; nt++) {
            int n = n0 + wn * 16 + nt * 8 + l3 * 2;
            #pragma unroll
            for (int half = 0; half < 2; half++) {
                int mm = m0 + wm * 32 + mt * 16 + lq + half * 8;
                float r0 = acc[mt][nt][half * 2];
                float r1 = acc[mt][nt][half * 2 + 1];
                if (n < N) {
                    if (EPI == 1) r0 += Cc[mm * N + n];
                    if (EPI == 2) r0 = gelu_f(r0);
                    Cc[mm * N + n] = r0;
                }
                if (n + 1 < N) {
                    if (EPI == 1) r1 += Cc[mm * N + n + 1];
                    if (EPI == 2) r1 = gelu_f(r1);
                    Cc[mm * N + n + 1] = r1;
                }
            }
        }
    }
}

// ------------------------------------------------------------------
// Pipelined fp16 lm_head — R8-proven.
// ------------------------------------------------------------------
#define LMH_AW   (128 * 36)
#define LMH_SW   (2 * LMH_AW)
#define LMH_SMEM (2 * LMH_SW * 4)

__global__ __launch_bounds__(256) void lmhead_h2(
    const __half* __restrict__ Ah_g, const __half* __restrict__ Bh_g,
    float* __restrict__ C)
{
    extern __shared__ uint32_t dsm[];
    const uint32_t smem_base = smem_u32(dsm);

    const int tid = threadIdx.x;
    const int lane = tid & 31, wid = tid >> 5;
    const int wm = wid >> 2, wn = wid & 3;
    const int l3 = lane & 3, lq = lane >> 2;
    const int m0 = blockIdx.x * 128, n0 = blockIdx.y * 128;

    float acc[4][4][4];
    #pragma unroll
    for (int i = 0; i < 4; i++)
        #pragma unroll
        for (int j = 0; j < 4; j++)
            #pragma unroll
            for (int q = 0; q < 4; q++) acc[i][j][q] = 0.f;

    const int r_ld = tid >> 3;
    const int c16  = tid & 7;

    auto issue = [&](int kc, int bi) {
        uint32_t ab = smem_base + (uint32_t)bi * (LMH_SW * 4);
        uint32_t bb = ab + LMH_AW * 4;
        const __half* asrc = Ah_g + (size_t)(m0 + r_ld) * KPAD + kc * 64 + c16 * 8;
        const __half* bsrc = Bh_g + (size_t)(n0 + r_ld) * KPAD + kc * 64 + c16 * 8;
        #pragma unroll
        for (int i = 0; i < 4; i++) {
            int r = r_ld + i * 32;
            cp_async16(ab + (uint32_t)(r * 36 + c16 * 4) * 4,
                       asrc + (size_t)(i * 32) * KPAD);
            cp_async16(bb + (uint32_t)(r * 36 + c16 * 4) * 4,
                       bsrc + (size_t)(i * 32) * KPAD);
        }
        asm volatile("cp.async.commit_group;" ::: "memory");
    };

    issue(0, 0);

    #pragma unroll 1
    for (int kc = 0; kc < 4; kc++) {
        if (kc + 1 < 4) {
            issue(kc + 1, (kc + 1) & 1);
            asm volatile("cp.async.wait_group 1;" ::: "memory");
        } else {
            asm volatile("cp.async.wait_group 0;" ::: "memory");
        }
        __syncthreads();

        const uint32_t* As2 = dsm + (kc & 1) * LMH_SW;
        const uint32_t* Bs2 = As2 + LMH_AW;

        #pragma unroll
        for (int kc2 = 0; kc2 < 32; kc2 += 8) {
            uint32_t af[4][4], bf[4][2];
            #pragma unroll
            for (int mt = 0; mt < 4; mt++) {
                int r = wm * 64 + mt * 16 + lq;
                af[mt][0] = As2[r * 36 + kc2 + l3];
                af[mt][1] = As2[(r + 8) * 36 + kc2 + l3];
                af[mt][2] = As2[r * 36 + kc2 + 4 + l3];
                af[mt][3] = As2[(r + 8) * 36 + kc2 + 4 + l3];
            }
            #pragma unroll
            for (int nt = 0; nt < 4; nt++) {
                int n = wn * 32 + nt * 8 + lq;
                bf[nt][0] = Bs2[n * 36 + kc2 + l3];
                bf[nt][1] = Bs2[n * 36 + kc2 + 4 + l3];
            }
            #pragma unroll
            for (int mt = 0; mt < 4; mt++)
                #pragma unroll
                for (int nt = 0; nt < 4; nt++)
                    mma16(acc[mt][nt], af[mt], bf[nt]);
        }
        __syncthreads();
    }

    #pragma unroll
    for (int mt = 0; mt < 4; mt++) {
        #pragma unroll
        for (int nt = 0; nt < 4; nt++) {
            int n = n0 + wn * 32 + nt * 8 + l3 * 2;
            #pragma unroll
            for (int half = 0; half < 2; half++) {
                int mm = m0 + wm * 64 + mt * 16 + lq + half * 8;
                float* dst = &C[(size_t)mm * VOCAB + n];
                if (n     < VOCAB) dst[0] = acc[mt][nt][half * 2];
                if (n + 1 < VOCAB) dst[1] = acc[mt][nt][half * 2 + 1];
            }
        }
    }
}

// ------------------------------------------------------------------
// Grid-wide barrier (all 128 blocks resident)
// ------------------------------------------------------------------
__device__ __forceinline__ void grid_barrier() {
    __syncthreads();
    if (threadIdx.x == 0) {
        __threadfence();
        unsigned gen = atomicAdd(&g_bar_gen, 0u);
        unsigned t = atomicAdd(&g_bar_cnt, 1u);
        if (t == gridDim.x - 1) {
            atomicExch(&g_bar_cnt, 0u);
            __threadfence();
            atomicAdd(&g_bar_gen, 1u);
        } else {
            while (atomicAdd(&g_bar_gen, 0u) == gen) __nanosleep(64);
        }
    }
    __syncthreads();
}

// ------------------------------------------------------------------
// Persistent pscan, fp16-split mix GEMM.
// 128 blocks x 256 threads, 16 tokens/block, 10 Kogge-Stone steps.
// smem (u32 words): mAh[16*124] mAl[16*124] rr[16*232]f mx[16*232]f
//                   Wh[128*124] Wl[128*124]  -> 172544 B
// ------------------------------------------------------------------
#define SCW_AW (16 * 124)
#define SCW_RR (16 * 232)
#define SCW_MX (16 * 232)
#define SCW_W  (128 * 124)
#define SCW_SMEM ((2*SCW_AW + SCW_RR + SCW_MX + 2*SCW_W) * 4)

__global__ __launch_bounds__(256) void scan_all_h(
    float* __restrict__ x0, float* __restrict__ x1,
    const __half* __restrict__ WhT, const __half* __restrict__ WlT,
    const float* __restrict__ ident)
{
    extern __shared__ uint32_t su[];
    uint32_t* mAh = su;
    uint32_t* mAl = mAh + SCW_AW;
    float*    rr  = (float*)(mAl + SCW_AW);
    float*    mx  = rr + SCW_RR;
    uint32_t* Wh  = (uint32_t*)(mx + SCW_MX);
    uint32_t* Wl  = Wh + SCW_W;
    const uint32_t wh_base = smem_u32(Wh);
    const uint32_t wl_base = smem_u32(Wl);
    __half* mAh_h = (__half*)mAh;
    __half* mAl_h = (__half*)mAl;

    const int tid = threadIdx.x;
    const int lane = tid & 31, wid = tid >> 5;
    const int l3 = lane & 3, lq = lane >> 2;
    const int T0 = blockIdx.x * 16;

    int step = 0;
    for (int off = 1; off < SEQ; off <<= 1, step++) {
        const float* xin = (step & 1) ? x1 : x0;
        float* xout      = (step & 1) ? x0 : x1;

        // ---- load + fp16 hi/lo split ----
        if (tid < 248) {
            int c = tid;
            #pragma unroll
            for (int t = 0; t < 16; t++) {
                int tok = T0 + t;
                int tt = tok & (SEQ - 1);
                float rv = 0.f, lv = 0.f;
                if (c < C_DIM) {
                    rv = xin[tok * C_DIM + c];
                    lv = (tt >= off) ? xin[(tok - off) * C_DIM + c] : ident[c];
                }
                if (c < 232) rr[t * 232 + c] = rv;
                float s = lv + rv;
                __half hi = __float2half_rn(s);
                __half lo = __float2half_rn(s - __half2float(hi));
                mAh_h[t * 248 + c] = hi;
                mAl_h[t * 248 + c] = lo;
            }
        }
        __syncthreads();

        // ---- mix GEMM: 2 n-chunks of 128, fp16 hi/lo 3-term ----
        float acc[2][2][4];
        #pragma unroll
        for (int i = 0; i < 2; i++)
            #pragma unroll
            for (int j = 0; j < 2; j++)
                #pragma unroll
                for (int q = 0; q < 4; q++) acc[i][j][q] = 0.f;

        #pragma unroll
        for (int ci = 0; ci < 2; ci++) {
            const int n0 = ci * 128;
            // stage W chunk via cp.async (rows n0..n0+127)
            for (int i = tid; i < 128 * 30; i += 256) {
                int n = i / 30, s5 = i - (i / 30) * 30;
                cp_async16(wh_base + (uint32_t)(n * 124 + s5 * 4) * 4,
                           WhT + (size_t)(n0 + n) * WKP + s5 * 8);
                cp_async16(wl_base + (uint32_t)(n * 124 + s5 * 4) * 4,
                           WlT + (size_t)(n0 + n) * WKP + s5 * 8);
            }
            asm volatile("cp.async.commit_group;" ::: "memory");
            asm volatile("cp.async.wait_group 0;" ::: "memory");
            __syncthreads();

            #pragma unroll
            for (int kk = 0; kk < 15; kk++) {
                uint32_t ah[4], al[4];
                ah[0] = mAh[lq * 124 + kk * 8 + l3];
                ah[1] = mAh[(lq + 8) * 124 + kk * 8 + l3];
                ah[2] = mAh[lq * 124 + kk * 8 + 4 + l3];
                ah[3] = mAh[(lq + 8) * 124 + kk * 8 + 4 + l3];
                al[0] = mAl[lq * 124 + kk * 8 + l3];
                al[1] = mAl[(lq + 8) * 124 + kk * 8 + l3];
                al[2] = mAl[lq * 124 + kk * 8 + 4 + l3];
                al[3] = mAl[(lq + 8) * 124 + kk * 8 + 4 + l3];
                #pragma unroll
                for (int nt = 0; nt < 2; nt++) {
                    int n = wid * 16 + nt * 8 + lq;
                    uint32_t bh[2], bl[2];
                    bh[0] = Wh[n * 124 + kk * 8 + l3];
                    bh[1] = Wh[n * 124 + kk * 8 + 4 + l3];
                    bl[0] = Wl[n * 124 + kk * 8 + l3];
                    bl[1] = Wl[n * 124 + kk * 8 + 4 + l3];
                    mma16(acc[ci][nt], ah, bh);
                    mma16(acc[ci][nt], ah, bl);
                    mma16(acc[ci][nt], al, bh);
                }
            }
            __syncthreads();  // all warps done reading W before next chunk overwrites
        }

        // ---- store mix ----
        #pragma unroll
        for (int ci = 0; ci < 2; ci++) {
            #pragma unroll
            for (int nt = 0; nt < 2; nt++) {
                int n = ci * 128 + wid * 16 + nt * 8 + l3 * 2;
                if (n < C_DIM) {
                    mx[lq * 232 + n]       = acc[ci][nt][0];
                    mx[(lq + 8) * 232 + n] = acc[ci][nt][2];
                }
                if (n + 1 < C_DIM) {
                    mx[lq * 232 + n + 1]       = acc[ci][nt][1];
                    mx[(lq + 8) * 232 + n + 1] = acc[ci][nt][3];
                }
            }
        }
        __syncthreads();

        // ---- combine (R8-proven) ----
        const int d0 = lane;
        const int d1 = lane + 32;
        const bool has1 = (lane < HD - 32);
        #pragma unroll
        for (int e = 0; e < 8; e++) {
            int p = wid * 8 + e;
            int t = p >> 2;
            int l = p & 3;
            int tok = T0 + t;

            float s0 = __half2float(mAh_h[t * 248 + l * HD + d0])
                     + __half2float(mAl_h[t * 248 + l * HD + d0]);
            float q0 = s0 - rr[t * 232 + l * HD + d0];
            float q1 = 0.f;
            if (has1) {
                float s1 = __half2float(mAh_h[t * 248 + l * HD + d1])
                         + __half2float(mAl_h[t * 248 + l * HD + d1]);
                q1 = s1 - rr[t * 232 + l * HD + d1];
            }

            float sc[4];
            #pragma unroll
            for (int m = 0; m < 4; m++) {
                float pr = q0 * rr[t * 232 + m * HD + d0];
                if (has1) pr += q1 * rr[t * 232 + m * HD + d1];
                #pragma unroll
                for (int o = 16; o > 0; o >>= 1) pr += __shfl_xor_sync(0xffffffffu, pr, o);
                sc[m] = pr * 0.13245323570650439f;
            }
            float mxv = fmaxf(fmaxf(sc[0], sc[1]), fmaxf(sc[2], sc[3]));
            float e0 = expf(sc[0] - mxv), e1 = expf(sc[1] - mxv);
            float e2 = expf(sc[2] - mxv), e3 = expf(sc[3] - mxv);
            float inv = 1.0f / (e0 + e1 + e2 + e3);
            float a0 = e0 * inv, a1 = e1 * inv, a2 = e2 * inv, a3 = e3 * inv;

            float z0 = a0 * mx[t * 232 + 0 * HD + d0] + a1 * mx[t * 232 + 1 * HD + d0]
                     + a2 * mx[t * 232 + 2 * HD + d0] + a3 * mx[t * 232 + 3 * HD + d0];
            float z1 = 0.f;
            if (has1)
                z1 = a0 * mx[t * 232 + 0 * HD + d1] + a1 * mx[t * 232 + 1 * HD + d1]
                   + a2 * mx[t * 232 + 2 * HD + d1] + a3 * mx[t * 232 + 3 * HD + d1];

            float ss = z0 * z0 + z1 * z1;
            #pragma unroll
            for (int o = 16; o > 0; o >>= 1) ss += __shfl_xor_sync(0xffffffffu, ss, o);
            float scale = rsqrtf(ss * (1.0f / 57.0f) + 1e-6f) / (1.0f + (float)l);

            xout[tok * C_DIM + l * HD + d0] = q0 + z0 * scale;
            if (has1) xout[tok * C_DIM + l * HD + d1] = q1 + z1 * scale;
        }

        if ((off << 1) < SEQ) grid_barrier();
    }
}

// ------------------------------------------------------------------
extern "C" void kernel_launch(void* const* d_in, const int* in_sizes, int n_in,
                              void* d_out, int out_size) {
    const int*   idx    = (const int*)  d_in[0];
    const float* wte    = (const float*)d_in[1];
    const float* ln1_g  = (const float*)d_in[2];
    const float* ln2_g  = (const float*)d_in[3];
    const float* w_up   = (const float*)d_in[4];
    const float* w_v    = (const float*)d_in[5];
    const float* w_cpr  = (const float*)d_in[6];
    const float* w_scan = (const float*)d_in[7];
    const float* ident  = (const float*)d_in[8];
    const float* w_fc   = (const float*)d_in[9];
    const float* w_proj = (const float*)d_in[10];
    float* out = (float*)d_out;

    float *px, *ph, *pv, *pa, *pb, *pmlp;
    __half *pwh, *pxh, *pwsh, *pwsl;
    cudaGetSymbolAddress((void**)&px,   g_x);
    cudaGetSymbolAddress((void**)&ph,   g_h);
    cudaGetSymbolAddress((void**)&pv,   g_v);
    cudaGetSymbolAddress((void**)&pa,   g_bufA);
    cudaGetSymbolAddress((void**)&pb,   g_bufB);
    cudaGetSymbolAddress((void**)&pmlp, g_mlp);
    cudaGetSymbolAddress((void**)&pwh,  g_wte_h);
    cudaGetSymbolAddress((void**)&pxh,  g_x_h);
    cudaGetSymbolAddress((void**)&pwsh, g_wsh);
    cudaGetSymbolAddress((void**)&pwsl, g_wsl);

    cudaFuncSetAttribute(scan_all_h,
                         cudaFuncAttributeMaxDynamicSharedMemorySize, SCW_SMEM);
    cudaFuncSetAttribute(lmhead_h2,
                         cudaFuncAttributeMaxDynamicSharedMemorySize, LMH_SMEM);

    const int CC = C_DIM * C_DIM;
    const int FC = FF * C_DIM;

    embed_kernel<<<(TOKENS * C_DIM + 255) / 256, 256>>>(idx, wte, px);
    cvt_half_kernel<<<(VPAD * 64 + 255) / 256, 256>>>(wte, pwh, VPAD, VOCAB);
    cvt_wscan_kernel<<<(NLAYER * WKP * 57 + 255) / 256, 256>>>(w_scan, pwsh, pwsl);

    for (int L = 0; L < NLAYER; L++) {
        const float* wupL  = w_up   + L * CC;
        const float* wvL   = w_v    + L * CC;
        const float* wcprL = w_cpr  + L * CC;
        const float* idL   = ident  + L * C_DIM;
        const float* wfcL  = w_fc   + L * FC;
        const float* wprL  = w_proj + L * FC;

        ln_kernel<<<(TOKENS * 32 + 255) / 256, 256>>>(px, ln1_g + L * C_DIM, ph);

        dim3 gs(TOKENS / 64, (C_DIM + 63) / 64);
        hgemm<0,0><<<gs, 256>>>(ph, nullptr, wupL, pa, TOKENS, C_DIM, C_DIM);
        hgemm<0,0><<<gs, 256>>>(ph, nullptr, wvL,  pv, TOKENS, C_DIM, C_DIM);

        scan_all_h<<<TOKENS / 16, 256, SCW_SMEM>>>(
            pa, pb, pwsh + (size_t)L * WNP * WKP, pwsl + (size_t)L * WNP * WKP, idL);

        hgemm<2,1><<<gs, 256>>>(pa, pv, wcprL, px, TOKENS, C_DIM, C_DIM);

        ln_kernel<<<(TOKENS * 32 + 255) / 256, 256>>>(px, ln2_g + L * C_DIM, ph);

        dim3 gf(TOKENS / 64, (FF + 63) / 64);
        hgemm<0,2><<<gf, 256>>>(ph, nullptr, wfcL, pmlp, TOKENS, FF, C_DIM);
        hgemm<0,1><<<gs, 256>>>(pmlp, nullptr, wprL, px, TOKENS, C_DIM, FF);
    }

    cvt_half_kernel<<<(TOKENS * 64 + 255) / 256, 256>>>(px, pxh, TOKENS, TOKENS);

    dim3 gl(TOKENS / 128, VPAD / 128);
    lmhead_h2<<<gl, 256, LMH_SMEM>>>(pxh, pwh, out);
}

// round 11
// speedup vs baseline: 4.2487x; 1.0375x over previous
#include <cuda_runtime.h>
#include <cuda_fp16.h>
#include <cstdint>
#include <math.h>

#define C_DIM 228
#define TOKENS 2048
#define SEQ 1024
#define HD 57
#define LANES 4
#define FF 912
#define NLAYER 4
#define VOCAB 50257
#define VPAD 50304
#define KPAD 256
#define WKP 240
#define WNP 256

// ------------------------------------------------------------------
// Scratch
// ------------------------------------------------------------------
__device__ float g_x   [TOKENS * C_DIM];
__device__ float g_v   [TOKENS * C_DIM];
__device__ float g_bufA[TOKENS * C_DIM];
__device__ float g_bufB[TOKENS * C_DIM];
__device__ float g_mlp [TOKENS * FF];
__device__ float2 g_stats[TOKENS];
__device__ __half g_wte_h[VPAD * KPAD];
__device__ __half g_x_h  [TOKENS * KPAD];
__device__ __half g_wsh  [NLAYER * WNP * WKP];
__device__ __half g_wsl  [NLAYER * WNP * WKP];
__device__ unsigned g_bar_cnt = 0;
__device__ unsigned g_bar_gen = 0;

__device__ __forceinline__ float gelu_f(float x) {
    float x3 = x * x * x;
    return 0.5f * x * (1.0f + tanhf(0.7978845608028654f * (x + 0.044715f * x3)));
}
__device__ __forceinline__ void mma16(float* c, const uint32_t* a, const uint32_t* b) {
    asm volatile("mma.sync.aligned.m16n8k16.row.col.f32.f16.f16.f32 "
        "{%0,%1,%2,%3}, {%4,%5,%6,%7}, {%8,%9}, {%0,%1,%2,%3};"
        : "+f"(c[0]), "+f"(c[1]), "+f"(c[2]), "+f"(c[3])
        : "r"(a[0]), "r"(a[1]), "r"(a[2]), "r"(a[3]), "r"(b[0]), "r"(b[1]));
}
__device__ __forceinline__ uint32_t pack_h2(float x, float y) {
    __half2 h = __halves2half2(__float2half_rn(x), __float2half_rn(y));
    return *(uint32_t*)&h;
}
__device__ __forceinline__ void split_h2(float x, float y, uint32_t& hi, uint32_t& lo) {
    __half hx = __float2half_rn(x), hy = __float2half_rn(y);
    float rx = x - __half2float(hx), ry = y - __half2float(hy);
    __half2 h = __halves2half2(hx, hy);
    __half2 l = __halves2half2(__float2half_rn(rx), __float2half_rn(ry));
    hi = *(uint32_t*)&h;
    lo = *(uint32_t*)&l;
}
__device__ __forceinline__ uint32_t smem_u32(const void* p) {
    uint32_t a;
    asm("{ .reg .u64 t; cvta.to.shared.u64 t, %1; cvt.u32.u64 %0, t; }" : "=r"(a) : "l"(p));
    return a;
}
__device__ __forceinline__ void cp_async16(uint32_t dst, const void* src) {
    asm volatile("cp.async.cg.shared.global [%0], [%1], 16;" :: "r"(dst), "l"(src));
}

// ------------------------------------------------------------------
// Embedding gather (int32/int64 auto-detect)
// ------------------------------------------------------------------
__global__ __launch_bounds__(256) void embed_kernel(const int* __restrict__ idx32,
                                                    const float* __restrict__ wte,
                                                    float* __restrict__ x) {
    __shared__ int s_is64;
    if (threadIdx.x == 0) {
        int all0 = 1;
        #pragma unroll
        for (int i = 1; i < 16; i += 2)
            if (idx32[i] != 0) all0 = 0;
        s_is64 = all0;
    }
    __syncthreads();
    int gid = blockIdx.x * 256 + threadIdx.x;
    if (gid >= TOKENS * C_DIM) return;
    int t = gid / C_DIM;
    int c = gid - t * C_DIM;
    int id = s_is64 ? idx32[2 * t] : idx32[t];
    x[gid] = wte[id * C_DIM + c];
}

// ------------------------------------------------------------------
// f32 -> padded f16 conversion (wte / final x)
// ------------------------------------------------------------------
__global__ __launch_bounds__(256) void cvt_half_kernel(const float* __restrict__ src,
                                                       __half* __restrict__ dst,
                                                       int dstRows, int srcRows) {
    int idx = blockIdx.x * 256 + threadIdx.x;
    if (idx >= dstRows * 64) return;
    int r = idx >> 6, c4 = idx & 63;
    uint32_t p[2];
    if (c4 < 57 && r < srcRows) {
        float4 v = *(const float4*)&src[r * C_DIM + c4 * 4];
        p[0] = pack_h2(v.x, v.y);
        p[1] = pack_h2(v.z, v.w);
    } else {
        p[0] = 0u; p[1] = 0u;
    }
    *(uint2*)&dst[r * KPAD + c4 * 4] = *(uint2*)p;
}

// ------------------------------------------------------------------
// w_scan (all layers) -> transposed fp16 hi/lo, zero-padded.
// ------------------------------------------------------------------
__global__ __launch_bounds__(256) void cvt_wscan_kernel(const float* __restrict__ wsc,
                                                        __half* __restrict__ WhT,
                                                        __half* __restrict__ WlT) {
    int idx = blockIdx.x * 256 + threadIdx.x;
    if (idx >= NLAYER * WKP * 57) return;
    int L = idx / (WKP * 57);
    int rem = idx - L * (WKP * 57);
    int k = rem / 57, n4 = rem - (rem / 57) * 57;
    float4 v = make_float4(0.f, 0.f, 0.f, 0.f);
    if (k < C_DIM)
        v = *(const float4*)&wsc[L * C_DIM * C_DIM + k * C_DIM + n4 * 4];
    __half* wh = WhT + L * WNP * WKP;
    __half* wl = WlT + L * WNP * WKP;
    const float* vv = (const float*)&v;
    #pragma unroll
    for (int j = 0; j < 4; j++) {
        float x = vv[j];
        __half hi = __float2half_rn(x);
        __half lo = __float2half_rn(x - __half2float(hi));
        wh[(n4 * 4 + j) * WKP + k] = hi;
        wl[(n4 * 4 + j) * WKP + k] = lo;
    }
}

// ------------------------------------------------------------------
// LN stats only: mean + rstd per token (16 KB instead of 1.8 MB)
// ------------------------------------------------------------------
__global__ __launch_bounds__(256) void ln_stats_kernel(const float* __restrict__ x,
                                                       float2* __restrict__ stats) {
    int w = (blockIdx.x * 256 + threadIdx.x) >> 5;
    int lane = threadIdx.x & 31;
    if (w >= TOKENS) return;
    const float* row = x + w * C_DIM;
    float s = 0.f, s2 = 0.f;
    for (int c = lane; c < C_DIM; c += 32) {
        float v = row[c];
        s += v; s2 += v * v;
    }
    #pragma unroll
    for (int o = 16; o > 0; o >>= 1) {
        s  += __shfl_xor_sync(0xffffffffu, s, o);
        s2 += __shfl_xor_sync(0xffffffffu, s2, o);
    }
    if (lane == 0) {
        float mean = s * (1.0f / C_DIM);
        float var = s2 * (1.0f / C_DIM) - mean * mean;
        stats[w] = make_float2(mean, rsqrtf(var + 1e-5f));
    }
}

// ------------------------------------------------------------------
// Split-fp16 internal GEMM (NT).
// AMODE 0: A plain; 1: LN fused ((A-mean)*rstd*gamma[k]); 2: A*A2.
// EPI 0: store; 1: +=; 2: gelu.
// ------------------------------------------------------------------
template<int AMODE, int EPI>
__global__ __launch_bounds__(256) void hgemm(
    const float* __restrict__ A, const float* __restrict__ A2,
    const float* __restrict__ B, float* __restrict__ Cc,
    int M, int N, int K,
    const float2* __restrict__ stats, const float* __restrict__ gamma)
{
    __shared__ uint32_t Ah[64][20], Al[64][20], Bh[64][20], Bl[64][20];
    const int tid = threadIdx.x;
    const int lane = tid & 31, wid = tid >> 5;
    const int wm = wid >> 2, wn = wid & 3;
    const int l3 = lane & 3, lq = lane >> 2;
    const int m0 = blockIdx.x * 64, n0 = blockIdx.y * 64;

    float acc[2][2][4];
    #pragma unroll
    for (int i = 0; i < 2; i++)
        #pragma unroll
        for (int j = 0; j < 2; j++)
            #pragma unroll
            for (int q = 0; q < 4; q++) acc[i][j][q] = 0.f;

    const int nchunk = (K + 31) / 32;

    auto loadA = [&](int r, int k) -> float4 {
        float4 v = make_float4(0.f,0.f,0.f,0.f);
        if (k + 3 < K) {
            v = *(const float4*)&A[(m0 + r) * K + k];
            if (AMODE == 1) {
                float2 st = stats[m0 + r];
                float4 gg = *(const float4*)&gamma[k];
                v.x = (v.x - st.x) * st.y * gg.x;
                v.y = (v.y - st.x) * st.y * gg.y;
                v.z = (v.z - st.x) * st.y * gg.z;
                v.w = (v.w - st.x) * st.y * gg.w;
            }
            if (AMODE == 2) {
                float4 u = *(const float4*)&A2[(m0 + r) * K + k];
                v.x *= u.x; v.y *= u.y; v.z *= u.z; v.w *= u.w;
            }
        }
        return v;
    };

    float4 pa[2], pb[2];
    #pragma unroll
    for (int i = 0; i < 2; i++) {
        int idx = tid + i * 256;
        int r = idx >> 3, f = idx & 7;
        int k = f * 4;
        pa[i] = loadA(r, k);
        float4 v = make_float4(0.f,0.f,0.f,0.f);
        if (k + 3 < K && (n0 + r) < N)
            v = *(const float4*)&B[(n0 + r) * K + k];
        pb[i] = v;
    }

    for (int ch = 0; ch < nchunk; ch++) {
        __syncthreads();
        #pragma unroll
        for (int i = 0; i < 2; i++) {
            int idx = tid + i * 256;
            int r = idx >> 3, f = idx & 7;
            uint32_t h0, l0, h1, l1;
            split_h2(pa[i].x, pa[i].y, h0, l0);
            split_h2(pa[i].z, pa[i].w, h1, l1);
            Ah[r][f*2] = h0; Ah[r][f*2+1] = h1;
            Al[r][f*2] = l0; Al[r][f*2+1] = l1;
            split_h2(pb[i].x, pb[i].y, h0, l0);
            split_h2(pb[i].z, pb[i].w, h1, l1);
            Bh[r][f*2] = h0; Bh[r][f*2+1] = h1;
            Bl[r][f*2] = l0; Bl[r][f*2+1] = l1;
        }
        __syncthreads();
        if (ch + 1 < nchunk) {
            int k0 = (ch + 1) * 32;
            #pragma unroll
            for (int i = 0; i < 2; i++) {
                int idx = tid + i * 256;
                int r = idx >> 3, f = idx & 7;
                int k = k0 + f * 4;
                pa[i] = loadA(r, k);
                float4 v = make_float4(0.f,0.f,0.f,0.f);
                if (k + 3 < K && (n0 + r) < N)
                    v = *(const float4*)&B[(n0 + r) * K + k];
                pb[i] = v;
            }
        }
        #pragma unroll
        for (int kc2 = 0; kc2 < 16; kc2 += 8) {
            uint32_t ah[2][4], al[2][4], bh[2][2], bl[2][2];
            #pragma unroll
            for (int mt = 0; mt < 2; mt++) {
                int r = wm * 32 + mt * 16 + lq;
                ah[mt][0] = Ah[r    ][kc2 + l3];
                ah[mt][1] = Ah[r + 8][kc2 + l3];
                ah[mt][2] = Ah[r    ][kc2 + 4 + l3];
                ah[mt][3] = Ah[r + 8][kc2 + 4 + l3];
                al[mt][0] = Al[r    ][kc2 + l3];
                al[mt][1] = Al[r + 8][kc2 + l3];
                al[mt][2] = Al[r    ][kc2 + 4 + l3];
                al[mt][3] = Al[r + 8][kc2 + 4 + l3];
            }
            #pragma unroll
            for (int nt = 0; nt < 2; nt++) {
                int n = wn * 16 + nt * 8 + lq;
                bh[nt][0] = Bh[n][kc2 + l3];
                bh[nt][1] = Bh[n][kc2 + 4 + l3];
                bl[nt][0] = Bl[n][kc2 + l3];
                bl[nt][1] = Bl[n][kc2 + 4 + l3];
            }
            #pragma unroll
            for (int mt = 0; mt < 2; mt++)
                #pragma unroll
                for (int nt = 0; nt < 2; nt++) {
                    mma16(acc[mt][nt], ah[mt], bh[nt]);
                    mma16(acc[mt][nt], ah[mt], bl[nt]);
                    mma16(acc[mt][nt], al[mt], bh[nt]);
                }
        }
    }

    #pragma unroll
    for (int mt = 0; mt < 2; mt++) {
        #pragma unroll
        for (int nt = 0; nt < 2; nt++) {
            int n = n0 + wn * 16 + nt * 8 + l3 * 2;
            #pragma unroll
            for (int half = 0; half < 2; half++) {
                int mm = m0 + wm * 32 + mt * 16 + lq + half * 8;
                float r0 = acc[mt][nt][half * 2];
                float r1 = acc[mt][nt][half * 2 + 1];
                if (n < N) {
                    if (EPI == 1) r0 += Cc[mm * N + n];
                    if (EPI == 2) r0 = gelu_f(r0);
                    Cc[mm * N + n] = r0;
                }
                if (n + 1 < N) {
                    if (EPI == 1) r1 += Cc[mm * N + n + 1];
                    if (EPI == 2) r1 = gelu_f(r1);
                    Cc[mm * N + n + 1] = r1;
                }
            }
        }
    }
}

// ------------------------------------------------------------------
// Pipelined fp16 lm_head — R8-proven.
// ------------------------------------------------------------------
#define LMH_AW   (128 * 36)
#define LMH_SW   (2 * LMH_AW)
#define LMH_SMEM (2 * LMH_SW * 4)

__global__ __launch_bounds__(256) void lmhead_h2(
    const __half* __restrict__ Ah_g, const __half* __restrict__ Bh_g,
    float* __restrict__ C)
{
    extern __shared__ uint32_t dsm[];
    const uint32_t smem_base = smem_u32(dsm);

    const int tid = threadIdx.x;
    const int lane = tid & 31, wid = tid >> 5;
    const int wm = wid >> 2, wn = wid & 3;
    const int l3 = lane & 3, lq = lane >> 2;
    const int m0 = blockIdx.x * 128, n0 = blockIdx.y * 128;

    float acc[4][4][4];
    #pragma unroll
    for (int i = 0; i < 4; i++)
        #pragma unroll
        for (int j = 0; j < 4; j++)
            #pragma unroll
            for (int q = 0; q < 4; q++) acc[i][j][q] = 0.f;

    const int r_ld = tid >> 3;
    const int c16  = tid & 7;

    auto issue = [&](int kc, int bi) {
        uint32_t ab = smem_base + (uint32_t)bi * (LMH_SW * 4);
        uint32_t bb = ab + LMH_AW * 4;
        const __half* asrc = Ah_g + (size_t)(m0 + r_ld) * KPAD + kc * 64 + c16 * 8;
        const __half* bsrc = Bh_g + (size_t)(n0 + r_ld) * KPAD + kc * 64 + c16 * 8;
        #pragma unroll
        for (int i = 0; i < 4; i++) {
            int r = r_ld + i * 32;
            cp_async16(ab + (uint32_t)(r * 36 + c16 * 4) * 4,
                       asrc + (size_t)(i * 32) * KPAD);
            cp_async16(bb + (uint32_t)(r * 36 + c16 * 4) * 4,
                       bsrc + (size_t)(i * 32) * KPAD);
        }
        asm volatile("cp.async.commit_group;" ::: "memory");
    };

    issue(0, 0);

    #pragma unroll 1
    for (int kc = 0; kc < 4; kc++) {
        if (kc + 1 < 4) {
            issue(kc + 1, (kc + 1) & 1);
            asm volatile("cp.async.wait_group 1;" ::: "memory");
        } else {
            asm volatile("cp.async.wait_group 0;" ::: "memory");
        }
        __syncthreads();

        const uint32_t* As2 = dsm + (kc & 1) * LMH_SW;
        const uint32_t* Bs2 = As2 + LMH_AW;

        #pragma unroll
        for (int kc2 = 0; kc2 < 32; kc2 += 8) {
            uint32_t af[4][4], bf[4][2];
            #pragma unroll
            for (int mt = 0; mt < 4; mt++) {
                int r = wm * 64 + mt * 16 + lq;
                af[mt][0] = As2[r * 36 + kc2 + l3];
                af[mt][1] = As2[(r + 8) * 36 + kc2 + l3];
                af[mt][2] = As2[r * 36 + kc2 + 4 + l3];
                af[mt][3] = As2[(r + 8) * 36 + kc2 + 4 + l3];
            }
            #pragma unroll
            for (int nt = 0; nt < 4; nt++) {
                int n = wn * 32 + nt * 8 + lq;
                bf[nt][0] = Bs2[n * 36 + kc2 + l3];
                bf[nt][1] = Bs2[n * 36 + kc2 + 4 + l3];
            }
            #pragma unroll
            for (int mt = 0; mt < 4; mt++)
                #pragma unroll
                for (int nt = 0; nt < 4; nt++)
                    mma16(acc[mt][nt], af[mt], bf[nt]);
        }
        __syncthreads();
    }

    #pragma unroll
    for (int mt = 0; mt < 4; mt++) {
        #pragma unroll
        for (int nt = 0; nt < 4; nt++) {
            int n = n0 + wn * 32 + nt * 8 + l3 * 2;
            #pragma unroll
            for (int half = 0; half < 2; half++) {
                int mm = m0 + wm * 64 + mt * 16 + lq + half * 8;
                float* dst = &C[(size_t)mm * VOCAB + n];
                if (n     < VOCAB) dst[0] = acc[mt][nt][half * 2];
                if (n + 1 < VOCAB) dst[1] = acc[mt][nt][half * 2 + 1];
            }
        }
    }
}

// ------------------------------------------------------------------
// Grid-wide barrier (all 128 blocks resident)
// ------------------------------------------------------------------
__device__ __forceinline__ void grid_barrier() {
    __syncthreads();
    if (threadIdx.x == 0) {
        __threadfence();
        unsigned gen = atomicAdd(&g_bar_gen, 0u);
        unsigned t = atomicAdd(&g_bar_cnt, 1u);
        if (t == gridDim.x - 1) {
            atomicExch(&g_bar_cnt, 0u);
            __threadfence();
            atomicAdd(&g_bar_gen, 1u);
        } else {
            while (atomicAdd(&g_bar_gen, 0u) == gen) __nanosleep(64);
        }
    }
    __syncthreads();
}

// ------------------------------------------------------------------
// Persistent pscan, fp16-split mix GEMM, 512 threads (16 warps).
// 128 blocks, 16 tokens/block, 10 Kogge-Stone steps.
// ------------------------------------------------------------------
#define SCW_AW (16 * 124)
#define SCW_RR (16 * 232)
#define SCW_MX (16 * 232)
#define SCW_W  (128 * 124)
#define SCW_SMEM ((2*SCW_AW + SCW_RR + SCW_MX + 2*SCW_W) * 4)

__global__ __launch_bounds__(512) void scan_all_h(
    float* __restrict__ x0, float* __restrict__ x1,
    const __half* __restrict__ WhT, const __half* __restrict__ WlT,
    const float* __restrict__ ident)
{
    extern __shared__ uint32_t su[];
    uint32_t* mAh = su;
    uint32_t* mAl = mAh + SCW_AW;
    float*    rr  = (float*)(mAl + SCW_AW);
    float*    mx  = rr + SCW_RR;
    uint32_t* Wh  = (uint32_t*)(mx + SCW_MX);
    uint32_t* Wl  = Wh + SCW_W;
    const uint32_t wh_base = smem_u32(Wh);
    const uint32_t wl_base = smem_u32(Wl);
    __half* mAh_h = (__half*)mAh;
    __half* mAl_h = (__half*)mAl;

    const int tid = threadIdx.x;
    const int lane = tid & 31, wid = tid >> 5;   // wid 0..15
    const int l3 = lane & 3, lq = lane >> 2;
    const int T0 = blockIdx.x * 16;
    const int half_id = tid >> 8;                // 0/1
    const int hc = tid & 255;                    // 0..255

    int step = 0;
    for (int off = 1; off < SEQ; off <<= 1, step++) {
        const float* xin = (step & 1) ? x1 : x0;
        float* xout      = (step & 1) ? x0 : x1;

        // ---- load + fp16 hi/lo split (each half of the block: 8 tokens) ----
        if (hc < 248) {
            int c = hc;
            #pragma unroll
            for (int tl = 0; tl < 8; tl++) {
                int t = half_id * 8 + tl;
                int tok = T0 + t;
                int tt = tok & (SEQ - 1);
                float rv = 0.f, lv = 0.f;
                if (c < C_DIM) {
                    rv = xin[tok * C_DIM + c];
                    lv = (tt >= off) ? xin[(tok - off) * C_DIM + c] : ident[c];
                }
                if (c < 232) rr[t * 232 + c] = rv;
                float s = lv + rv;
                __half hi = __float2half_rn(s);
                __half lo = __float2half_rn(s - __half2float(hi));
                mAh_h[t * 248 + c] = hi;
                mAl_h[t * 248 + c] = lo;
            }
        }
        __syncthreads();

        // ---- mix GEMM: 2 n-chunks of 128; warp covers 8 n-cols ----
        float acc[2][4];
        #pragma unroll
        for (int i = 0; i < 2; i++)
            #pragma unroll
            for (int q = 0; q < 4; q++) acc[i][q] = 0.f;

        #pragma unroll
        for (int ci = 0; ci < 2; ci++) {
            const int n0 = ci * 128;
            for (int i = tid; i < 128 * 30; i += 512) {
                int n = i / 30, s5 = i - (i / 30) * 30;
                cp_async16(wh_base + (uint32_t)(n * 124 + s5 * 4) * 4,
                           WhT + (size_t)(n0 + n) * WKP + s5 * 8);
                cp_async16(wl_base + (uint32_t)(n * 124 + s5 * 4) * 4,
                           WlT + (size_t)(n0 + n) * WKP + s5 * 8);
            }
            asm volatile("cp.async.commit_group;" ::: "memory");
            asm volatile("cp.async.wait_group 0;" ::: "memory");
            __syncthreads();

            #pragma unroll
            for (int kk = 0; kk < 15; kk++) {
                uint32_t ah[4], al[4], bh[2], bl[2];
                ah[0] = mAh[lq * 124 + kk * 8 + l3];
                ah[1] = mAh[(lq + 8) * 124 + kk * 8 + l3];
                ah[2] = mAh[lq * 124 + kk * 8 + 4 + l3];
                ah[3] = mAh[(lq + 8) * 124 + kk * 8 + 4 + l3];
                al[0] = mAl[lq * 124 + kk * 8 + l3];
                al[1] = mAl[(lq + 8) * 124 + kk * 8 + l3];
                al[2] = mAl[lq * 124 + kk * 8 + 4 + l3];
                al[3] = mAl[(lq + 8) * 124 + kk * 8 + 4 + l3];
                int n = wid * 8 + lq;
                bh[0] = Wh[n * 124 + kk * 8 + l3];
                bh[1] = Wh[n * 124 + kk * 8 + 4 + l3];
                bl[0] = Wl[n * 124 + kk * 8 + l3];
                bl[1] = Wl[n * 124 + kk * 8 + 4 + l3];
                mma16(acc[ci], ah, bh);
                mma16(acc[ci], ah, bl);
                mma16(acc[ci], al, bh);
            }
            __syncthreads();
        }

        // ---- store mix ----
        #pragma unroll
        for (int ci = 0; ci < 2; ci++) {
            int n = ci * 128 + wid * 8 + l3 * 2;
            if (n < C_DIM) {
                mx[lq * 232 + n]       = acc[ci][0];
                mx[(lq + 8) * 232 + n] = acc[ci][2];
            }
            if (n + 1 < C_DIM) {
                mx[lq * 232 + n + 1]       = acc[ci][1];
                mx[(lq + 8) * 232 + n + 1] = acc[ci][3];
            }
        }
        __syncthreads();

        // ---- combine: 64 (token,lane) pairs, 4 per warp ----
        const int d0 = lane;
        const int d1 = lane + 32;
        const bool has1 = (lane < HD - 32);
        #pragma unroll
        for (int e = 0; e < 4; e++) {
            int p = wid * 4 + e;
            int t = p >> 2;
            int l = p & 3;
            int tok = T0 + t;

            float s0 = __half2float(mAh_h[t * 248 + l * HD + d0])
                     + __half2float(mAl_h[t * 248 + l * HD + d0]);
            float q0 = s0 - rr[t * 232 + l * HD + d0];
            float q1 = 0.f;
            if (has1) {
                float s1 = __half2float(mAh_h[t * 248 + l * HD + d1])
                         + __half2float(mAl_h[t * 248 + l * HD + d1]);
                q1 = s1 - rr[t * 232 + l * HD + d1];
            }

            float sc[4];
            #pragma unroll
            for (int m = 0; m < 4; m++) {
                float pr = q0 * rr[t * 232 + m * HD + d0];
                if (has1) pr += q1 * rr[t * 232 + m * HD + d1];
                #pragma unroll
                for (int o = 16; o > 0; o >>= 1) pr += __shfl_xor_sync(0xffffffffu, pr, o);
                sc[m] = pr * 0.13245323570650439f;
            }
            float mxv = fmaxf(fmaxf(sc[0], sc[1]), fmaxf(sc[2], sc[3]));
            float e0 = expf(sc[0] - mxv), e1 = expf(sc[1] - mxv);
            float e2 = expf(sc[2] - mxv), e3 = expf(sc[3] - mxv);
            float inv = 1.0f / (e0 + e1 + e2 + e3);
            float a0 = e0 * inv, a1 = e1 * inv, a2 = e2 * inv, a3 = e3 * inv;

            float z0 = a0 * mx[t * 232 + 0 * HD + d0] + a1 * mx[t * 232 + 1 * HD + d0]
                     + a2 * mx[t * 232 + 2 * HD + d0] + a3 * mx[t * 232 + 3 * HD + d0];
            float z1 = 0.f;
            if (has1)
                z1 = a0 * mx[t * 232 + 0 * HD + d1] + a1 * mx[t * 232 + 1 * HD + d1]
                   + a2 * mx[t * 232 + 2 * HD + d1] + a3 * mx[t * 232 + 3 * HD + d1];

            float ss = z0 * z0 + z1 * z1;
            #pragma unroll
            for (int o = 16; o > 0; o >>= 1) ss += __shfl_xor_sync(0xffffffffu, ss, o);
            float scale = rsqrtf(ss * (1.0f / 57.0f) + 1e-6f) / (1.0f + (float)l);

            xout[tok * C_DIM + l * HD + d0] = q0 + z0 * scale;
            if (has1) xout[tok * C_DIM + l * HD + d1] = q1 + z1 * scale;
        }

        if ((off << 1) < SEQ) grid_barrier();
    }
}

// ------------------------------------------------------------------
extern "C" void kernel_launch(void* const* d_in, const int* in_sizes, int n_in,
                              void* d_out, int out_size) {
    const int*   idx    = (const int*)  d_in[0];
    const float* wte    = (const float*)d_in[1];
    const float* ln1_g  = (const float*)d_in[2];
    const float* ln2_g  = (const float*)d_in[3];
    const float* w_up   = (const float*)d_in[4];
    const float* w_v    = (const float*)d_in[5];
    const float* w_cpr  = (const float*)d_in[6];
    const float* w_scan = (const float*)d_in[7];
    const float* ident  = (const float*)d_in[8];
    const float* w_fc   = (const float*)d_in[9];
    const float* w_proj = (const float*)d_in[10];
    float* out = (float*)d_out;

    float *px, *pv, *pa, *pb, *pmlp;
    float2* pst;
    __half *pwh, *pxh, *pwsh, *pwsl;
    cudaGetSymbolAddress((void**)&px,   g_x);
    cudaGetSymbolAddress((void**)&pv,   g_v);
    cudaGetSymbolAddress((void**)&pa,   g_bufA);
    cudaGetSymbolAddress((void**)&pb,   g_bufB);
    cudaGetSymbolAddress((void**)&pmlp, g_mlp);
    cudaGetSymbolAddress((void**)&pst,  g_stats);
    cudaGetSymbolAddress((void**)&pwh,  g_wte_h);
    cudaGetSymbolAddress((void**)&pxh,  g_x_h);
    cudaGetSymbolAddress((void**)&pwsh, g_wsh);
    cudaGetSymbolAddress((void**)&pwsl, g_wsl);

    cudaFuncSetAttribute(scan_all_h,
                         cudaFuncAttributeMaxDynamicSharedMemorySize, SCW_SMEM);
    cudaFuncSetAttribute(lmhead_h2,
                         cudaFuncAttributeMaxDynamicSharedMemorySize, LMH_SMEM);

    const int CC = C_DIM * C_DIM;
    const int FC = FF * C_DIM;

    embed_kernel<<<(TOKENS * C_DIM + 255) / 256, 256>>>(idx, wte, px);
    cvt_half_kernel<<<(VPAD * 64 + 255) / 256, 256>>>(wte, pwh, VPAD, VOCAB);
    cvt_wscan_kernel<<<(NLAYER * WKP * 57 + 255) / 256, 256>>>(w_scan, pwsh, pwsl);

    for (int L = 0; L < NLAYER; L++) {
        const float* wupL  = w_up   + L * CC;
        const float* wvL   = w_v    + L * CC;
        const float* wcprL = w_cpr  + L * CC;
        const float* idL   = ident  + L * C_DIM;
        const float* wfcL  = w_fc   + L * FC;
        const float* wprL  = w_proj + L * FC;

        ln_stats_kernel<<<(TOKENS * 32 + 255) / 256, 256>>>(px, pst);

        dim3 gs(TOKENS / 64, (C_DIM + 63) / 64);
        hgemm<1,0><<<gs, 256>>>(px, nullptr, wupL, pa, TOKENS, C_DIM, C_DIM,
                                pst, ln1_g + L * C_DIM);
        hgemm<1,0><<<gs, 256>>>(px, nullptr, wvL,  pv, TOKENS, C_DIM, C_DIM,
                                pst, ln1_g + L * C_DIM);

        scan_all_h<<<TOKENS / 16, 512, SCW_SMEM>>>(
            pa, pb, pwsh + (size_t)L * WNP * WKP, pwsl + (size_t)L * WNP * WKP, idL);

        hgemm<2,1><<<gs, 256>>>(pa, pv, wcprL, px, TOKENS, C_DIM, C_DIM,
                                nullptr, nullptr);

        ln_stats_kernel<<<(TOKENS * 32 + 255) / 256, 256>>>(px, pst);

        dim3 gf(TOKENS / 64, (FF + 63) / 64);
        hgemm<1,2><<<gf, 256>>>(px, nullptr, wfcL, pmlp, TOKENS, FF, C_DIM,
                                pst, ln2_g + L * C_DIM);
        hgemm<0,1><<<gs, 256>>>(pmlp, nullptr, wprL, px, TOKENS, C_DIM, FF,
                                nullptr, nullptr);
    }

    cvt_half_kernel<<<(TOKENS * 64 + 255) / 256, 256>>>(px, pxh, TOKENS, TOKENS);

    dim3 gl(TOKENS / 128, VPAD / 128);
    lmhead_h2<<<gl, 256, LMH_SMEM>>>(pxh, pwh, out);
}

// round 12
// speedup vs baseline: 5.1350x; 1.2086x over previous
#include <cuda_runtime.h>
#include <cuda_fp16.h>
#include <cstdint>
#include <math.h>

#define C_DIM 228
#define TOKENS 2048
#define SEQ 1024
#define HD 57
#define LANES 4
#define FF 912
#define NLAYER 4
#define VOCAB 50257
#define VPAD 50304
#define KPAD 256
#define WKP 240
#define WNP 256

// ------------------------------------------------------------------
// Scratch
// ------------------------------------------------------------------
__device__ float g_x   [TOKENS * C_DIM];
__device__ float g_v   [TOKENS * C_DIM];
__device__ float g_bufA[TOKENS * C_DIM];
__device__ float g_bufB[TOKENS * C_DIM];
__device__ float g_mlp [TOKENS * FF];
__device__ float2 g_stats[TOKENS];
__device__ __half g_wte_h[VPAD * KPAD];
__device__ __half g_x_h  [TOKENS * KPAD];
__device__ __half g_wsh  [NLAYER * WNP * WKP];
__device__ unsigned g_bar_cnt = 0;
__device__ unsigned g_bar_gen = 0;

__device__ __forceinline__ float gelu_f(float x) {
    float x3 = x * x * x;
    return 0.5f * x * (1.0f + tanhf(0.7978845608028654f * (x + 0.044715f * x3)));
}
__device__ __forceinline__ void mma16(float* c, const uint32_t* a, const uint32_t* b) {
    asm volatile("mma.sync.aligned.m16n8k16.row.col.f32.f16.f16.f32 "
        "{%0,%1,%2,%3}, {%4,%5,%6,%7}, {%8,%9}, {%0,%1,%2,%3};"
        : "+f"(c[0]), "+f"(c[1]), "+f"(c[2]), "+f"(c[3])
        : "r"(a[0]), "r"(a[1]), "r"(a[2]), "r"(a[3]), "r"(b[0]), "r"(b[1]));
}
__device__ __forceinline__ uint32_t pack_h2(float x, float y) {
    __half2 h = __halves2half2(__float2half_rn(x), __float2half_rn(y));
    return *(uint32_t*)&h;
}
__device__ __forceinline__ void split_h2(float x, float y, uint32_t& hi, uint32_t& lo) {
    __half hx = __float2half_rn(x), hy = __float2half_rn(y);
    float rx = x - __half2float(hx), ry = y - __half2float(hy);
    __half2 h = __halves2half2(hx, hy);
    __half2 l = __halves2half2(__float2half_rn(rx), __float2half_rn(ry));
    hi = *(uint32_t*)&h;
    lo = *(uint32_t*)&l;
}
__device__ __forceinline__ uint32_t smem_u32(const void* p) {
    uint32_t a;
    asm("{ .reg .u64 t; cvta.to.shared.u64 t, %1; cvt.u32.u64 %0, t; }" : "=r"(a) : "l"(p));
    return a;
}
__device__ __forceinline__ void cp_async16(uint32_t dst, const void* src) {
    asm volatile("cp.async.cg.shared.global [%0], [%1], 16;" :: "r"(dst), "l"(src));
}

// ------------------------------------------------------------------
// Embedding gather (int32/int64 auto-detect)
// ------------------------------------------------------------------
__global__ __launch_bounds__(256) void embed_kernel(const int* __restrict__ idx32,
                                                    const float* __restrict__ wte,
                                                    float* __restrict__ x) {
    __shared__ int s_is64;
    if (threadIdx.x == 0) {
        int all0 = 1;
        #pragma unroll
        for (int i = 1; i < 16; i += 2)
            if (idx32[i] != 0) all0 = 0;
        s_is64 = all0;
    }
    __syncthreads();
    int gid = blockIdx.x * 256 + threadIdx.x;
    if (gid >= TOKENS * C_DIM) return;
    int t = gid / C_DIM;
    int c = gid - t * C_DIM;
    int id = s_is64 ? idx32[2 * t] : idx32[t];
    x[gid] = wte[id * C_DIM + c];
}

// ------------------------------------------------------------------
// f32 -> padded f16 conversion (wte / final x)
// ------------------------------------------------------------------
__global__ __launch_bounds__(256) void cvt_half_kernel(const float* __restrict__ src,
                                                       __half* __restrict__ dst,
                                                       int dstRows, int srcRows) {
    int idx = blockIdx.x * 256 + threadIdx.x;
    if (idx >= dstRows * 64) return;
    int r = idx >> 6, c4 = idx & 63;
    uint32_t p[2];
    if (c4 < 57 && r < srcRows) {
        float4 v = *(const float4*)&src[r * C_DIM + c4 * 4];
        p[0] = pack_h2(v.x, v.y);
        p[1] = pack_h2(v.z, v.w);
    } else {
        p[0] = 0u; p[1] = 0u;
    }
    *(uint2*)&dst[r * KPAD + c4 * 4] = *(uint2*)p;
}

// ------------------------------------------------------------------
// w_scan (all layers) -> transposed fp16 hi, zero-padded.
// ------------------------------------------------------------------
__global__ __launch_bounds__(256) void cvt_wscan_kernel(const float* __restrict__ wsc,
                                                        __half* __restrict__ WhT) {
    int idx = blockIdx.x * 256 + threadIdx.x;
    if (idx >= NLAYER * WKP * 57) return;
    int L = idx / (WKP * 57);
    int rem = idx - L * (WKP * 57);
    int k = rem / 57, n4 = rem - (rem / 57) * 57;
    float4 v = make_float4(0.f, 0.f, 0.f, 0.f);
    if (k < C_DIM)
        v = *(const float4*)&wsc[L * C_DIM * C_DIM + k * C_DIM + n4 * 4];
    __half* wh = WhT + L * WNP * WKP;
    const float* vv = (const float*)&v;
    #pragma unroll
    for (int j = 0; j < 4; j++)
        wh[(n4 * 4 + j) * WKP + k] = __float2half_rn(vv[j]);
}

// ------------------------------------------------------------------
// LN stats only (float4 reads): mean + rstd per token
// ------------------------------------------------------------------
__global__ __launch_bounds__(256) void ln_stats_kernel(const float* __restrict__ x,
                                                       float2* __restrict__ stats) {
    int w = (blockIdx.x * 256 + threadIdx.x) >> 5;
    int lane = threadIdx.x & 31;
    if (w >= TOKENS) return;
    const float* row = x + w * C_DIM;
    float s = 0.f, s2 = 0.f;
    for (int c4 = lane; c4 < 57; c4 += 32) {
        float4 v = *(const float4*)&row[c4 * 4];
        s  += v.x + v.y + v.z + v.w;
        s2 += v.x * v.x + v.y * v.y + v.z * v.z + v.w * v.w;
    }
    #pragma unroll
    for (int o = 16; o > 0; o >>= 1) {
        s  += __shfl_xor_sync(0xffffffffu, s, o);
        s2 += __shfl_xor_sync(0xffffffffu, s2, o);
    }
    if (lane == 0) {
        float mean = s * (1.0f / C_DIM);
        float var = s2 * (1.0f / C_DIM) - mean * mean;
        stats[w] = make_float2(mean, rsqrtf(var + 1e-5f));
    }
}

// ------------------------------------------------------------------
// Split-fp16 internal GEMM (NT). AMODE 0 plain / 1 LN-fused / 2 A*A2.
// EPI 0 store / 1 += / 2 gelu.   (R11-proven)
// ------------------------------------------------------------------
template<int AMODE, int EPI>
__global__ __launch_bounds__(256) void hgemm(
    const float* __restrict__ A, const float* __restrict__ A2,
    const float* __restrict__ B, float* __restrict__ Cc,
    int M, int N, int K,
    const float2* __restrict__ stats, const float* __restrict__ gamma)
{
    __shared__ uint32_t Ah[64][20], Al[64][20], Bh[64][20], Bl[64][20];
    const int tid = threadIdx.x;
    const int lane = tid & 31, wid = tid >> 5;
    const int wm = wid >> 2, wn = wid & 3;
    const int l3 = lane & 3, lq = lane >> 2;
    const int m0 = blockIdx.x * 64, n0 = blockIdx.y * 64;

    float acc[2][2][4];
    #pragma unroll
    for (int i = 0; i < 2; i++)
        #pragma unroll
        for (int j = 0; j < 2; j++)
            #pragma unroll
            for (int q = 0; q < 4; q++) acc[i][j][q] = 0.f;

    const int nchunk = (K + 31) / 32;

    auto loadA = [&](int r, int k) -> float4 {
        float4 v = make_float4(0.f,0.f,0.f,0.f);
        if (k + 3 < K) {
            v = *(const float4*)&A[(m0 + r) * K + k];
            if (AMODE == 1) {
                float2 st = stats[m0 + r];
                float4 gg = *(const float4*)&gamma[k];
                v.x = (v.x - st.x) * st.y * gg.x;
                v.y = (v.y - st.x) * st.y * gg.y;
                v.z = (v.z - st.x) * st.y * gg.z;
                v.w = (v.w - st.x) * st.y * gg.w;
            }
            if (AMODE == 2) {
                float4 u = *(const float4*)&A2[(m0 + r) * K + k];
                v.x *= u.x; v.y *= u.y; v.z *= u.z; v.w *= u.w;
            }
        }
        return v;
    };

    float4 pa[2], pb[2];
    #pragma unroll
    for (int i = 0; i < 2; i++) {
        int idx = tid + i * 256;
        int r = idx >> 3, f = idx & 7;
        int k = f * 4;
        pa[i] = loadA(r, k);
        float4 v = make_float4(0.f,0.f,0.f,0.f);
        if (k + 3 < K && (n0 + r) < N)
            v = *(const float4*)&B[(n0 + r) * K + k];
        pb[i] = v;
    }

    for (int ch = 0; ch < nchunk; ch++) {
        __syncthreads();
        #pragma unroll
        for (int i = 0; i < 2; i++) {
            int idx = tid + i * 256;
            int r = idx >> 3, f = idx & 7;
            uint32_t h0, l0, h1, l1;
            split_h2(pa[i].x, pa[i].y, h0, l0);
            split_h2(pa[i].z, pa[i].w, h1, l1);
            Ah[r][f*2] = h0; Ah[r][f*2+1] = h1;
            Al[r][f*2] = l0; Al[r][f*2+1] = l1;
            split_h2(pb[i].x, pb[i].y, h0, l0);
            split_h2(pb[i].z, pb[i].w, h1, l1);
            Bh[r][f*2] = h0; Bh[r][f*2+1] = h1;
            Bl[r][f*2] = l0; Bl[r][f*2+1] = l1;
        }
        __syncthreads();
        if (ch + 1 < nchunk) {
            int k0 = (ch + 1) * 32;
            #pragma unroll
            for (int i = 0; i < 2; i++) {
                int idx = tid + i * 256;
                int r = idx >> 3, f = idx & 7;
                int k = k0 + f * 4;
                pa[i] = loadA(r, k);
                float4 v = make_float4(0.f,0.f,0.f,0.f);
                if (k + 3 < K && (n0 + r) < N)
                    v = *(const float4*)&B[(n0 + r) * K + k];
                pb[i] = v;
            }
        }
        #pragma unroll
        for (int kc2 = 0; kc2 < 16; kc2 += 8) {
            uint32_t ah[2][4], al[2][4], bh[2][2], bl[2][2];
            #pragma unroll
            for (int mt = 0; mt < 2; mt++) {
                int r = wm * 32 + mt * 16 + lq;
                ah[mt][0] = Ah[r    ][kc2 + l3];
                ah[mt][1] = Ah[r + 8][kc2 + l3];
                ah[mt][2] = Ah[r    ][kc2 + 4 + l3];
                ah[mt][3] = Ah[r + 8][kc2 + 4 + l3];
                al[mt][0] = Al[r    ][kc2 + l3];
                al[mt][1] = Al[r + 8][kc2 + l3];
                al[mt][2] = Al[r    ][kc2 + 4 + l3];
                al[mt][3] = Al[r + 8][kc2 + 4 + l3];
            }
            #pragma unroll
            for (int nt = 0; nt < 2; nt++) {
                int n = wn * 16 + nt * 8 + lq;
                bh[nt][0] = Bh[n][kc2 + l3];
                bh[nt][1] = Bh[n][kc2 + 4 + l3];
                bl[nt][0] = Bl[n][kc2 + l3];
                bl[nt][1] = Bl[n][kc2 + 4 + l3];
            }
            #pragma unroll
            for (int mt = 0; mt < 2; mt++)
                #pragma unroll
                for (int nt = 0; nt < 2; nt++) {
                    mma16(acc[mt][nt], ah[mt], bh[nt]);
                    mma16(acc[mt][nt], ah[mt], bl[nt]);
                    mma16(acc[mt][nt], al[mt], bh[nt]);
                }
        }
    }

    #pragma unroll
    for (int mt = 0; mt < 2; mt++) {
        #pragma unroll
        for (int nt = 0; nt < 2; nt++) {
            int n = n0 + wn * 16 + nt * 8 + l3 * 2;
            #pragma unroll
            for (int half = 0; half < 2; half++) {
                int mm = m0 + wm * 32 + mt * 16 + lq + half * 8;
                float r0 = acc[mt][nt][half * 2];
                float r1 = acc[mt][nt][half * 2 + 1];
                if (n < N) {
                    if (EPI == 1) r0 += Cc[mm * N + n];
                    if (EPI == 2) r0 = gelu_f(r0);
                    Cc[mm * N + n] = r0;
                }
                if (n + 1 < N) {
                    if (EPI == 1) r1 += Cc[mm * N + n + 1];
                    if (EPI == 2) r1 = gelu_f(r1);
                    Cc[mm * N + n + 1] = r1;
                }
            }
        }
    }
}

// ------------------------------------------------------------------
// Pipelined fp16 lm_head — R8-proven.
// ------------------------------------------------------------------
#define LMH_AW   (128 * 36)
#define LMH_SW   (2 * LMH_AW)
#define LMH_SMEM (2 * LMH_SW * 4)

__global__ __launch_bounds__(256) void lmhead_h2(
    const __half* __restrict__ Ah_g, const __half* __restrict__ Bh_g,
    float* __restrict__ C)
{
    extern __shared__ uint32_t dsm[];
    const uint32_t smem_base = smem_u32(dsm);

    const int tid = threadIdx.x;
    const int lane = tid & 31, wid = tid >> 5;
    const int wm = wid >> 2, wn = wid & 3;
    const int l3 = lane & 3, lq = lane >> 2;
    const int m0 = blockIdx.x * 128, n0 = blockIdx.y * 128;

    float acc[4][4][4];
    #pragma unroll
    for (int i = 0; i < 4; i++)
        #pragma unroll
        for (int j = 0; j < 4; j++)
            #pragma unroll
            for (int q = 0; q < 4; q++) acc[i][j][q] = 0.f;

    const int r_ld = tid >> 3;
    const int c16  = tid & 7;

    auto issue = [&](int kc, int bi) {
        uint32_t ab = smem_base + (uint32_t)bi * (LMH_SW * 4);
        uint32_t bb = ab + LMH_AW * 4;
        const __half* asrc = Ah_g + (size_t)(m0 + r_ld) * KPAD + kc * 64 + c16 * 8;
        const __half* bsrc = Bh_g + (size_t)(n0 + r_ld) * KPAD + kc * 64 + c16 * 8;
        #pragma unroll
        for (int i = 0; i < 4; i++) {
            int r = r_ld + i * 32;
            cp_async16(ab + (uint32_t)(r * 36 + c16 * 4) * 4,
                       asrc + (size_t)(i * 32) * KPAD);
            cp_async16(bb + (uint32_t)(r * 36 + c16 * 4) * 4,
                       bsrc + (size_t)(i * 32) * KPAD);
        }
        asm volatile("cp.async.commit_group;" ::: "memory");
    };

    issue(0, 0);

    #pragma unroll 1
    for (int kc = 0; kc < 4; kc++) {
        if (kc + 1 < 4) {
            issue(kc + 1, (kc + 1) & 1);
            asm volatile("cp.async.wait_group 1;" ::: "memory");
        } else {
            asm volatile("cp.async.wait_group 0;" ::: "memory");
        }
        __syncthreads();

        const uint32_t* As2 = dsm + (kc & 1) * LMH_SW;
        const uint32_t* Bs2 = As2 + LMH_AW;

        #pragma unroll
        for (int kc2 = 0; kc2 < 32; kc2 += 8) {
            uint32_t af[4][4], bf[4][2];
            #pragma unroll
            for (int mt = 0; mt < 4; mt++) {
                int r = wm * 64 + mt * 16 + lq;
                af[mt][0] = As2[r * 36 + kc2 + l3];
                af[mt][1] = As2[(r + 8) * 36 + kc2 + l3];
                af[mt][2] = As2[r * 36 + kc2 + 4 + l3];
                af[mt][3] = As2[(r + 8) * 36 + kc2 + 4 + l3];
            }
            #pragma unroll
            for (int nt = 0; nt < 4; nt++) {
                int n = wn * 32 + nt * 8 + lq;
                bf[nt][0] = Bs2[n * 36 + kc2 + l3];
                bf[nt][1] = Bs2[n * 36 + kc2 + 4 + l3];
            }
            #pragma unroll
            for (int mt = 0; mt < 4; mt++)
                #pragma unroll
                for (int nt = 0; nt < 4; nt++)
                    mma16(acc[mt][nt], af[mt], bf[nt]);
        }
        __syncthreads();
    }

    #pragma unroll
    for (int mt = 0; mt < 4; mt++) {
        #pragma unroll
        for (int nt = 0; nt < 4; nt++) {
            int n = n0 + wn * 32 + nt * 8 + l3 * 2;
            #pragma unroll
            for (int half = 0; half < 2; half++) {
                int mm = m0 + wm * 64 + mt * 16 + lq + half * 8;
                float* dst = &C[(size_t)mm * VOCAB + n];
                if (n     < VOCAB) dst[0] = acc[mt][nt][half * 2];
                if (n + 1 < VOCAB) dst[1] = acc[mt][nt][half * 2 + 1];
            }
        }
    }
}

// ------------------------------------------------------------------
// Grid-wide barrier (all 128 blocks resident)
// ------------------------------------------------------------------
__device__ __forceinline__ void grid_barrier() {
    __syncthreads();
    if (threadIdx.x == 0) {
        __threadfence();
        unsigned gen = atomicAdd(&g_bar_gen, 0u);
        unsigned t = atomicAdd(&g_bar_cnt, 1u);
        if (t == gridDim.x - 1) {
            atomicExch(&g_bar_cnt, 0u);
            __threadfence();
            atomicAdd(&g_bar_gen, 1u);
        } else {
            while (atomicAdd(&g_bar_gen, 0u) == gen) __nanosleep(64);
        }
    }
    __syncthreads();
}

// ------------------------------------------------------------------
// Persistent pscan v3: W-hi RESIDENT in smem (staged once), A hi/lo
// split, 2 mma16 per fragment. 128 blocks x 512 threads, 16 tok/block.
// smem: mAh[16*124] mAl[16*124] rr[16*232]f mx[16*232]f Wh[256*124]
//       = 172544 B
// ------------------------------------------------------------------
#define SCW_AW (16 * 124)
#define SCW_RR (16 * 232)
#define SCW_MX (16 * 232)
#define SCW_W  (256 * 124)
#define SCW_SMEM ((2*SCW_AW + SCW_RR + SCW_MX + SCW_W) * 4)

__global__ __launch_bounds__(512) void scan_all_h(
    float* __restrict__ x0, float* __restrict__ x1,
    const __half* __restrict__ WhT,
    const float* __restrict__ ident)
{
    extern __shared__ uint32_t su[];
    uint32_t* mAh = su;
    uint32_t* mAl = mAh + SCW_AW;
    float*    rr  = (float*)(mAl + SCW_AW);
    float*    mx  = rr + SCW_RR;
    uint32_t* Wh  = (uint32_t*)(mx + SCW_MX);
    const uint32_t wh_base = smem_u32(Wh);
    __half* mAh_h = (__half*)mAh;
    __half* mAl_h = (__half*)mAl;

    const int tid = threadIdx.x;
    const int lane = tid & 31, wid = tid >> 5;   // wid 0..15
    const int l3 = lane & 3, lq = lane >> 2;
    const int T0 = blockIdx.x * 16;
    const int half_id = tid >> 8;
    const int hc = tid & 255;

    // ---- stage W hi ONCE (resident for all 10 steps) ----
    for (int i = tid; i < 256 * 30; i += 512) {
        int n = i / 30, s5 = i - (i / 30) * 30;
        cp_async16(wh_base + (uint32_t)(n * 124 + s5 * 4) * 4,
                   WhT + (size_t)n * WKP + s5 * 8);
    }
    asm volatile("cp.async.commit_group;" ::: "memory");
    asm volatile("cp.async.wait_group 0;" ::: "memory");
    __syncthreads();

    int step = 0;
    for (int off = 1; off < SEQ; off <<= 1, step++) {
        const float* xin = (step & 1) ? x1 : x0;
        float* xout      = (step & 1) ? x0 : x1;

        // ---- load + fp16 hi/lo split ----
        if (hc < 248) {
            int c = hc;
            #pragma unroll
            for (int tl = 0; tl < 8; tl++) {
                int t = half_id * 8 + tl;
                int tok = T0 + t;
                int tt = tok & (SEQ - 1);
                float rv = 0.f, lv = 0.f;
                if (c < C_DIM) {
                    rv = xin[tok * C_DIM + c];
                    lv = (tt >= off) ? xin[(tok - off) * C_DIM + c] : ident[c];
                }
                if (c < 232) rr[t * 232 + c] = rv;
                float s = lv + rv;
                __half hi = __float2half_rn(s);
                __half lo = __float2half_rn(s - __half2float(hi));
                mAh_h[t * 248 + c] = hi;
                mAl_h[t * 248 + c] = lo;
            }
        }
        __syncthreads();

        // ---- mix GEMM: W resident; warp covers n = {wid*8, 128+wid*8} ----
        float acc[2][4];
        #pragma unroll
        for (int i = 0; i < 2; i++)
            #pragma unroll
            for (int q = 0; q < 4; q++) acc[i][q] = 0.f;

        #pragma unroll
        for (int kk = 0; kk < 15; kk++) {
            uint32_t ah[4], al[4];
            ah[0] = mAh[lq * 124 + kk * 8 + l3];
            ah[1] = mAh[(lq + 8) * 124 + kk * 8 + l3];
            ah[2] = mAh[lq * 124 + kk * 8 + 4 + l3];
            ah[3] = mAh[(lq + 8) * 124 + kk * 8 + 4 + l3];
            al[0] = mAl[lq * 124 + kk * 8 + l3];
            al[1] = mAl[(lq + 8) * 124 + kk * 8 + l3];
            al[2] = mAl[lq * 124 + kk * 8 + 4 + l3];
            al[3] = mAl[(lq + 8) * 124 + kk * 8 + 4 + l3];
            #pragma unroll
            for (int ci = 0; ci < 2; ci++) {
                int n = ci * 128 + wid * 8 + lq;
                uint32_t bh[2];
                bh[0] = Wh[n * 124 + kk * 8 + l3];
                bh[1] = Wh[n * 124 + kk * 8 + 4 + l3];
                mma16(acc[ci], ah, bh);
                mma16(acc[ci], al, bh);
            }
        }

        // ---- store mix ----
        #pragma unroll
        for (int ci = 0; ci < 2; ci++) {
            int n = ci * 128 + wid * 8 + l3 * 2;
            if (n < C_DIM) {
                mx[lq * 232 + n]       = acc[ci][0];
                mx[(lq + 8) * 232 + n] = acc[ci][2];
            }
            if (n + 1 < C_DIM) {
                mx[lq * 232 + n + 1]       = acc[ci][1];
                mx[(lq + 8) * 232 + n + 1] = acc[ci][3];
            }
        }
        __syncthreads();

        // ---- combine: 64 (token,lane) pairs, 4 per warp ----
        const int d0 = lane;
        const int d1 = lane + 32;
        const bool has1 = (lane < HD - 32);
        #pragma unroll
        for (int e = 0; e < 4; e++) {
            int p = wid * 4 + e;
            int t = p >> 2;
            int l = p & 3;
            int tok = T0 + t;

            float s0 = __half2float(mAh_h[t * 248 + l * HD + d0])
                     + __half2float(mAl_h[t * 248 + l * HD + d0]);
            float q0 = s0 - rr[t * 232 + l * HD + d0];
            float q1 = 0.f;
            if (has1) {
                float s1 = __half2float(mAh_h[t * 248 + l * HD + d1])
                         + __half2float(mAl_h[t * 248 + l * HD + d1]);
                q1 = s1 - rr[t * 232 + l * HD + d1];
            }

            float sc[4];
            #pragma unroll
            for (int m = 0; m < 4; m++) {
                float pr = q0 * rr[t * 232 + m * HD + d0];
                if (has1) pr += q1 * rr[t * 232 + m * HD + d1];
                #pragma unroll
                for (int o = 16; o > 0; o >>= 1) pr += __shfl_xor_sync(0xffffffffu, pr, o);
                sc[m] = pr * 0.13245323570650439f;
            }
            float mxv = fmaxf(fmaxf(sc[0], sc[1]), fmaxf(sc[2], sc[3]));
            float e0 = expf(sc[0] - mxv), e1 = expf(sc[1] - mxv);
            float e2 = expf(sc[2] - mxv), e3 = expf(sc[3] - mxv);
            float inv = 1.0f / (e0 + e1 + e2 + e3);
            float a0 = e0 * inv, a1 = e1 * inv, a2 = e2 * inv, a3 = e3 * inv;

            float z0 = a0 * mx[t * 232 + 0 * HD + d0] + a1 * mx[t * 232 + 1 * HD + d0]
                     + a2 * mx[t * 232 + 2 * HD + d0] + a3 * mx[t * 232 + 3 * HD + d0];
            float z1 = 0.f;
            if (has1)
                z1 = a0 * mx[t * 232 + 0 * HD + d1] + a1 * mx[t * 232 + 1 * HD + d1]
                   + a2 * mx[t * 232 + 2 * HD + d1] + a3 * mx[t * 232 + 3 * HD + d1];

            float ss = z0 * z0 + z1 * z1;
            #pragma unroll
            for (int o = 16; o > 0; o >>= 1) ss += __shfl_xor_sync(0xffffffffu, ss, o);
            float scale = rsqrtf(ss * (1.0f / 57.0f) + 1e-6f) / (1.0f + (float)l);

            xout[tok * C_DIM + l * HD + d0] = q0 + z0 * scale;
            if (has1) xout[tok * C_DIM + l * HD + d1] = q1 + z1 * scale;
        }

        if ((off << 1) < SEQ) grid_barrier();
    }
}

// ------------------------------------------------------------------
extern "C" void kernel_launch(void* const* d_in, const int* in_sizes, int n_in,
                              void* d_out, int out_size) {
    const int*   idx    = (const int*)  d_in[0];
    const float* wte    = (const float*)d_in[1];
    const float* ln1_g  = (const float*)d_in[2];
    const float* ln2_g  = (const float*)d_in[3];
    const float* w_up   = (const float*)d_in[4];
    const float* w_v    = (const float*)d_in[5];
    const float* w_cpr  = (const float*)d_in[6];
    const float* w_scan = (const float*)d_in[7];
    const float* ident  = (const float*)d_in[8];
    const float* w_fc   = (const float*)d_in[9];
    const float* w_proj = (const float*)d_in[10];
    float* out = (float*)d_out;

    float *px, *pv, *pa, *pb, *pmlp;
    float2* pst;
    __half *pwh, *pxh, *pwsh;
    cudaGetSymbolAddress((void**)&px,   g_x);
    cudaGetSymbolAddress((void**)&pv,   g_v);
    cudaGetSymbolAddress((void**)&pa,   g_bufA);
    cudaGetSymbolAddress((void**)&pb,   g_bufB);
    cudaGetSymbolAddress((void**)&pmlp, g_mlp);
    cudaGetSymbolAddress((void**)&pst,  g_stats);
    cudaGetSymbolAddress((void**)&pwh,  g_wte_h);
    cudaGetSymbolAddress((void**)&pxh,  g_x_h);
    cudaGetSymbolAddress((void**)&pwsh, g_wsh);

    cudaFuncSetAttribute(scan_all_h,
                         cudaFuncAttributeMaxDynamicSharedMemorySize, SCW_SMEM);
    cudaFuncSetAttribute(lmhead_h2,
                         cudaFuncAttributeMaxDynamicSharedMemorySize, LMH_SMEM);

    const int CC = C_DIM * C_DIM;
    const int FC = FF * C_DIM;

    embed_kernel<<<(TOKENS * C_DIM + 255) / 256, 256>>>(idx, wte, px);
    cvt_half_kernel<<<(VPAD * 64 + 255) / 256, 256>>>(wte, pwh, VPAD, VOCAB);
    cvt_wscan_kernel<<<(NLAYER * WKP * 57 + 255) / 256, 256>>>(w_scan, pwsh);

    for (int L = 0; L < NLAYER; L++) {
        const float* wupL  = w_up   + L * CC;
        const float* wvL   = w_v    + L * CC;
        const float* wcprL = w_cpr  + L * CC;
        const float* idL   = ident  + L * C_DIM;
        const float* wfcL  = w_fc   + L * FC;
        const float* wprL  = w_proj + L * FC;

        ln_stats_kernel<<<(TOKENS * 32 + 255) / 256, 256>>>(px, pst);

        dim3 gs(TOKENS / 64, (C_DIM + 63) / 64);
        hgemm<1,0><<<gs, 256>>>(px, nullptr, wupL, pa, TOKENS, C_DIM, C_DIM,
                                pst, ln1_g + L * C_DIM);
        hgemm<1,0><<<gs, 256>>>(px, nullptr, wvL,  pv, TOKENS, C_DIM, C_DIM,
                                pst, ln1_g + L * C_DIM);

        scan_all_h<<<TOKENS / 16, 512, SCW_SMEM>>>(
            pa, pb, pwsh + (size_t)L * WNP * WKP, idL);

        hgemm<2,1><<<gs, 256>>>(pa, pv, wcprL, px, TOKENS, C_DIM, C_DIM,
                                nullptr, nullptr);

        ln_stats_kernel<<<(TOKENS * 32 + 255) / 256, 256>>>(px, pst);

        dim3 gf(TOKENS / 64, (FF + 63) / 64);
        hgemm<1,2><<<gf, 256>>>(px, nullptr, wfcL, pmlp, TOKENS, FF, C_DIM,
                                pst, ln2_g + L * C_DIM);
        hgemm<0,1><<<gs, 256>>>(pmlp, nullptr, wprL, px, TOKENS, C_DIM, FF,
                                nullptr, nullptr);
    }

    cvt_half_kernel<<<(TOKENS * 64 + 255) / 256, 256>>>(px, pxh, TOKENS, TOKENS);

    dim3 gl(TOKENS / 128, VPAD / 128);
    lmhead_h2<<<gl, 256, LMH_SMEM>>>(pxh, pwh, out);
}